// round 1
// baseline (speedup 1.0000x reference)
#include <cuda_runtime.h>
#include <math.h>

#define BB 256
#define HS 512
#define INSZ 512
#define NC 38
#define TT 26
#define CH 512
#define FH 8
#define FW 32
#define PP 256   /* FH*FW */

// ---------------- scratch (device globals; no allocation allowed) ----------
__device__ float g_fmh[BB*CH*PP];      // conv output, 134MB
__device__ float g_meanH[BB*INSZ];
__device__ float g_bhproj[BB*HS];
__device__ float g_h1a[BB*HS], g_c1a[BB*HS], g_h2a[BB*HS], g_c2a[BB*HS];
__device__ float g_h1b[BB*HS], g_c1b[BB*HS], g_h2b[BB*HS], g_c2b[BB*HS];
__device__ float g_v[BB*HS];
__device__ float g_q[BB*HS];
__device__ float g_ctx[BB*HS];
__device__ float g_gates[BB*4*HS];
__device__ float g_cur[BB*HS];

__device__ __forceinline__ float sigm(float x){ return 1.0f/(1.0f+expf(-x)); }

// ---------------- generic fused GEMM: C = A1*W1^T [+A2*W2^T] [+b1] [+b2] [+Cadd] [+gather] ----
// A row-major MxK (lda), W row-major NxK (ldw). BM=BN=64, BK=16, 256 thr, 4x4/thr.
__global__ void gemm_kernel(
    float* __restrict__ C, int ldc,
    const float* __restrict__ A1, int lda1, const float* __restrict__ W1, int ldw1, int K1,
    const float* __restrict__ A2, int lda2, const float* __restrict__ W2, int ldw2, int K2,
    const float* __restrict__ bias1, const float* __restrict__ bias2,
    const float* __restrict__ Cadd, int ldadd,
    const float* __restrict__ Wg, int ldwg, int gcolbase,
    const int* __restrict__ textcol, int textstride,
    int M, int N)
{
    __shared__ float As[16][68];
    __shared__ float Bs[16][68];
    int m0 = blockIdx.y * 64;
    int n0 = blockIdx.x * 64;
    int tid = threadIdx.x;
    int tx = tid & 15, ty = tid >> 4;

    float acc[4][4];
    #pragma unroll
    for (int i=0;i<4;i++)
        #pragma unroll
        for (int j=0;j<4;j++) acc[i][j]=0.f;

    #pragma unroll 1
    for (int pass=0; pass<2; ++pass){
        const float* A = pass ? A2 : A1;
        const float* W = pass ? W2 : W1;
        int K   = pass ? K2  : K1;
        int lda = pass ? lda2: lda1;
        int ldw = pass ? ldw2: ldw1;
        if (A == nullptr) continue;

        for (int k0=0; k0<K; k0+=16){
            #pragma unroll
            for (int i=0;i<4;i++){
                int e = i*256 + tid;
                int m = e >> 4, kk = e & 15;
                int gm = m0 + m, gk = k0 + kk;
                As[kk][m] = (gm < M && gk < K) ? A[gm*lda + gk] : 0.f;
            }
            #pragma unroll
            for (int i=0;i<4;i++){
                int e = i*256 + tid;
                int n = e >> 4, kk = e & 15;
                int gn = n0 + n, gk = k0 + kk;
                Bs[kk][n] = (gn < N && gk < K) ? W[gn*ldw + gk] : 0.f;
            }
            __syncthreads();
            #pragma unroll
            for (int kk=0; kk<16; kk++){
                float4 a = *(const float4*)&As[kk][ty*4];
                float4 b = *(const float4*)&Bs[kk][tx*4];
                acc[0][0]+=a.x*b.x; acc[0][1]+=a.x*b.y; acc[0][2]+=a.x*b.z; acc[0][3]+=a.x*b.w;
                acc[1][0]+=a.y*b.x; acc[1][1]+=a.y*b.y; acc[1][2]+=a.y*b.z; acc[1][3]+=a.y*b.w;
                acc[2][0]+=a.z*b.x; acc[2][1]+=a.z*b.y; acc[2][2]+=a.z*b.z; acc[2][3]+=a.z*b.w;
                acc[3][0]+=a.w*b.x; acc[3][1]+=a.w*b.y; acc[3][2]+=a.w*b.z; acc[3][3]+=a.w*b.w;
            }
            __syncthreads();
        }
    }

    #pragma unroll
    for (int i=0;i<4;i++){
        int m = m0 + ty*4 + i;
        if (m >= M) continue;
        int tcol = 0;
        if (Wg) tcol = textcol[m*textstride];
        #pragma unroll
        for (int j=0;j<4;j++){
            int n = n0 + tx*4 + j;
            if (n >= N) continue;
            float v = acc[i][j];
            if (bias1) v += bias1[n];
            if (bias2) v += bias2[n];
            if (Cadd)  v += Cadd[m*ldadd + n];
            if (Wg)    v += Wg[n*ldwg + gcolbase + tcol];
            C[m*ldc + n] = v;
        }
    }
}

// ---------------- conv 3x3 SAME, implicit GEMM -----------------------------
// block: 64 positions (2 rows x 32 cols) x 64 ocs. grid (8 oc-tiles, 4 row-pairs, 256 b)
__global__ void conv_kernel(const float* __restrict__ in, const float* __restrict__ w,
                            const float* __restrict__ bias, float* __restrict__ out)
{
    __shared__ float As[16][68];
    __shared__ float Bs[16][68];
    int b  = blockIdx.z;
    int py = blockIdx.y;
    int oc0 = blockIdx.x * 64;
    int tid = threadIdx.x;
    int tx = tid & 15, ty = tid >> 4;

    float acc[4][4];
    #pragma unroll
    for (int i=0;i<4;i++)
        #pragma unroll
        for (int j=0;j<4;j++) acc[i][j]=0.f;

    const float* inb = in + (size_t)b * CH * PP;

    for (int kh=0; kh<3; kh++){
        for (int kw=0; kw<3; kw++){
            for (int ic0=0; ic0<CH; ic0+=16){
                #pragma unroll
                for (int i=0;i<4;i++){
                    int e = i*256 + tid;
                    int kk = e >> 6, m = e & 63;
                    int r = py*2 + (m >> 5);
                    int c = m & 31;
                    int hh = r + kh - 1, ww = c + kw - 1;
                    float vv = 0.f;
                    if ((unsigned)hh < 8u && (unsigned)ww < 32u)
                        vv = inb[(ic0+kk)*PP + hh*32 + ww];
                    As[kk][m] = vv;
                }
                #pragma unroll
                for (int i=0;i<4;i++){
                    int e = i*256 + tid;
                    int n = e >> 4, kk = e & 15;
                    Bs[kk][n] = w[(size_t)(oc0+n)*(CH*9) + (ic0+kk)*9 + kh*3 + kw];
                }
                __syncthreads();
                #pragma unroll
                for (int kk=0; kk<16; kk++){
                    float4 a = *(const float4*)&As[kk][ty*4];
                    float4 bb = *(const float4*)&Bs[kk][tx*4];
                    acc[0][0]+=a.x*bb.x; acc[0][1]+=a.x*bb.y; acc[0][2]+=a.x*bb.z; acc[0][3]+=a.x*bb.w;
                    acc[1][0]+=a.y*bb.x; acc[1][1]+=a.y*bb.y; acc[1][2]+=a.y*bb.z; acc[1][3]+=a.y*bb.w;
                    acc[2][0]+=a.z*bb.x; acc[2][1]+=a.z*bb.y; acc[2][2]+=a.z*bb.z; acc[2][3]+=a.z*bb.w;
                    acc[3][0]+=a.w*bb.x; acc[3][1]+=a.w*bb.y; acc[3][2]+=a.w*bb.z; acc[3][3]+=a.w*bb.w;
                }
                __syncthreads();
            }
        }
    }

    #pragma unroll
    for (int i=0;i<4;i++){
        int p = py*64 + ty*4 + i;
        #pragma unroll
        for (int j=0;j<4;j++){
            int oc = oc0 + tx*4 + j;
            out[((size_t)b*CH + oc)*PP + p] = acc[i][j] + bias[oc];
        }
    }
}

// ---------------- mean over T of batch_H ------------------------------------
__global__ void mean_kernel(const float* __restrict__ bH, float* __restrict__ out)
{
    int idx = blockIdx.x*256 + threadIdx.x; // B*INSZ
    if (idx >= BB*INSZ) return;
    int b = idx >> 9, k = idx & 511;
    const float* p = bH + (size_t)b*TT*INSZ + k;
    float s = 0.f;
    #pragma unroll
    for (int t=0;t<TT;t++) s += p[t*INSZ];
    out[idx] = s * (1.0f/26.0f);
}

// ---------------- init h0/c0 -------------------------------------------------
__global__ void init_kernel(const float* __restrict__ hh, const float* __restrict__ hc,
                            float* __restrict__ h1, float* __restrict__ h2,
                            float* __restrict__ c1, float* __restrict__ c2)
{
    int idx = blockIdx.x*256 + threadIdx.x;
    if (idx >= BB*HS) return;
    float h0 = 0.5f*(hh[idx] + hh[BB*HS + idx]);
    float c0 = 0.5f*(hc[idx] + hc[BB*HS + idx]);
    h1[idx]=h0; h2[idx]=h0; c1[idx]=c0; c2[idx]=c0;
}

// ---------------- attention: e -> softmax -> context ------------------------
// one block per batch element, 256 threads (one per spatial position)
__global__ void attn_kernel(const float* __restrict__ fmh, const float* __restrict__ q,
                            const float* __restrict__ ws, const float* __restrict__ sb,
                            float* __restrict__ ctx)
{
    __shared__ float qs[CH];
    __shared__ float wss[CH];
    __shared__ float red[256];
    __shared__ float alpha[256];

    int b = blockIdx.x;
    int p = threadIdx.x;
    const float* f = fmh + (size_t)b * CH * PP;

    qs[p]       = q[b*HS + p];
    qs[p+256]   = q[b*HS + p + 256];
    wss[p]      = ws[p];
    wss[p+256]  = ws[p+256];
    __syncthreads();

    float acc = 0.f;
    #pragma unroll 4
    for (int c=0; c<CH; c++){
        acc += tanhf(f[c*PP + p] + qs[c]) * wss[c];
    }
    float e = acc + sb[0];

    // block softmax over 256
    red[p] = e; __syncthreads();
    #pragma unroll
    for (int s=128; s>0; s>>=1){
        if (p < s) red[p] = fmaxf(red[p], red[p+s]);
        __syncthreads();
    }
    float mx = red[0];
    __syncthreads();
    float ex = expf(e - mx);
    red[p] = ex; __syncthreads();
    #pragma unroll
    for (int s=128; s>0; s>>=1){
        if (p < s) red[p] += red[p+s];
        __syncthreads();
    }
    float sum = red[0];
    __syncthreads();
    alpha[p] = ex / sum;
    __syncthreads();

    // context[c] = sum_p alpha[p]*f[c][p]; warp per channel
    int lane = p & 31, wid = p >> 5;
    for (int c = wid; c < CH; c += 8){
        const float* fr = f + c*PP;
        float s = 0.f;
        #pragma unroll
        for (int pp = lane; pp < PP; pp += 32) s += alpha[pp] * fr[pp];
        #pragma unroll
        for (int o=16; o>0; o>>=1) s += __shfl_down_sync(0xffffffffu, s, o);
        if (lane == 0) ctx[b*HS + c] = s;
    }
}

// ---------------- LSTM pointwise --------------------------------------------
__global__ void lstm_kernel(const float* __restrict__ g, const float* __restrict__ cin,
                            float* __restrict__ hout, float* __restrict__ cout)
{
    int idx = blockIdx.x*256 + threadIdx.x;
    if (idx >= BB*HS) return;
    int b = idx >> 9, j = idx & 511;
    const float* gb = g + (size_t)b*4*HS;
    float i_ = gb[j], f_ = gb[HS + j], gg = gb[2*HS + j], o_ = gb[3*HS + j];
    float c2 = sigm(f_)*cin[idx] + sigm(i_)*tanhf(gg);
    cout[idx] = c2;
    hout[idx] = sigm(o_)*tanhf(c2);
}

// ---------------- host orchestration ----------------------------------------
extern "C" void kernel_launch(void* const* d_in, const int* in_sizes, int n_in,
                              void* d_out, int out_size)
{
    const float* feature_map = (const float*)d_in[0];
    const float* batch_H     = (const float*)d_in[1];
    const float* hidden_h    = (const float*)d_in[2];
    const float* hidden_c    = (const float*)d_in[3];
    const int*   text        = (const int*)  d_in[4];
    const float* i2h_w       = (const float*)d_in[5];
    const float* h2h_w       = (const float*)d_in[6];
    const float* h2h_b       = (const float*)d_in[7];
    const float* conv_m2h_w  = (const float*)d_in[8];
    const float* conv_m2h_b  = (const float*)d_in[9];
    const float* conv_h2h_w  = (const float*)d_in[10];
    const float* conv_h2h_b  = (const float*)d_in[11];
    const float* score_w     = (const float*)d_in[12];
    const float* score_b     = (const float*)d_in[13];
    const float* rnn1_w_ih   = (const float*)d_in[14];
    const float* rnn1_w_hh   = (const float*)d_in[15];
    const float* rnn1_b_ih   = (const float*)d_in[16];
    const float* rnn1_b_hh   = (const float*)d_in[17];
    const float* hlin_w      = (const float*)d_in[18];
    const float* hlin_b      = (const float*)d_in[19];
    const float* rnn2_w_ih   = (const float*)d_in[20];
    const float* rnn2_w_hh   = (const float*)d_in[21];
    const float* rnn2_b_ih   = (const float*)d_in[22];
    const float* rnn2_b_hh   = (const float*)d_in[23];
    const float* gen_w       = (const float*)d_in[24];
    const float* gen_b       = (const float*)d_in[25];
    float* out = (float*)d_out;

    float *fmh,*meanH,*bhproj,*h1a,*c1a,*h2a,*c2a,*h1b,*c1b,*h2b,*c2b,*v,*q,*ctx,*gates,*cur;
    cudaGetSymbolAddress((void**)&fmh,   g_fmh);
    cudaGetSymbolAddress((void**)&meanH, g_meanH);
    cudaGetSymbolAddress((void**)&bhproj,g_bhproj);
    cudaGetSymbolAddress((void**)&h1a, g_h1a); cudaGetSymbolAddress((void**)&c1a, g_c1a);
    cudaGetSymbolAddress((void**)&h2a, g_h2a); cudaGetSymbolAddress((void**)&c2a, g_c2a);
    cudaGetSymbolAddress((void**)&h1b, g_h1b); cudaGetSymbolAddress((void**)&c1b, g_c1b);
    cudaGetSymbolAddress((void**)&h2b, g_h2b); cudaGetSymbolAddress((void**)&c2b, g_c2b);
    cudaGetSymbolAddress((void**)&v,   g_v);   cudaGetSymbolAddress((void**)&q,   g_q);
    cudaGetSymbolAddress((void**)&ctx, g_ctx); cudaGetSymbolAddress((void**)&gates, g_gates);
    cudaGetSymbolAddress((void**)&cur, g_cur);

    // conv fmh
    conv_kernel<<<dim3(8,4,BB), 256>>>(feature_map, conv_m2h_w, conv_m2h_b, fmh);
    // mean over T, then bh_proj = meanH @ i2h_w^T
    mean_kernel<<<512,256>>>(batch_H, meanH);
    gemm_kernel<<<dim3(8,4),256>>>(bhproj, HS,
        meanH, INSZ, i2h_w, INSZ, INSZ,
        nullptr,0,nullptr,0,0,
        nullptr,nullptr, nullptr,0, nullptr,0,0, nullptr,0, BB, HS);
    // init states
    init_kernel<<<512,256>>>(hidden_h, hidden_c, h1a, h2a, c1a, c2a);

    float *h1c=h1a,*c1c=c1a,*h2c=h2a,*c2c=c2a;
    float *h1n=h1b,*c1n=c1b,*h2n=h2b,*c2n=c2b;

    for (int t=0; t<TT; t++){
        // v = bhproj + h2 @ h2h_w^T + h2h_b
        gemm_kernel<<<dim3(8,4),256>>>(v, HS,
            h2c, HS, h2h_w, HS, HS,
            nullptr,0,nullptr,0,0,
            h2h_b, nullptr, bhproj, HS, nullptr,0,0, nullptr,0, BB, HS);
        // q = v @ w_h2h_1x1^T + conv_h2h_b
        gemm_kernel<<<dim3(8,4),256>>>(q, HS,
            v, HS, conv_h2h_w, HS, HS,
            nullptr,0,nullptr,0,0,
            conv_h2h_b, nullptr, nullptr,0, nullptr,0,0, nullptr,0, BB, HS);
        // attention -> ctx
        attn_kernel<<<BB,256>>>(fmh, q, score_w, score_b, ctx);
        // gates1 = [ctx,onehot] @ w_ih^T + h1 @ w_hh^T + b_ih + b_hh
        gemm_kernel<<<dim3(32,4),256>>>(gates, 4*HS,
            ctx, HS, rnn1_w_ih, INSZ+NC, HS,
            h1c, HS, rnn1_w_hh, HS, HS,
            rnn1_b_ih, rnn1_b_hh, nullptr,0,
            rnn1_w_ih, INSZ+NC, INSZ, text + t, TT, BB, 4*HS);
        lstm_kernel<<<512,256>>>(gates, c1c, h1n, c1n);
        // cur = h1n @ hlin_w^T + hlin_b
        gemm_kernel<<<dim3(8,4),256>>>(cur, HS,
            h1n, HS, hlin_w, HS, HS,
            nullptr,0,nullptr,0,0,
            hlin_b, nullptr, nullptr,0, nullptr,0,0, nullptr,0, BB, HS);
        // gates2 = cur @ w_ih^T + h2 @ w_hh^T + biases
        gemm_kernel<<<dim3(32,4),256>>>(gates, 4*HS,
            cur, HS, rnn2_w_ih, HS, HS,
            h2c, HS, rnn2_w_hh, HS, HS,
            rnn2_b_ih, rnn2_b_hh, nullptr,0,
            nullptr,0,0, nullptr,0, BB, 4*HS);
        lstm_kernel<<<512,256>>>(gates, c2c, h2n, c2n);
        // probs[:, t, :] = h2n @ gen_w^T + gen_b
        gemm_kernel<<<dim3(1,4),256>>>(out + t*NC, TT*NC,
            h2n, HS, gen_w, HS, HS,
            nullptr,0,nullptr,0,0,
            gen_b, nullptr, nullptr,0, nullptr,0,0, nullptr,0, BB, NC);

        // swap state buffers
        float* tp;
        tp=h1c; h1c=h1n; h1n=tp;  tp=c1c; c1c=c1n; c1n=tp;
        tp=h2c; h2c=h2n; h2n=tp;  tp=c2c; c2c=c2n; c2n=tp;
    }
}

// round 2
// speedup vs baseline: 1.3865x; 1.3865x over previous
#include <cuda_runtime.h>
#include <math.h>
#include <stdint.h>

#define BB 256
#define HS 512
#define INSZ 512
#define NC 38
#define TT 26
#define CH 512
#define PP 256   /* 8*32 */

// ---------------- scratch (device globals; no allocation allowed) ----------
__device__ float g_inpad3[(size_t)3*BB*CH*10*32];  // kw-shifted zero-padded input, fp32
__device__ float g_w2t[9*CH*CH];                   // weights [khw][ic][oc]
__device__ float g_fmh[(size_t)BB*CH*PP];          // conv output, 134MB
__device__ float g_meanH[BB*INSZ];
__device__ float g_bhproj[BB*HS];                  // meanH@i2h^T + h2h_b
__device__ float g_Wq[HS*HS];                      // conv1x1 @ h2h_w
__device__ float g_qb[BB*HS];
__device__ float g_h1a[BB*HS], g_c1a[BB*HS], g_h2a[BB*HS], g_c2a[BB*HS];
__device__ float g_h1b[BB*HS], g_c1b[BB*HS], g_h2b[BB*HS], g_c2b[BB*HS];
__device__ float g_q[BB*HS];
__device__ float g_ctx[BB*HS];
__device__ float g_gates[BB*4*HS];
__device__ float g_cur[BB*HS];

// ---------------- fast math ------------------------------------------------
__device__ __forceinline__ float fexp(float x){
    float y; asm("ex2.approx.f32 %0, %1;" : "=f"(y) : "f"(x*1.4426950408889634f)); return y;
}
__device__ __forceinline__ float frcp(float x){
    float y; asm("rcp.approx.f32 %0, %1;" : "=f"(y) : "f"(x)); return y;
}
__device__ __forceinline__ float ftanh(float x){
    float xc = fminf(fmaxf(x, -15.f), 15.f);
    float t = fexp(2.f*xc);
    return (t - 1.f) * frcp(t + 1.f);
}
__device__ __forceinline__ float fsigm(float x){
    return frcp(1.f + fexp(-x));
}
__device__ __forceinline__ float tf32r(float x){
    uint32_t u; asm("cvt.rna.tf32.f32 %0, %1;" : "=r"(u) : "f"(x)); return __uint_as_float(u);
}
__device__ __forceinline__ void mma_tf32(float* d, const uint32_t* a, const uint32_t* b){
    asm volatile(
      "mma.sync.aligned.m16n8k8.row.col.f32.tf32.tf32.f32 "
      "{%0,%1,%2,%3},{%4,%5,%6,%7},{%8,%9},{%0,%1,%2,%3};"
      : "+f"(d[0]),"+f"(d[1]),"+f"(d[2]),"+f"(d[3])
      : "r"(a[0]),"r"(a[1]),"r"(a[2]),"r"(a[3]), "r"(b[0]),"r"(b[1]));
}

// ---------------- prep: pad+shift input, transpose weights ------------------
__global__ void pad3_kernel(const float* __restrict__ in, float* __restrict__ out)
{
    size_t idx = (size_t)blockIdx.x*256 + threadIdx.x;
    if (idx >= (size_t)3*BB*CH*10*32) return;
    int c  = idx & 31;
    size_t t = idx >> 5;
    int rr = (int)(t % 10); t /= 10;
    int ic = (int)(t & 511); t >>= 9;
    int b  = (int)(t & 255); t >>= 8;
    int kw = (int)t;
    int r = rr - 1, cc = c + kw - 1;
    float v = 0.f;
    if ((unsigned)r < 8u && (unsigned)cc < 32u)
        v = in[((size_t)b*CH + ic)*PP + r*32 + cc];
    out[idx] = v;
}

__global__ void w2t_kernel(const float* __restrict__ w, float* __restrict__ out)
{
    int idx = blockIdx.x*256 + threadIdx.x;
    if (idx >= 9*CH*CH) return;
    int oc = idx & 511;
    int ic = (idx >> 9) & 511;
    int khw = idx >> 18;
    out[idx] = w[((size_t)oc*CH + ic)*9 + khw];
}

// ---------------- conv 3x3 SAME via tf32 mma ---------------------------------
// block tile 128(p) x 128(oc); 8 warps (2m x 4n), warp tile 64x32
__global__ void __launch_bounds__(256, 2) conv_mma_kernel(
    const float* __restrict__ inp3, const float* __restrict__ w2t,
    const float* __restrict__ bias, float* __restrict__ out)
{
    __shared__ float As[16][136];
    __shared__ float Bs[16][136];
    const int b  = blockIdx.z;
    const int m0 = blockIdx.y * 128;
    const int n0 = blockIdx.x * 128;
    const int tid = threadIdx.x;
    const int lane = tid & 31, warp = tid >> 5;
    const int wm = (warp >> 2) * 64;
    const int wn = (warp & 3) * 32;
    const int gid = lane >> 2, tig = lane & 3;

    float acc[4][4][4];
    #pragma unroll
    for (int i=0;i<4;i++)
      #pragma unroll
      for (int j=0;j<4;j++)
        #pragma unroll
        for (int k=0;k<4;k++) acc[i][j][k]=0.f;

    const int a_kk = tid >> 4;        // 0..15 (k row within chunk)
    const int a_m  = (tid & 15) * 8;  // 0..120
    const int p    = m0 + a_m;
    const int r    = p >> 5;
    const int c    = p & 31;

    for (int khw = 0; khw < 9; ++khw){
        const int kh = khw / 3, kw = khw - kh*3;
        const float* abase = inp3 + (((size_t)kw*BB + b)*CH + a_kk)*320
                                  + (size_t)(r + kh)*32 + c;
        const float* bbase = w2t + (size_t)khw*CH*CH + (size_t)a_kk*CH + n0 + a_m;
        for (int ic0 = 0; ic0 < CH; ic0 += 16){
            float4 av0 = *(const float4*)(abase + (size_t)ic0*320);
            float4 av1 = *(const float4*)(abase + (size_t)ic0*320 + 4);
            float4 bv0 = *(const float4*)(bbase + (size_t)ic0*CH);
            float4 bv1 = *(const float4*)(bbase + (size_t)ic0*CH + 4);
            __syncthreads();
            av0.x=tf32r(av0.x); av0.y=tf32r(av0.y); av0.z=tf32r(av0.z); av0.w=tf32r(av0.w);
            av1.x=tf32r(av1.x); av1.y=tf32r(av1.y); av1.z=tf32r(av1.z); av1.w=tf32r(av1.w);
            bv0.x=tf32r(bv0.x); bv0.y=tf32r(bv0.y); bv0.z=tf32r(bv0.z); bv0.w=tf32r(bv0.w);
            bv1.x=tf32r(bv1.x); bv1.y=tf32r(bv1.y); bv1.z=tf32r(bv1.z); bv1.w=tf32r(bv1.w);
            *(float4*)&As[a_kk][a_m]     = av0;
            *(float4*)&As[a_kk][a_m + 4] = av1;
            *(float4*)&Bs[a_kk][a_m]     = bv0;
            *(float4*)&Bs[a_kk][a_m + 4] = bv1;
            __syncthreads();
            #pragma unroll
            for (int s = 0; s < 2; ++s){
                const int kb = s*8 + tig;
                uint32_t afr[4][4], bfr[4][2];
                #pragma unroll
                for (int mi=0; mi<4; ++mi){
                    int rowb = wm + mi*16 + gid;
                    afr[mi][0] = __float_as_uint(As[kb  ][rowb]);
                    afr[mi][1] = __float_as_uint(As[kb  ][rowb+8]);
                    afr[mi][2] = __float_as_uint(As[kb+4][rowb]);
                    afr[mi][3] = __float_as_uint(As[kb+4][rowb+8]);
                }
                #pragma unroll
                for (int ni=0; ni<4; ++ni){
                    int colb = wn + ni*8 + gid;
                    bfr[ni][0] = __float_as_uint(Bs[kb  ][colb]);
                    bfr[ni][1] = __float_as_uint(Bs[kb+4][colb]);
                }
                #pragma unroll
                for (int mi=0; mi<4; ++mi)
                    #pragma unroll
                    for (int ni=0; ni<4; ++ni)
                        mma_tf32(acc[mi][ni], afr[mi], bfr[ni]);
            }
        }
    }

    #pragma unroll
    for (int mi=0; mi<4; ++mi){
        int prow = m0 + wm + mi*16 + gid;
        #pragma unroll
        for (int ni=0; ni<4; ++ni){
            int oc = n0 + wn + ni*8 + tig*2;
            float bz0 = bias[oc], bz1 = bias[oc+1];
            float* o0 = out + ((size_t)b*CH + oc)*PP;
            o0[prow]          = acc[mi][ni][0] + bz0;
            o0[PP + prow]     = acc[mi][ni][1] + bz1;
            o0[prow + 8]      = acc[mi][ni][2] + bz0;
            o0[PP + prow + 8] = acc[mi][ni][3] + bz1;
        }
    }
}

// ---------------- generic fused GEMM (fp32 FFMA) ----------------------------
// C = A1*W1^T [+A2*W2^T] [+b1] [+b2] [+Cadd] [+gather]; nn=1 => pass0 is A1*W1 (NN)
__global__ void gemm_kernel(
    float* __restrict__ C, int ldc,
    const float* __restrict__ A1, int lda1, const float* __restrict__ W1, int ldw1, int K1,
    const float* __restrict__ A2, int lda2, const float* __restrict__ W2, int ldw2, int K2,
    const float* __restrict__ bias1, const float* __restrict__ bias2,
    const float* __restrict__ Cadd, int ldadd,
    const float* __restrict__ Wg, int ldwg, int gcolbase,
    const int* __restrict__ textcol, int textstride,
    int nn, int M, int N)
{
    __shared__ float As[16][68];
    __shared__ float Bs[16][68];
    int m0 = blockIdx.y * 64;
    int n0 = blockIdx.x * 64;
    int tid = threadIdx.x;
    int tx = tid & 15, ty = tid >> 4;

    float acc[4][4];
    #pragma unroll
    for (int i=0;i<4;i++)
        #pragma unroll
        for (int j=0;j<4;j++) acc[i][j]=0.f;

    #pragma unroll 1
    for (int pass=0; pass<2; ++pass){
        const float* A = pass ? A2 : A1;
        const float* W = pass ? W2 : W1;
        int K   = pass ? K2  : K1;
        int lda = pass ? lda2: lda1;
        int ldw = pass ? ldw2: ldw1;
        if (A == nullptr) continue;
        int donn = (pass == 0) ? nn : 0;

        for (int k0=0; k0<K; k0+=16){
            #pragma unroll
            for (int i=0;i<4;i++){
                int e = i*256 + tid;
                int m = e >> 4, kk = e & 15;
                int gm = m0 + m, gk = k0 + kk;
                As[kk][m] = (gm < M && gk < K) ? A[gm*lda + gk] : 0.f;
            }
            if (donn){
                #pragma unroll
                for (int i=0;i<4;i++){
                    int e = i*256 + tid;
                    int kk = e >> 6, n = e & 63;
                    int gn = n0 + n, gk = k0 + kk;
                    Bs[kk][n] = (gn < N && gk < K) ? W[gk*ldw + gn] : 0.f;
                }
            } else {
                #pragma unroll
                for (int i=0;i<4;i++){
                    int e = i*256 + tid;
                    int n = e >> 4, kk = e & 15;
                    int gn = n0 + n, gk = k0 + kk;
                    Bs[kk][n] = (gn < N && gk < K) ? W[gn*ldw + gk] : 0.f;
                }
            }
            __syncthreads();
            #pragma unroll
            for (int kk=0; kk<16; kk++){
                float4 a = *(const float4*)&As[kk][ty*4];
                float4 b = *(const float4*)&Bs[kk][tx*4];
                acc[0][0]+=a.x*b.x; acc[0][1]+=a.x*b.y; acc[0][2]+=a.x*b.z; acc[0][3]+=a.x*b.w;
                acc[1][0]+=a.y*b.x; acc[1][1]+=a.y*b.y; acc[1][2]+=a.y*b.z; acc[1][3]+=a.y*b.w;
                acc[2][0]+=a.z*b.x; acc[2][1]+=a.z*b.y; acc[2][2]+=a.z*b.z; acc[2][3]+=a.z*b.w;
                acc[3][0]+=a.w*b.x; acc[3][1]+=a.w*b.y; acc[3][2]+=a.w*b.z; acc[3][3]+=a.w*b.w;
            }
            __syncthreads();
        }
    }

    #pragma unroll
    for (int i=0;i<4;i++){
        int m = m0 + ty*4 + i;
        if (m >= M) continue;
        int tcol = 0;
        if (Wg) tcol = textcol[m*textstride];
        #pragma unroll
        for (int j=0;j<4;j++){
            int n = n0 + tx*4 + j;
            if (n >= N) continue;
            float v = acc[i][j];
            if (bias1) v += bias1[n];
            if (bias2) v += bias2[n];
            if (Cadd)  v += Cadd[m*ldadd + n];
            if (Wg)    v += Wg[n*ldwg + gcolbase + tcol];
            C[m*ldc + n] = v;
        }
    }
}

// ---------------- mean over T of batch_H ------------------------------------
__global__ void mean_kernel(const float* __restrict__ bH, float* __restrict__ out)
{
    int idx = blockIdx.x*256 + threadIdx.x;
    if (idx >= BB*INSZ) return;
    int b = idx >> 9, k = idx & 511;
    const float* p = bH + (size_t)b*TT*INSZ + k;
    float s = 0.f;
    #pragma unroll
    for (int t=0;t<TT;t++) s += p[t*INSZ];
    out[idx] = s * (1.0f/26.0f);
}

// ---------------- init h0/c0 -------------------------------------------------
__global__ void init_kernel(const float* __restrict__ hh, const float* __restrict__ hc,
                            float* __restrict__ h1, float* __restrict__ h2,
                            float* __restrict__ c1, float* __restrict__ c2)
{
    int idx = blockIdx.x*256 + threadIdx.x;
    if (idx >= BB*HS) return;
    float h0 = 0.5f*(hh[idx] + hh[BB*HS + idx]);
    float c0 = 0.5f*(hc[idx] + hc[BB*HS + idx]);
    h1[idx]=h0; h2[idx]=h0; c1[idx]=c0; c2[idx]=c0;
}

// ---------------- attention: e -> softmax -> context ------------------------
__global__ void attn_kernel(const float* __restrict__ fmh, const float* __restrict__ q,
                            const float* __restrict__ ws, const float* __restrict__ sb,
                            float* __restrict__ ctx)
{
    __shared__ float qs[CH];
    __shared__ float wss[CH];
    __shared__ float red[256];
    __shared__ float alpha[256];

    int b = blockIdx.x;
    int p = threadIdx.x;
    const float* f = fmh + (size_t)b * CH * PP;

    qs[p]       = q[b*HS + p];
    qs[p+256]   = q[b*HS + p + 256];
    wss[p]      = ws[p];
    wss[p+256]  = ws[p+256];
    __syncthreads();

    float acc = 0.f;
    #pragma unroll 4
    for (int c=0; c<CH; c++){
        acc += ftanh(f[c*PP + p] + qs[c]) * wss[c];
    }
    float e = acc + sb[0];

    red[p] = e; __syncthreads();
    #pragma unroll
    for (int s=128; s>0; s>>=1){
        if (p < s) red[p] = fmaxf(red[p], red[p+s]);
        __syncthreads();
    }
    float mx = red[0];
    __syncthreads();
    float ex = fexp(e - mx);
    red[p] = ex; __syncthreads();
    #pragma unroll
    for (int s=128; s>0; s>>=1){
        if (p < s) red[p] += red[p+s];
        __syncthreads();
    }
    float sum = red[0];
    __syncthreads();
    alpha[p] = ex * frcp(sum);
    __syncthreads();

    int lane = p & 31, wid = p >> 5;
    for (int c = wid; c < CH; c += 8){
        const float* fr = f + c*PP;
        float s = 0.f;
        #pragma unroll
        for (int pp = lane; pp < PP; pp += 32) s += alpha[pp] * fr[pp];
        #pragma unroll
        for (int o=16; o>0; o>>=1) s += __shfl_down_sync(0xffffffffu, s, o);
        if (lane == 0) ctx[b*HS + c] = s;
    }
}

// ---------------- LSTM pointwise --------------------------------------------
__global__ void lstm_kernel(const float* __restrict__ g, const float* __restrict__ cin,
                            float* __restrict__ hout, float* __restrict__ cout)
{
    int idx = blockIdx.x*256 + threadIdx.x;
    if (idx >= BB*HS) return;
    int b = idx >> 9, j = idx & 511;
    const float* gb = g + (size_t)b*4*HS;
    float i_ = gb[j], f_ = gb[HS + j], gg = gb[2*HS + j], o_ = gb[3*HS + j];
    float c2 = fsigm(f_)*cin[idx] + fsigm(i_)*ftanh(gg);
    cout[idx] = c2;
    hout[idx] = fsigm(o_)*ftanh(c2);
}

// ---------------- host orchestration ----------------------------------------
extern "C" void kernel_launch(void* const* d_in, const int* in_sizes, int n_in,
                              void* d_out, int out_size)
{
    const float* feature_map = (const float*)d_in[0];
    const float* batch_H     = (const float*)d_in[1];
    const float* hidden_h    = (const float*)d_in[2];
    const float* hidden_c    = (const float*)d_in[3];
    const int*   text        = (const int*)  d_in[4];
    const float* i2h_w       = (const float*)d_in[5];
    const float* h2h_w       = (const float*)d_in[6];
    const float* h2h_b       = (const float*)d_in[7];
    const float* conv_m2h_w  = (const float*)d_in[8];
    const float* conv_m2h_b  = (const float*)d_in[9];
    const float* conv_h2h_w  = (const float*)d_in[10];
    const float* conv_h2h_b  = (const float*)d_in[11];
    const float* score_w     = (const float*)d_in[12];
    const float* score_b     = (const float*)d_in[13];
    const float* rnn1_w_ih   = (const float*)d_in[14];
    const float* rnn1_w_hh   = (const float*)d_in[15];
    const float* rnn1_b_ih   = (const float*)d_in[16];
    const float* rnn1_b_hh   = (const float*)d_in[17];
    const float* hlin_w      = (const float*)d_in[18];
    const float* hlin_b      = (const float*)d_in[19];
    const float* rnn2_w_ih   = (const float*)d_in[20];
    const float* rnn2_w_hh   = (const float*)d_in[21];
    const float* rnn2_b_ih   = (const float*)d_in[22];
    const float* rnn2_b_hh   = (const float*)d_in[23];
    const float* gen_w       = (const float*)d_in[24];
    const float* gen_b       = (const float*)d_in[25];
    float* out = (float*)d_out;

    float *inpad3,*w2t,*fmh,*meanH,*bhproj,*Wq,*qb;
    float *h1a,*c1a,*h2a,*c2a,*h1b,*c1b,*h2b,*c2b,*q,*ctx,*gates,*cur;
    cudaGetSymbolAddress((void**)&inpad3,g_inpad3);
    cudaGetSymbolAddress((void**)&w2t,   g_w2t);
    cudaGetSymbolAddress((void**)&fmh,   g_fmh);
    cudaGetSymbolAddress((void**)&meanH, g_meanH);
    cudaGetSymbolAddress((void**)&bhproj,g_bhproj);
    cudaGetSymbolAddress((void**)&Wq,    g_Wq);
    cudaGetSymbolAddress((void**)&qb,    g_qb);
    cudaGetSymbolAddress((void**)&h1a, g_h1a); cudaGetSymbolAddress((void**)&c1a, g_c1a);
    cudaGetSymbolAddress((void**)&h2a, g_h2a); cudaGetSymbolAddress((void**)&c2a, g_c2a);
    cudaGetSymbolAddress((void**)&h1b, g_h1b); cudaGetSymbolAddress((void**)&c1b, g_c1b);
    cudaGetSymbolAddress((void**)&h2b, g_h2b); cudaGetSymbolAddress((void**)&c2b, g_c2b);
    cudaGetSymbolAddress((void**)&q,   g_q);   cudaGetSymbolAddress((void**)&ctx, g_ctx);
    cudaGetSymbolAddress((void**)&gates, g_gates); cudaGetSymbolAddress((void**)&cur, g_cur);

    // prep: shifted/padded input + transposed weights, then tensor-core conv
    {
        size_t tot = (size_t)3*BB*CH*10*32;
        pad3_kernel<<<(unsigned)((tot+255)/256),256>>>(feature_map, inpad3);
        w2t_kernel<<<(9*CH*CH+255)/256,256>>>(conv_m2h_w, w2t);
        conv_mma_kernel<<<dim3(4,2,BB),256>>>(inpad3, w2t, conv_m2h_b, fmh);
    }

    // mean over T, then bhproj = meanH @ i2h_w^T + h2h_b
    mean_kernel<<<512,256>>>(batch_H, meanH);
    gemm_kernel<<<dim3(8,4),256>>>(bhproj, HS,
        meanH, INSZ, i2h_w, INSZ, INSZ,
        nullptr,0,nullptr,0,0,
        h2h_b,nullptr, nullptr,0, nullptr,0,0, nullptr,0, 0, BB, HS);
    // Wq = conv1x1 @ h2h_w  (NN)
    gemm_kernel<<<dim3(8,8),256>>>(Wq, HS,
        conv_h2h_w, HS, h2h_w, HS, HS,
        nullptr,0,nullptr,0,0,
        nullptr,nullptr, nullptr,0, nullptr,0,0, nullptr,0, 1, HS, HS);
    // qb = bhproj @ conv1x1^T + conv_h2h_b
    gemm_kernel<<<dim3(8,4),256>>>(qb, HS,
        bhproj, HS, conv_h2h_w, HS, HS,
        nullptr,0,nullptr,0,0,
        conv_h2h_b,nullptr, nullptr,0, nullptr,0,0, nullptr,0, 0, BB, HS);
    // init states
    init_kernel<<<512,256>>>(hidden_h, hidden_c, h1a, h2a, c1a, c2a);

    float *h1c=h1a,*c1c=c1a,*h2c=h2a,*c2c=c2a;
    float *h1n=h1b,*c1n=c1b,*h2n=h2b,*c2n=c2b;

    for (int t=0; t<TT; t++){
        // q = qb + h2 @ Wq^T
        gemm_kernel<<<dim3(8,4),256>>>(q, HS,
            h2c, HS, Wq, HS, HS,
            nullptr,0,nullptr,0,0,
            nullptr,nullptr, qb, HS, nullptr,0,0, nullptr,0, 0, BB, HS);
        // attention -> ctx
        attn_kernel<<<BB,256>>>(fmh, q, score_w, score_b, ctx);
        // gates1 = ctx @ w_ih[:,:512]^T + onehot-gather + h1 @ w_hh^T + biases
        gemm_kernel<<<dim3(32,4),256>>>(gates, 4*HS,
            ctx, HS, rnn1_w_ih, INSZ+NC, HS,
            h1c, HS, rnn1_w_hh, HS, HS,
            rnn1_b_ih, rnn1_b_hh, nullptr,0,
            rnn1_w_ih, INSZ+NC, INSZ, text + t, TT, 0, BB, 4*HS);
        lstm_kernel<<<512,256>>>(gates, c1c, h1n, c1n);
        // cur = h1n @ hlin_w^T + hlin_b
        gemm_kernel<<<dim3(8,4),256>>>(cur, HS,
            h1n, HS, hlin_w, HS, HS,
            nullptr,0,nullptr,0,0,
            hlin_b, nullptr, nullptr,0, nullptr,0,0, nullptr,0, 0, BB, HS);
        // gates2 = cur @ w_ih^T + h2 @ w_hh^T + biases
        gemm_kernel<<<dim3(32,4),256>>>(gates, 4*HS,
            cur, HS, rnn2_w_ih, HS, HS,
            h2c, HS, rnn2_w_hh, HS, HS,
            rnn2_b_ih, rnn2_b_hh, nullptr,0,
            nullptr,0,0, nullptr,0, 0, BB, 4*HS);
        lstm_kernel<<<512,256>>>(gates, c2c, h2n, c2n);
        // probs[:, t, :] = h2n @ gen_w^T + gen_b
        gemm_kernel<<<dim3(1,4),256>>>(out + t*NC, TT*NC,
            h2n, HS, gen_w, HS, HS,
            nullptr,0,nullptr,0,0,
            gen_b, nullptr, nullptr,0, nullptr,0,0, nullptr,0, 0, BB, NC);

        float* tp;
        tp=h1c; h1c=h1n; h1n=tp;  tp=c1c; c1c=c1n; c1n=tp;
        tp=h2c; h2c=h2n; h2n=tp;  tp=c2c; c2c=c2n; c2n=tp;
    }
}

// round 4
// speedup vs baseline: 1.6517x; 1.1913x over previous
#include <cuda_runtime.h>
#include <math.h>
#include <stdint.h>

#define BB 256
#define HS 512
#define INSZ 512
#define NC 38
#define TT 26
#define CH 512
#define PP 256   /* 8*32 */

// ---------------- scratch (device globals; no allocation allowed) ----------
__device__ float g_inpad3[(size_t)3*BB*CH*10*32];  // kw-shifted zero-padded input
__device__ float g_w2t[9*CH*CH];                   // weights [khw][ic][oc]
__device__ float g_fmh[(size_t)BB*CH*PP];          // conv output, 134MB
__device__ float g_meanH[BB*INSZ];
__device__ float g_bhproj[BB*HS];
__device__ float g_Wq[HS*HS];                      // conv1x1 @ h2h_w
__device__ float g_qb[BB*HS];
__device__ float g_w1ih[4*HS*INSZ];                // rnn1_w_ih[:, :512] repacked ld=512
__device__ float g_h1a[BB*HS], g_c1a[BB*HS], g_h2a[BB*HS], g_c2a[BB*HS];
__device__ float g_h1b[BB*HS], g_c1b[BB*HS], g_c2b[BB*HS];
__device__ float g_h2hist[(size_t)TT*BB*HS];       // h2 per step (13.6MB)
__device__ float g_q[BB*HS];
__device__ float g_ctx[BB*HS];
__device__ float g_gates[BB*4*HS];
__device__ float g_cur[BB*HS];

// ---------------- fast math ------------------------------------------------
__device__ __forceinline__ float fexp(float x){
    float y; asm("ex2.approx.f32 %0, %1;" : "=f"(y) : "f"(x*1.4426950408889634f)); return y;
}
__device__ __forceinline__ float frcp(float x){
    float y; asm("rcp.approx.f32 %0, %1;" : "=f"(y) : "f"(x)); return y;
}
__device__ __forceinline__ float ftanh(float x){
    float xc = fminf(fmaxf(x, -15.f), 15.f);
    float t = fexp(2.f*xc);
    return (t - 1.f) * frcp(t + 1.f);
}
__device__ __forceinline__ float fsigm(float x){
    return frcp(1.f + fexp(-x));
}
__device__ __forceinline__ float tf32r(float x){
    uint32_t u; asm("cvt.rna.tf32.f32 %0, %1;" : "=r"(u) : "f"(x)); return __uint_as_float(u);
}
__device__ __forceinline__ void mma_tf32(float* d, const uint32_t* a, const uint32_t* b){
    asm volatile(
      "mma.sync.aligned.m16n8k8.row.col.f32.tf32.tf32.f32 "
      "{%0,%1,%2,%3},{%4,%5,%6,%7},{%8,%9},{%0,%1,%2,%3};"
      : "+f"(d[0]),"+f"(d[1]),"+f"(d[2]),"+f"(d[3])
      : "r"(a[0]),"r"(a[1]),"r"(a[2]),"r"(a[3]), "r"(b[0]),"r"(b[1]));
}

// ---------------- prep kernels ------------------------------------------------
__global__ void pad3_kernel(const float* __restrict__ in, float* __restrict__ out)
{
    size_t idx = (size_t)blockIdx.x*256 + threadIdx.x;
    if (idx >= (size_t)3*BB*CH*10*32) return;
    int c  = idx & 31;
    size_t t = idx >> 5;
    int rr = (int)(t % 10); t /= 10;
    int ic = (int)(t & 511); t >>= 9;
    int b  = (int)(t & 255); t >>= 8;
    int kw = (int)t;
    int r = rr - 1, cc = c + kw - 1;
    float v = 0.f;
    if ((unsigned)r < 8u && (unsigned)cc < 32u)
        v = in[((size_t)b*CH + ic)*PP + r*32 + cc];
    out[idx] = v;
}

__global__ void w2t_kernel(const float* __restrict__ w, float* __restrict__ out)
{
    int idx = blockIdx.x*256 + threadIdx.x;
    if (idx >= 9*CH*CH) return;
    int oc = idx & 511;
    int ic = (idx >> 9) & 511;
    int khw = idx >> 18;
    out[idx] = w[((size_t)oc*CH + ic)*9 + khw];
}

// repack rnn1_w_ih[:, :INSZ] from ld=550 to ld=512
__global__ void w1ih_kernel(const float* __restrict__ w, float* __restrict__ out)
{
    int idx = blockIdx.x*256 + threadIdx.x;
    if (idx >= 4*HS*INSZ) return;
    int k = idx & 511;
    int n = idx >> 9;
    out[idx] = w[(size_t)n*(INSZ+NC) + k];
}

// ---------------- conv 3x3 SAME via tf32 mma ---------------------------------
__global__ void __launch_bounds__(256, 2) conv_mma_kernel(
    const float* __restrict__ inp3, const float* __restrict__ w2t,
    const float* __restrict__ bias, float* __restrict__ out)
{
    __shared__ float As[16][136];
    __shared__ float Bs[16][136];
    const int b  = blockIdx.z;
    const int m0 = blockIdx.y * 128;
    const int n0 = blockIdx.x * 128;
    const int tid = threadIdx.x;
    const int lane = tid & 31, warp = tid >> 5;
    const int wm = (warp >> 2) * 64;
    const int wn = (warp & 3) * 32;
    const int gid = lane >> 2, tig = lane & 3;

    float acc[4][4][4];
    #pragma unroll
    for (int i=0;i<4;i++)
      #pragma unroll
      for (int j=0;j<4;j++)
        #pragma unroll
        for (int k=0;k<4;k++) acc[i][j][k]=0.f;

    const int a_kk = tid >> 4;
    const int a_m  = (tid & 15) * 8;
    const int p    = m0 + a_m;
    const int r    = p >> 5;
    const int c    = p & 31;

    for (int khw = 0; khw < 9; ++khw){
        const int kh = khw / 3, kw = khw - kh*3;
        const float* abase = inp3 + (((size_t)kw*BB + b)*CH + a_kk)*320
                                  + (size_t)(r + kh)*32 + c;
        const float* bbase = w2t + (size_t)khw*CH*CH + (size_t)a_kk*CH + n0 + a_m;
        for (int ic0 = 0; ic0 < CH; ic0 += 16){
            float4 av0 = *(const float4*)(abase + (size_t)ic0*320);
            float4 av1 = *(const float4*)(abase + (size_t)ic0*320 + 4);
            float4 bv0 = *(const float4*)(bbase + (size_t)ic0*CH);
            float4 bv1 = *(const float4*)(bbase + (size_t)ic0*CH + 4);
            __syncthreads();
            av0.x=tf32r(av0.x); av0.y=tf32r(av0.y); av0.z=tf32r(av0.z); av0.w=tf32r(av0.w);
            av1.x=tf32r(av1.x); av1.y=tf32r(av1.y); av1.z=tf32r(av1.z); av1.w=tf32r(av1.w);
            bv0.x=tf32r(bv0.x); bv0.y=tf32r(bv0.y); bv0.z=tf32r(bv0.z); bv0.w=tf32r(bv0.w);
            bv1.x=tf32r(bv1.x); bv1.y=tf32r(bv1.y); bv1.z=tf32r(bv1.z); bv1.w=tf32r(bv1.w);
            *(float4*)&As[a_kk][a_m]     = av0;
            *(float4*)&As[a_kk][a_m + 4] = av1;
            *(float4*)&Bs[a_kk][a_m]     = bv0;
            *(float4*)&Bs[a_kk][a_m + 4] = bv1;
            __syncthreads();
            #pragma unroll
            for (int s = 0; s < 2; ++s){
                const int kb = s*8 + tig;
                uint32_t afr[4][4], bfr[4][2];
                #pragma unroll
                for (int mi=0; mi<4; ++mi){
                    int rowb = wm + mi*16 + gid;
                    afr[mi][0] = __float_as_uint(As[kb  ][rowb]);
                    afr[mi][1] = __float_as_uint(As[kb  ][rowb+8]);
                    afr[mi][2] = __float_as_uint(As[kb+4][rowb]);
                    afr[mi][3] = __float_as_uint(As[kb+4][rowb+8]);
                }
                #pragma unroll
                for (int ni=0; ni<4; ++ni){
                    int colb = wn + ni*8 + gid;
                    bfr[ni][0] = __float_as_uint(Bs[kb  ][colb]);
                    bfr[ni][1] = __float_as_uint(Bs[kb+4][colb]);
                }
                #pragma unroll
                for (int mi=0; mi<4; ++mi)
                    #pragma unroll
                    for (int ni=0; ni<4; ++ni)
                        mma_tf32(acc[mi][ni], afr[mi], bfr[ni]);
            }
        }
    }

    #pragma unroll
    for (int mi=0; mi<4; ++mi){
        int prow = m0 + wm + mi*16 + gid;
        #pragma unroll
        for (int ni=0; ni<4; ++ni){
            int oc = n0 + wn + ni*8 + tig*2;
            float bz0 = bias[oc], bz1 = bias[oc+1];
            float* o0 = out + ((size_t)b*CH + oc)*PP;
            o0[prow]          = acc[mi][ni][0] + bz0;
            o0[PP + prow]     = acc[mi][ni][1] + bz1;
            o0[prow + 8]      = acc[mi][ni][2] + bz0;
            o0[PP + prow + 8] = acc[mi][ni][3] + bz1;
        }
    }
}

// ---------------- tf32 mma GEMM for recurrent-step matmuls ------------------
// NOTE: all lda/ldw passed here MUST be multiples of 4 (float4 loads).
__global__ void __launch_bounds__(256, 2) gemm_tf32_kernel(
    float* __restrict__ C, int ldc,
    const float* __restrict__ A1, int lda1, const float* __restrict__ W1, int ldw1, int K1,
    const float* __restrict__ A2, int lda2, const float* __restrict__ W2, int ldw2, int K2,
    const float* __restrict__ bias1, const float* __restrict__ bias2,
    const float* __restrict__ Cadd, int ldadd,
    const float* __restrict__ Wg, int ldwg, int gcolbase,
    const int* __restrict__ textcol, int textstride)
{
    __shared__ float As[128][20];
    __shared__ float Bs[128][20];
    const int m0 = blockIdx.y * 128;
    const int n0 = blockIdx.x * 128;
    const int tid = threadIdx.x;
    const int lane = tid & 31, warp = tid >> 5;
    const int wm = (warp >> 2) * 64;
    const int wn = (warp & 3) * 32;
    const int gid = lane >> 2, tig = lane & 3;

    const int lrow = tid >> 2;          // 0..63
    const int lk4  = (tid & 3) * 4;     // 0,4,8,12

    float acc[4][4][4];
    #pragma unroll
    for (int i=0;i<4;i++)
      #pragma unroll
      for (int j=0;j<4;j++)
        #pragma unroll
        for (int k=0;k<4;k++) acc[i][j][k]=0.f;

    #pragma unroll 1
    for (int pass = 0; pass < 2; ++pass){
        const float* A = pass ? A2 : A1;
        const float* W = pass ? W2 : W1;
        if (A == nullptr) continue;
        const int K   = pass ? K2  : K1;
        const int lda = pass ? lda2: lda1;
        const int ldw = pass ? ldw2: ldw1;

        for (int k0 = 0; k0 < K; k0 += 16){
            float4 av0 = *(const float4*)(A + (size_t)(m0+lrow)*lda    + k0 + lk4);
            float4 av1 = *(const float4*)(A + (size_t)(m0+lrow+64)*lda + k0 + lk4);
            float4 bv0 = *(const float4*)(W + (size_t)(n0+lrow)*ldw    + k0 + lk4);
            float4 bv1 = *(const float4*)(W + (size_t)(n0+lrow+64)*ldw + k0 + lk4);
            __syncthreads();
            av0.x=tf32r(av0.x); av0.y=tf32r(av0.y); av0.z=tf32r(av0.z); av0.w=tf32r(av0.w);
            av1.x=tf32r(av1.x); av1.y=tf32r(av1.y); av1.z=tf32r(av1.z); av1.w=tf32r(av1.w);
            bv0.x=tf32r(bv0.x); bv0.y=tf32r(bv0.y); bv0.z=tf32r(bv0.z); bv0.w=tf32r(bv0.w);
            bv1.x=tf32r(bv1.x); bv1.y=tf32r(bv1.y); bv1.z=tf32r(bv1.z); bv1.w=tf32r(bv1.w);
            *(float4*)&As[lrow][lk4]    = av0;
            *(float4*)&As[lrow+64][lk4] = av1;
            *(float4*)&Bs[lrow][lk4]    = bv0;
            *(float4*)&Bs[lrow+64][lk4] = bv1;
            __syncthreads();
            #pragma unroll
            for (int s = 0; s < 2; ++s){
                const int kb = s*8 + tig;
                uint32_t afr[4][4], bfr[4][2];
                #pragma unroll
                for (int mi=0; mi<4; ++mi){
                    int rowb = wm + mi*16 + gid;
                    afr[mi][0] = __float_as_uint(As[rowb  ][kb]);
                    afr[mi][1] = __float_as_uint(As[rowb+8][kb]);
                    afr[mi][2] = __float_as_uint(As[rowb  ][kb+4]);
                    afr[mi][3] = __float_as_uint(As[rowb+8][kb+4]);
                }
                #pragma unroll
                for (int ni=0; ni<4; ++ni){
                    int colb = wn + ni*8 + gid;
                    bfr[ni][0] = __float_as_uint(Bs[colb][kb]);
                    bfr[ni][1] = __float_as_uint(Bs[colb][kb+4]);
                }
                #pragma unroll
                for (int mi=0; mi<4; ++mi)
                    #pragma unroll
                    for (int ni=0; ni<4; ++ni)
                        mma_tf32(acc[mi][ni], afr[mi], bfr[ni]);
            }
        }
    }

    #pragma unroll
    for (int mi=0; mi<4; ++mi){
        int m = m0 + wm + mi*16 + gid;
        int tc0 = 0, tc1 = 0;
        if (Wg){ tc0 = textcol[m*textstride]; tc1 = textcol[(m+8)*textstride]; }
        #pragma unroll
        for (int ni=0; ni<4; ++ni){
            int n = n0 + wn + ni*8 + tig*2;
            float b0 = 0.f, b1 = 0.f;
            if (bias1){ b0 += bias1[n]; b1 += bias1[n+1]; }
            if (bias2){ b0 += bias2[n]; b1 += bias2[n+1]; }
            float v00 = acc[mi][ni][0] + b0;
            float v01 = acc[mi][ni][1] + b1;
            float v10 = acc[mi][ni][2] + b0;
            float v11 = acc[mi][ni][3] + b1;
            if (Cadd){
                v00 += Cadd[(size_t)m*ldadd + n];     v01 += Cadd[(size_t)m*ldadd + n+1];
                v10 += Cadd[(size_t)(m+8)*ldadd + n]; v11 += Cadd[(size_t)(m+8)*ldadd + n+1];
            }
            if (Wg){
                v00 += Wg[(size_t)n*ldwg + gcolbase + tc0];
                v01 += Wg[(size_t)(n+1)*ldwg + gcolbase + tc0];
                v10 += Wg[(size_t)n*ldwg + gcolbase + tc1];
                v11 += Wg[(size_t)(n+1)*ldwg + gcolbase + tc1];
            }
            C[(size_t)m*ldc + n]       = v00;
            C[(size_t)m*ldc + n+1]     = v01;
            C[(size_t)(m+8)*ldc + n]   = v10;
            C[(size_t)(m+8)*ldc + n+1] = v11;
        }
    }
}

// ---------------- fp32 fused GEMM (prologue + generator) --------------------
// remap!=0: row m encodes (t,b) as m=t*BB+b; output index = (b*TT+t)*NC + n
__global__ void gemm_kernel(
    float* __restrict__ C, int ldc,
    const float* __restrict__ A1, int lda1, const float* __restrict__ W1, int ldw1, int K1,
    const float* __restrict__ bias1,
    const float* __restrict__ Cadd, int ldadd,
    int nn, int remap, int M, int N)
{
    __shared__ float As[16][68];
    __shared__ float Bs[16][68];
    int m0 = blockIdx.y * 64;
    int n0 = blockIdx.x * 64;
    int tid = threadIdx.x;
    int tx = tid & 15, ty = tid >> 4;

    float acc[4][4];
    #pragma unroll
    for (int i=0;i<4;i++)
        #pragma unroll
        for (int j=0;j<4;j++) acc[i][j]=0.f;

    for (int k0=0; k0<K1; k0+=16){
        #pragma unroll
        for (int i=0;i<4;i++){
            int e = i*256 + tid;
            int m = e >> 4, kk = e & 15;
            int gm = m0 + m, gk = k0 + kk;
            As[kk][m] = (gm < M && gk < K1) ? A1[(size_t)gm*lda1 + gk] : 0.f;
        }
        if (nn){
            #pragma unroll
            for (int i=0;i<4;i++){
                int e = i*256 + tid;
                int kk = e >> 6, n = e & 63;
                int gn = n0 + n, gk = k0 + kk;
                Bs[kk][n] = (gn < N && gk < K1) ? W1[(size_t)gk*ldw1 + gn] : 0.f;
            }
        } else {
            #pragma unroll
            for (int i=0;i<4;i++){
                int e = i*256 + tid;
                int n = e >> 4, kk = e & 15;
                int gn = n0 + n, gk = k0 + kk;
                Bs[kk][n] = (gn < N && gk < K1) ? W1[(size_t)gn*ldw1 + gk] : 0.f;
            }
        }
        __syncthreads();
        #pragma unroll
        for (int kk=0; kk<16; kk++){
            float4 a = *(const float4*)&As[kk][ty*4];
            float4 b = *(const float4*)&Bs[kk][tx*4];
            acc[0][0]+=a.x*b.x; acc[0][1]+=a.x*b.y; acc[0][2]+=a.x*b.z; acc[0][3]+=a.x*b.w;
            acc[1][0]+=a.y*b.x; acc[1][1]+=a.y*b.y; acc[1][2]+=a.y*b.z; acc[1][3]+=a.y*b.w;
            acc[2][0]+=a.z*b.x; acc[2][1]+=a.z*b.y; acc[2][2]+=a.z*b.z; acc[2][3]+=a.z*b.w;
            acc[3][0]+=a.w*b.x; acc[3][1]+=a.w*b.y; acc[3][2]+=a.w*b.z; acc[3][3]+=a.w*b.w;
        }
        __syncthreads();
    }

    #pragma unroll
    for (int i=0;i<4;i++){
        int m = m0 + ty*4 + i;
        if (m >= M) continue;
        #pragma unroll
        for (int j=0;j<4;j++){
            int n = n0 + tx*4 + j;
            if (n >= N) continue;
            float v = acc[i][j];
            if (bias1) v += bias1[n];
            if (Cadd)  v += Cadd[(size_t)m*ldadd + n];
            if (remap){
                int t = m >> 8, b = m & 255;
                C[(size_t)(b*TT + t)*NC + n] = v;
            } else {
                C[(size_t)m*ldc + n] = v;
            }
        }
    }
}

// ---------------- mean over T of batch_H ------------------------------------
__global__ void mean_kernel(const float* __restrict__ bH, float* __restrict__ out)
{
    int idx = blockIdx.x*256 + threadIdx.x;
    if (idx >= BB*INSZ) return;
    int b = idx >> 9, k = idx & 511;
    const float* p = bH + (size_t)b*TT*INSZ + k;
    float s = 0.f;
    #pragma unroll
    for (int t=0;t<TT;t++) s += p[t*INSZ];
    out[idx] = s * (1.0f/26.0f);
}

// ---------------- init h0/c0 -------------------------------------------------
__global__ void init_kernel(const float* __restrict__ hh, const float* __restrict__ hc,
                            float* __restrict__ h1, float* __restrict__ h2,
                            float* __restrict__ c1, float* __restrict__ c2)
{
    int idx = blockIdx.x*256 + threadIdx.x;
    if (idx >= BB*HS) return;
    float h0 = 0.5f*(hh[idx] + hh[BB*HS + idx]);
    float c0 = 0.5f*(hc[idx] + hc[BB*HS + idx]);
    h1[idx]=h0; h2[idx]=h0; c1[idx]=c0; c2[idx]=c0;
}

// ---------------- attention: e -> softmax -> context ------------------------
__global__ void attn_kernel(const float* __restrict__ fmh, const float* __restrict__ q,
                            const float* __restrict__ ws, const float* __restrict__ sb,
                            float* __restrict__ ctx)
{
    __shared__ float qs[CH];
    __shared__ float wss[CH];
    __shared__ float red[256];
    __shared__ float alpha[256];

    int b = blockIdx.x;
    int p = threadIdx.x;
    const float* f = fmh + (size_t)b * CH * PP;

    qs[p]       = q[b*HS + p];
    qs[p+256]   = q[b*HS + p + 256];
    wss[p]      = ws[p];
    wss[p+256]  = ws[p+256];
    __syncthreads();

    float acc = 0.f;
    #pragma unroll 4
    for (int c=0; c<CH; c++){
        acc += ftanh(f[c*PP + p] + qs[c]) * wss[c];
    }
    float e = acc + sb[0];

    red[p] = e; __syncthreads();
    #pragma unroll
    for (int s=128; s>0; s>>=1){
        if (p < s) red[p] = fmaxf(red[p], red[p+s]);
        __syncthreads();
    }
    float mx = red[0];
    __syncthreads();
    float ex = fexp(e - mx);
    red[p] = ex; __syncthreads();
    #pragma unroll
    for (int s=128; s>0; s>>=1){
        if (p < s) red[p] += red[p+s];
        __syncthreads();
    }
    float sum = red[0];
    __syncthreads();
    alpha[p] = ex * frcp(sum);
    __syncthreads();

    int lane = p & 31, wid = p >> 5;
    for (int c = wid; c < CH; c += 8){
        const float* fr = f + c*PP;
        float s = 0.f;
        #pragma unroll
        for (int pp = lane; pp < PP; pp += 32) s += alpha[pp] * fr[pp];
        #pragma unroll
        for (int o=16; o>0; o>>=1) s += __shfl_down_sync(0xffffffffu, s, o);
        if (lane == 0) ctx[b*HS + c] = s;
    }
}

// ---------------- LSTM pointwise --------------------------------------------
__global__ void lstm_kernel(const float* __restrict__ g, const float* __restrict__ cin,
                            float* __restrict__ hout, float* __restrict__ cout)
{
    int idx = blockIdx.x*256 + threadIdx.x;
    if (idx >= BB*HS) return;
    int b = idx >> 9, j = idx & 511;
    const float* gb = g + (size_t)b*4*HS;
    float i_ = gb[j], f_ = gb[HS + j], gg = gb[2*HS + j], o_ = gb[3*HS + j];
    float c2 = fsigm(f_)*cin[idx] + fsigm(i_)*ftanh(gg);
    cout[idx] = c2;
    hout[idx] = fsigm(o_)*ftanh(c2);
}

// ---------------- host orchestration ----------------------------------------
extern "C" void kernel_launch(void* const* d_in, const int* in_sizes, int n_in,
                              void* d_out, int out_size)
{
    const float* feature_map = (const float*)d_in[0];
    const float* batch_H     = (const float*)d_in[1];
    const float* hidden_h    = (const float*)d_in[2];
    const float* hidden_c    = (const float*)d_in[3];
    const int*   text        = (const int*)  d_in[4];
    const float* i2h_w       = (const float*)d_in[5];
    const float* h2h_w       = (const float*)d_in[6];
    const float* h2h_b       = (const float*)d_in[7];
    const float* conv_m2h_w  = (const float*)d_in[8];
    const float* conv_m2h_b  = (const float*)d_in[9];
    const float* conv_h2h_w  = (const float*)d_in[10];
    const float* conv_h2h_b  = (const float*)d_in[11];
    const float* score_w     = (const float*)d_in[12];
    const float* score_b     = (const float*)d_in[13];
    const float* rnn1_w_ih   = (const float*)d_in[14];
    const float* rnn1_w_hh   = (const float*)d_in[15];
    const float* rnn1_b_ih   = (const float*)d_in[16];
    const float* rnn1_b_hh   = (const float*)d_in[17];
    const float* hlin_w      = (const float*)d_in[18];
    const float* hlin_b      = (const float*)d_in[19];
    const float* rnn2_w_ih   = (const float*)d_in[20];
    const float* rnn2_w_hh   = (const float*)d_in[21];
    const float* rnn2_b_ih   = (const float*)d_in[22];
    const float* rnn2_b_hh   = (const float*)d_in[23];
    const float* gen_w       = (const float*)d_in[24];
    const float* gen_b       = (const float*)d_in[25];
    float* out = (float*)d_out;

    float *inpad3,*w2t,*fmh,*meanH,*bhproj,*Wq,*qb,*w1ih;
    float *h1a,*c1a,*h2a,*c2a,*h1b,*c1b,*c2b,*hist,*q,*ctx,*gates,*cur;
    cudaGetSymbolAddress((void**)&inpad3,g_inpad3);
    cudaGetSymbolAddress((void**)&w2t,   g_w2t);
    cudaGetSymbolAddress((void**)&fmh,   g_fmh);
    cudaGetSymbolAddress((void**)&meanH, g_meanH);
    cudaGetSymbolAddress((void**)&bhproj,g_bhproj);
    cudaGetSymbolAddress((void**)&Wq,    g_Wq);
    cudaGetSymbolAddress((void**)&qb,    g_qb);
    cudaGetSymbolAddress((void**)&w1ih,  g_w1ih);
    cudaGetSymbolAddress((void**)&h1a, g_h1a); cudaGetSymbolAddress((void**)&c1a, g_c1a);
    cudaGetSymbolAddress((void**)&h2a, g_h2a); cudaGetSymbolAddress((void**)&c2a, g_c2a);
    cudaGetSymbolAddress((void**)&h1b, g_h1b); cudaGetSymbolAddress((void**)&c1b, g_c1b);
    cudaGetSymbolAddress((void**)&c2b, g_c2b); cudaGetSymbolAddress((void**)&hist, g_h2hist);
    cudaGetSymbolAddress((void**)&q,   g_q);   cudaGetSymbolAddress((void**)&ctx, g_ctx);
    cudaGetSymbolAddress((void**)&gates, g_gates); cudaGetSymbolAddress((void**)&cur, g_cur);

    // conv prep + tensor-core conv
    {
        size_t tot = (size_t)3*BB*CH*10*32;
        pad3_kernel<<<(unsigned)((tot+255)/256),256>>>(feature_map, inpad3);
        w2t_kernel<<<(9*CH*CH+255)/256,256>>>(conv_m2h_w, w2t);
        w1ih_kernel<<<(4*HS*INSZ+255)/256,256>>>(rnn1_w_ih, w1ih);
        conv_mma_kernel<<<dim3(4,2,BB),256>>>(inpad3, w2t, conv_m2h_b, fmh);
    }

    // prologue (fp32)
    mean_kernel<<<512,256>>>(batch_H, meanH);
    gemm_kernel<<<dim3(8,4),256>>>(bhproj, HS, meanH, INSZ, i2h_w, INSZ, INSZ,
                                   h2h_b, nullptr,0, 0,0, BB, HS);
    gemm_kernel<<<dim3(8,8),256>>>(Wq, HS, conv_h2h_w, HS, h2h_w, HS, HS,
                                   nullptr, nullptr,0, 1,0, HS, HS);
    gemm_kernel<<<dim3(8,4),256>>>(qb, HS, bhproj, HS, conv_h2h_w, HS, HS,
                                   conv_h2h_b, nullptr,0, 0,0, BB, HS);
    init_kernel<<<512,256>>>(hidden_h, hidden_c, h1a, h2a, c1a, c2a);

    float *h1c=h1a,*c1c=c1a,*h2c=h2a,*c2c=c2a;
    float *h1n=h1b,*c1n=c1b,*c2n=c2b;

    for (int t=0; t<TT; t++){
        float* h2n = hist + (size_t)t*BB*HS;
        // q = qb + h2 @ Wq^T
        gemm_tf32_kernel<<<dim3(4,2),256>>>(q, HS,
            h2c, HS, Wq, HS, HS, nullptr,0,nullptr,0,0,
            nullptr,nullptr, qb, HS, nullptr,0,0, nullptr,0);
        // attention -> ctx
        attn_kernel<<<BB,256>>>(fmh, q, score_w, score_b, ctx);
        // gates1: ctx@w1ih^T (repacked, ld=512) + h1@w_hh^T + biases + onehot gather
        gemm_tf32_kernel<<<dim3(16,2),256>>>(gates, 4*HS,
            ctx, HS, w1ih, INSZ, HS,
            h1c, HS, rnn1_w_hh, HS, HS,
            rnn1_b_ih, rnn1_b_hh, nullptr,0,
            rnn1_w_ih, INSZ+NC, INSZ, text + t, TT);
        lstm_kernel<<<512,256>>>(gates, c1c, h1n, c1n);
        // cur = h1n @ hlin_w^T + hlin_b
        gemm_tf32_kernel<<<dim3(4,2),256>>>(cur, HS,
            h1n, HS, hlin_w, HS, HS, nullptr,0,nullptr,0,0,
            hlin_b, nullptr, nullptr,0, nullptr,0,0, nullptr,0);
        // gates2
        gemm_tf32_kernel<<<dim3(16,2),256>>>(gates, 4*HS,
            cur, HS, rnn2_w_ih, HS, HS,
            h2c, HS, rnn2_w_hh, HS, HS,
            rnn2_b_ih, rnn2_b_hh, nullptr,0,
            nullptr,0,0, nullptr,0);
        lstm_kernel<<<512,256>>>(gates, c2c, h2n, c2n);

        float* tp;
        tp=h1c; h1c=h1n; h1n=tp;  tp=c1c; c1c=c1n; c1n=tp;
        h2c = h2n;
        tp=c2c; c2c=c2n; c2n=tp;
    }

    // probs: one batched GEMM over all timesteps, output remapped to [b][t][n]
    gemm_kernel<<<dim3(1,104),256>>>(out, NC,
        hist, HS, gen_w, HS, HS,
        gen_b, nullptr,0, 0,1, TT*BB, NC);
}

// round 6
// speedup vs baseline: 1.6734x; 1.0132x over previous
#include <cuda_runtime.h>
#include <math.h>
#include <stdint.h>

#define BB 256
#define HS 512
#define INSZ 512
#define NC 38
#define TT 26
#define CH 512
#define PP 256   /* 8*32 */

// ---------------- scratch (device globals; no allocation allowed) ----------
__device__ float g_inpad3[(size_t)3*BB*CH*10*32];  // kw-shifted zero-padded input
__device__ float g_w2t[9*CH*CH];                   // weights [khw][ic][oc]
__device__ float g_fmh[(size_t)BB*CH*PP];          // conv output, 134MB
__device__ float g_meanH[BB*INSZ];
__device__ float g_bhproj[BB*HS];
__device__ float g_Wq[HS*HS];                      // conv1x1 @ h2h_w
__device__ float g_qb[BB*HS];
__device__ float g_w1ih[4*HS*INSZ];                // rnn1_w_ih[:, :512] repacked ld=512
__device__ float g_h1a[BB*HS], g_c1a[BB*HS], g_h2a[BB*HS], g_c2a[BB*HS];
__device__ float g_h1b[BB*HS], g_c1b[BB*HS], g_c2b[BB*HS];
__device__ float g_h2hist[(size_t)TT*BB*HS];       // h2 per step (13.6MB)
__device__ float g_q[BB*HS];
__device__ float g_ctx[BB*HS];
__device__ float g_gates[BB*4*HS];
__device__ float g_cur[BB*HS];

// ---------------- fast math ------------------------------------------------
__device__ __forceinline__ float fexp(float x){
    float y; asm("ex2.approx.f32 %0, %1;" : "=f"(y) : "f"(x*1.4426950408889634f)); return y;
}
__device__ __forceinline__ float frcp(float x){
    float y; asm("rcp.approx.f32 %0, %1;" : "=f"(y) : "f"(x)); return y;
}
__device__ __forceinline__ float ftanh(float x){
    float xc = fminf(fmaxf(x, -15.f), 15.f);
    float t = fexp(2.f*xc);
    return (t - 1.f) * frcp(t + 1.f);
}
__device__ __forceinline__ float fsigm(float x){
    return frcp(1.f + fexp(-x));
}
__device__ __forceinline__ float tf32r(float x){
    uint32_t u; asm("cvt.rna.tf32.f32 %0, %1;" : "=r"(u) : "f"(x)); return __uint_as_float(u);
}
__device__ __forceinline__ void mma_tf32(float* d, const uint32_t* a, const uint32_t* b){
    asm volatile(
      "mma.sync.aligned.m16n8k8.row.col.f32.tf32.tf32.f32 "
      "{%0,%1,%2,%3},{%4,%5,%6,%7},{%8,%9},{%0,%1,%2,%3};"
      : "+f"(d[0]),"+f"(d[1]),"+f"(d[2]),"+f"(d[3])
      : "r"(a[0]),"r"(a[1]),"r"(a[2]),"r"(a[3]), "r"(b[0]),"r"(b[1]));
}

// ---------------- prep kernels ------------------------------------------------
__global__ void pad3_kernel(const float* __restrict__ in, float* __restrict__ out)
{
    size_t idx = (size_t)blockIdx.x*256 + threadIdx.x;
    if (idx >= (size_t)3*BB*CH*10*32) return;
    int c  = idx & 31;
    size_t t = idx >> 5;
    int rr = (int)(t % 10); t /= 10;
    int ic = (int)(t & 511); t >>= 9;
    int b  = (int)(t & 255); t >>= 8;
    int kw = (int)t;
    int r = rr - 1, cc = c + kw - 1;
    float v = 0.f;
    if ((unsigned)r < 8u && (unsigned)cc < 32u)
        v = in[((size_t)b*CH + ic)*PP + r*32 + cc];
    out[idx] = v;
}

__global__ void w2t_kernel(const float* __restrict__ w, float* __restrict__ out)
{
    int idx = blockIdx.x*256 + threadIdx.x;
    if (idx >= 9*CH*CH) return;
    int oc = idx & 511;
    int ic = (idx >> 9) & 511;
    int khw = idx >> 18;
    out[idx] = w[((size_t)oc*CH + ic)*9 + khw];
}

// repack rnn1_w_ih[:, :INSZ] from ld=550 to ld=512
__global__ void w1ih_kernel(const float* __restrict__ w, float* __restrict__ out)
{
    int idx = blockIdx.x*256 + threadIdx.x;
    if (idx >= 4*HS*INSZ) return;
    int k = idx & 511;
    int n = idx >> 9;
    out[idx] = w[(size_t)n*(INSZ+NC) + k];
}

// ---------------- conv 3x3 SAME via tf32 mma, software-pipelined -------------
// block tile 128(p) x 128(oc); 8 warps (2m x 4n); 288 K-slabs of 16
__global__ void __launch_bounds__(256, 1) conv_mma_kernel(
    const float* __restrict__ inp3, const float* __restrict__ w2t,
    const float* __restrict__ bias, float* __restrict__ out)
{
    __shared__ float As[16][136];
    __shared__ float Bs[16][136];
    const int b  = blockIdx.z;
    const int m0 = blockIdx.y * 128;
    const int n0 = blockIdx.x * 128;
    const int tid = threadIdx.x;
    const int lane = tid & 31, warp = tid >> 5;
    const int wm = (warp >> 2) * 64;
    const int wn = (warp & 3) * 32;
    const int gid = lane >> 2, tig = lane & 3;

    float acc[4][4][4];
    #pragma unroll
    for (int i=0;i<4;i++)
      #pragma unroll
      for (int j=0;j<4;j++)
        #pragma unroll
        for (int k=0;k<4;k++) acc[i][j][k]=0.f;

    const int a_kk = tid >> 4;        // 0..15 (k row within slab)
    const int a_m  = (tid & 15) * 8;  // 0..120
    const int p    = m0 + a_m;
    const int r    = p >> 5;
    const int c    = p & 31;

    float4 av0, av1, bv0, bv1;

#define CONV_LOAD(s) do { \
        int khw_ = (s) >> 5; \
        int ic_  = (((s) & 31) << 4) + a_kk; \
        int kh_ = khw_ / 3, kw_ = khw_ - kh_*3; \
        const float* ap_ = inp3 + (((size_t)kw_*BB + b)*CH + ic_)*320 \
                                + (size_t)(r + kh_)*32 + c; \
        const float* bp_ = w2t + (size_t)khw_*CH*CH + (size_t)ic_*CH + n0 + a_m; \
        av0 = *(const float4*)ap_;      av1 = *(const float4*)(ap_ + 4); \
        bv0 = *(const float4*)bp_;      bv1 = *(const float4*)(bp_ + 4); \
    } while(0)

    CONV_LOAD(0);

    for (int s = 0; s < 288; ++s){
        __syncthreads();   // previous slab's mma done reading smem
        As[a_kk][a_m  ] = tf32r(av0.x); As[a_kk][a_m+1] = tf32r(av0.y);
        As[a_kk][a_m+2] = tf32r(av0.z); As[a_kk][a_m+3] = tf32r(av0.w);
        As[a_kk][a_m+4] = tf32r(av1.x); As[a_kk][a_m+5] = tf32r(av1.y);
        As[a_kk][a_m+6] = tf32r(av1.z); As[a_kk][a_m+7] = tf32r(av1.w);
        Bs[a_kk][a_m  ] = tf32r(bv0.x); Bs[a_kk][a_m+1] = tf32r(bv0.y);
        Bs[a_kk][a_m+2] = tf32r(bv0.z); Bs[a_kk][a_m+3] = tf32r(bv0.w);
        Bs[a_kk][a_m+4] = tf32r(bv1.x); Bs[a_kk][a_m+5] = tf32r(bv1.y);
        Bs[a_kk][a_m+6] = tf32r(bv1.z); Bs[a_kk][a_m+7] = tf32r(bv1.w);
        __syncthreads();

        if (s < 287) CONV_LOAD(s + 1);   // prefetch next slab (hides LDG latency)

        #pragma unroll
        for (int ss = 0; ss < 2; ++ss){
            const int kb = ss*8 + tig;
            uint32_t afr[4][4], bfr[4][2];
            #pragma unroll
            for (int mi=0; mi<4; ++mi){
                int rowb = wm + mi*16 + gid;
                afr[mi][0] = __float_as_uint(As[kb  ][rowb]);
                afr[mi][1] = __float_as_uint(As[kb  ][rowb+8]);
                afr[mi][2] = __float_as_uint(As[kb+4][rowb]);
                afr[mi][3] = __float_as_uint(As[kb+4][rowb+8]);
            }
            #pragma unroll
            for (int ni=0; ni<4; ++ni){
                int colb = wn + ni*8 + gid;
                bfr[ni][0] = __float_as_uint(Bs[kb  ][colb]);
                bfr[ni][1] = __float_as_uint(Bs[kb+4][colb]);
            }
            #pragma unroll
            for (int mi=0; mi<4; ++mi)
                #pragma unroll
                for (int ni=0; ni<4; ++ni)
                    mma_tf32(acc[mi][ni], afr[mi], bfr[ni]);
        }
    }
#undef CONV_LOAD

    #pragma unroll
    for (int mi=0; mi<4; ++mi){
        int prow = m0 + wm + mi*16 + gid;
        #pragma unroll
        for (int ni=0; ni<4; ++ni){
            int oc = n0 + wn + ni*8 + tig*2;
            float bz0 = bias[oc], bz1 = bias[oc+1];
            float* o0 = out + ((size_t)b*CH + oc)*PP;
            o0[prow]          = acc[mi][ni][0] + bz0;
            o0[PP + prow]     = acc[mi][ni][1] + bz1;
            o0[prow + 8]      = acc[mi][ni][2] + bz0;
            o0[PP + prow + 8] = acc[mi][ni][3] + bz1;
        }
    }
}

// ---------------- tf32 mma GEMM, software-pipelined --------------------------
// NOTE: all lda/ldw MUST be multiples of 4 (float4 loads).
__global__ void __launch_bounds__(256, 1) gemm_tf32_kernel(
    float* __restrict__ C, int ldc,
    const float* __restrict__ A1, int lda1, const float* __restrict__ W1, int ldw1, int K1,
    const float* __restrict__ A2, int lda2, const float* __restrict__ W2, int ldw2, int K2,
    const float* __restrict__ bias1, const float* __restrict__ bias2,
    const float* __restrict__ Cadd, int ldadd,
    const float* __restrict__ Wg, int ldwg, int gcolbase,
    const int* __restrict__ textcol, int textstride)
{
    __shared__ float As[128][20];
    __shared__ float Bs[128][20];
    const int m0 = blockIdx.y * 128;
    const int n0 = blockIdx.x * 128;
    const int tid = threadIdx.x;
    const int lane = tid & 31, warp = tid >> 5;
    const int wm = (warp >> 2) * 64;
    const int wn = (warp & 3) * 32;
    const int gid = lane >> 2, tig = lane & 3;

    const int lrow = tid >> 2;          // 0..63
    const int lk4  = (tid & 3) * 4;     // 0,4,8,12

    float acc[4][4][4];
    #pragma unroll
    for (int i=0;i<4;i++)
      #pragma unroll
      for (int j=0;j<4;j++)
        #pragma unroll
        for (int k=0;k<4;k++) acc[i][j][k]=0.f;

    const int s1 = K1 >> 4;
    const int s2 = (A2 != nullptr) ? (K2 >> 4) : 0;
    const int S  = s1 + s2;

    float4 av0, av1, bv0, bv1;

#define GEMM_LOAD(s) do { \
        const float* A_; const float* W_; int lda_, ldw_, k0_; \
        if ((s) < s1){ A_ = A1; W_ = W1; lda_ = lda1; ldw_ = ldw1; k0_ = (s) << 4; } \
        else         { A_ = A2; W_ = W2; lda_ = lda2; ldw_ = ldw2; k0_ = ((s) - s1) << 4; } \
        av0 = *(const float4*)(A_ + (size_t)(m0+lrow)*lda_    + k0_ + lk4); \
        av1 = *(const float4*)(A_ + (size_t)(m0+lrow+64)*lda_ + k0_ + lk4); \
        bv0 = *(const float4*)(W_ + (size_t)(n0+lrow)*ldw_    + k0_ + lk4); \
        bv1 = *(const float4*)(W_ + (size_t)(n0+lrow+64)*ldw_ + k0_ + lk4); \
    } while(0)

    GEMM_LOAD(0);

    for (int s = 0; s < S; ++s){
        __syncthreads();
        As[lrow   ][lk4  ] = tf32r(av0.x); As[lrow   ][lk4+1] = tf32r(av0.y);
        As[lrow   ][lk4+2] = tf32r(av0.z); As[lrow   ][lk4+3] = tf32r(av0.w);
        As[lrow+64][lk4  ] = tf32r(av1.x); As[lrow+64][lk4+1] = tf32r(av1.y);
        As[lrow+64][lk4+2] = tf32r(av1.z); As[lrow+64][lk4+3] = tf32r(av1.w);
        Bs[lrow   ][lk4  ] = tf32r(bv0.x); Bs[lrow   ][lk4+1] = tf32r(bv0.y);
        Bs[lrow   ][lk4+2] = tf32r(bv0.z); Bs[lrow   ][lk4+3] = tf32r(bv0.w);
        Bs[lrow+64][lk4  ] = tf32r(bv1.x); Bs[lrow+64][lk4+1] = tf32r(bv1.y);
        Bs[lrow+64][lk4+2] = tf32r(bv1.z); Bs[lrow+64][lk4+3] = tf32r(bv1.w);
        __syncthreads();

        if (s + 1 < S) GEMM_LOAD(s + 1);

        #pragma unroll
        for (int ss = 0; ss < 2; ++ss){
            const int kb = ss*8 + tig;
            uint32_t afr[4][4], bfr[4][2];
            #pragma unroll
            for (int mi=0; mi<4; ++mi){
                int rowb = wm + mi*16 + gid;
                afr[mi][0] = __float_as_uint(As[rowb  ][kb]);
                afr[mi][1] = __float_as_uint(As[rowb+8][kb]);
                afr[mi][2] = __float_as_uint(As[rowb  ][kb+4]);
                afr[mi][3] = __float_as_uint(As[rowb+8][kb+4]);
            }
            #pragma unroll
            for (int ni=0; ni<4; ++ni){
                int colb = wn + ni*8 + gid;
                bfr[ni][0] = __float_as_uint(Bs[colb][kb]);
                bfr[ni][1] = __float_as_uint(Bs[colb][kb+4]);
            }
            #pragma unroll
            for (int mi=0; mi<4; ++mi)
                #pragma unroll
                for (int ni=0; ni<4; ++ni)
                    mma_tf32(acc[mi][ni], afr[mi], bfr[ni]);
        }
    }
#undef GEMM_LOAD

    #pragma unroll
    for (int mi=0; mi<4; ++mi){
        int m = m0 + wm + mi*16 + gid;
        int tc0 = 0, tc1 = 0;
        if (Wg){ tc0 = textcol[m*textstride]; tc1 = textcol[(m+8)*textstride]; }
        #pragma unroll
        for (int ni=0; ni<4; ++ni){
            int n = n0 + wn + ni*8 + tig*2;
            float b0 = 0.f, b1 = 0.f;
            if (bias1){ b0 += bias1[n]; b1 += bias1[n+1]; }
            if (bias2){ b0 += bias2[n]; b1 += bias2[n+1]; }
            float v00 = acc[mi][ni][0] + b0;
            float v01 = acc[mi][ni][1] + b1;
            float v10 = acc[mi][ni][2] + b0;
            float v11 = acc[mi][ni][3] + b1;
            if (Cadd){
                v00 += Cadd[(size_t)m*ldadd + n];     v01 += Cadd[(size_t)m*ldadd + n+1];
                v10 += Cadd[(size_t)(m+8)*ldadd + n]; v11 += Cadd[(size_t)(m+8)*ldadd + n+1];
            }
            if (Wg){
                v00 += Wg[(size_t)n*ldwg + gcolbase + tc0];
                v01 += Wg[(size_t)(n+1)*ldwg + gcolbase + tc0];
                v10 += Wg[(size_t)n*ldwg + gcolbase + tc1];
                v11 += Wg[(size_t)(n+1)*ldwg + gcolbase + tc1];
            }
            C[(size_t)m*ldc + n]       = v00;
            C[(size_t)m*ldc + n+1]     = v01;
            C[(size_t)(m+8)*ldc + n]   = v10;
            C[(size_t)(m+8)*ldc + n+1] = v11;
        }
    }
}

// ---------------- fp32 fused GEMM (prologue + generator) --------------------
__global__ void gemm_kernel(
    float* __restrict__ C, int ldc,
    const float* __restrict__ A1, int lda1, const float* __restrict__ W1, int ldw1, int K1,
    const float* __restrict__ bias1,
    const float* __restrict__ Cadd, int ldadd,
    int nn, int remap, int M, int N)
{
    __shared__ float As[16][68];
    __shared__ float Bs[16][68];
    int m0 = blockIdx.y * 64;
    int n0 = blockIdx.x * 64;
    int tid = threadIdx.x;
    int tx = tid & 15, ty = tid >> 4;

    float acc[4][4];
    #pragma unroll
    for (int i=0;i<4;i++)
        #pragma unroll
        for (int j=0;j<4;j++) acc[i][j]=0.f;

    for (int k0=0; k0<K1; k0+=16){
        #pragma unroll
        for (int i=0;i<4;i++){
            int e = i*256 + tid;
            int m = e >> 4, kk = e & 15;
            int gm = m0 + m, gk = k0 + kk;
            As[kk][m] = (gm < M && gk < K1) ? A1[(size_t)gm*lda1 + gk] : 0.f;
        }
        if (nn){
            #pragma unroll
            for (int i=0;i<4;i++){
                int e = i*256 + tid;
                int kk = e >> 6, n = e & 63;
                int gn = n0 + n, gk = k0 + kk;
                Bs[kk][n] = (gn < N && gk < K1) ? W1[(size_t)gk*ldw1 + gn] : 0.f;
            }
        } else {
            #pragma unroll
            for (int i=0;i<4;i++){
                int e = i*256 + tid;
                int n = e >> 4, kk = e & 15;
                int gn = n0 + n, gk = k0 + kk;
                Bs[kk][n] = (gn < N && gk < K1) ? W1[(size_t)gn*ldw1 + gk] : 0.f;
            }
        }
        __syncthreads();
        #pragma unroll
        for (int kk=0; kk<16; kk++){
            float4 a = *(const float4*)&As[kk][ty*4];
            float4 b = *(const float4*)&Bs[kk][tx*4];
            acc[0][0]+=a.x*b.x; acc[0][1]+=a.x*b.y; acc[0][2]+=a.x*b.z; acc[0][3]+=a.x*b.w;
            acc[1][0]+=a.y*b.x; acc[1][1]+=a.y*b.y; acc[1][2]+=a.y*b.z; acc[1][3]+=a.y*b.w;
            acc[2][0]+=a.z*b.x; acc[2][1]+=a.z*b.y; acc[2][2]+=a.z*b.z; acc[2][3]+=a.z*b.w;
            acc[3][0]+=a.w*b.x; acc[3][1]+=a.w*b.y; acc[3][2]+=a.w*b.z; acc[3][3]+=a.w*b.w;
        }
        __syncthreads();
    }

    #pragma unroll
    for (int i=0;i<4;i++){
        int m = m0 + ty*4 + i;
        if (m >= M) continue;
        #pragma unroll
        for (int j=0;j<4;j++){
            int n = n0 + tx*4 + j;
            if (n >= N) continue;
            float v = acc[i][j];
            if (bias1) v += bias1[n];
            if (Cadd)  v += Cadd[(size_t)m*ldadd + n];
            if (remap){
                int t = m >> 8, b = m & 255;
                C[(size_t)(b*TT + t)*NC + n] = v;
            } else {
                C[(size_t)m*ldc + n] = v;
            }
        }
    }
}

// ---------------- mean over T of batch_H ------------------------------------
__global__ void mean_kernel(const float* __restrict__ bH, float* __restrict__ out)
{
    int idx = blockIdx.x*256 + threadIdx.x;
    if (idx >= BB*INSZ) return;
    int b = idx >> 9, k = idx & 511;
    const float* p = bH + (size_t)b*TT*INSZ + k;
    float s = 0.f;
    #pragma unroll
    for (int t=0;t<TT;t++) s += p[t*INSZ];
    out[idx] = s * (1.0f/26.0f);
}

// ---------------- init h0/c0 -------------------------------------------------
__global__ void init_kernel(const float* __restrict__ hh, const float* __restrict__ hc,
                            float* __restrict__ h1, float* __restrict__ h2,
                            float* __restrict__ c1, float* __restrict__ c2)
{
    int idx = blockIdx.x*256 + threadIdx.x;
    if (idx >= BB*HS) return;
    float h0 = 0.5f*(hh[idx] + hh[BB*HS + idx]);
    float c0 = 0.5f*(hc[idx] + hc[BB*HS + idx]);
    h1[idx]=h0; h2[idx]=h0; c1[idx]=c0; c2[idx]=c0;
}

// ---------------- attention: e -> softmax -> context ------------------------
__global__ void attn_kernel(const float* __restrict__ fmh, const float* __restrict__ q,
                            const float* __restrict__ ws, const float* __restrict__ sb,
                            float* __restrict__ ctx)
{
    __shared__ float qs[CH];
    __shared__ float wss[CH];
    __shared__ float red[256];
    __shared__ float alpha[256];

    int b = blockIdx.x;
    int p = threadIdx.x;
    const float* f = fmh + (size_t)b * CH * PP;

    qs[p]       = q[b*HS + p];
    qs[p+256]   = q[b*HS + p + 256];
    wss[p]      = ws[p];
    wss[p+256]  = ws[p+256];
    __syncthreads();

    float acc = 0.f;
    #pragma unroll 4
    for (int c=0; c<CH; c++){
        acc += ftanh(f[c*PP + p] + qs[c]) * wss[c];
    }
    float e = acc + sb[0];

    red[p] = e; __syncthreads();
    #pragma unroll
    for (int s=128; s>0; s>>=1){
        if (p < s) red[p] = fmaxf(red[p], red[p+s]);
        __syncthreads();
    }
    float mx = red[0];
    __syncthreads();
    float ex = fexp(e - mx);
    red[p] = ex; __syncthreads();
    #pragma unroll
    for (int s=128; s>0; s>>=1){
        if (p < s) red[p] += red[p+s];
        __syncthreads();
    }
    float sum = red[0];
    __syncthreads();
    alpha[p] = ex * frcp(sum);
    __syncthreads();

    int lane = p & 31, wid = p >> 5;
    for (int c = wid; c < CH; c += 8){
        const float* fr = f + c*PP;
        float s = 0.f;
        #pragma unroll
        for (int pp = lane; pp < PP; pp += 32) s += alpha[pp] * fr[pp];
        #pragma unroll
        for (int o=16; o>0; o>>=1) s += __shfl_down_sync(0xffffffffu, s, o);
        if (lane == 0) ctx[b*HS + c] = s;
    }
}

// ---------------- LSTM pointwise --------------------------------------------
__global__ void lstm_kernel(const float* __restrict__ g, const float* __restrict__ cin,
                            float* __restrict__ hout, float* __restrict__ cout)
{
    int idx = blockIdx.x*256 + threadIdx.x;
    if (idx >= BB*HS) return;
    int b = idx >> 9, j = idx & 511;
    const float* gb = g + (size_t)b*4*HS;
    float i_ = gb[j], f_ = gb[HS + j], gg = gb[2*HS + j], o_ = gb[3*HS + j];
    float c2 = fsigm(f_)*cin[idx] + fsigm(i_)*ftanh(gg);
    cout[idx] = c2;
    hout[idx] = fsigm(o_)*ftanh(c2);
}

// ---------------- host orchestration ----------------------------------------
extern "C" void kernel_launch(void* const* d_in, const int* in_sizes, int n_in,
                              void* d_out, int out_size)
{
    const float* feature_map = (const float*)d_in[0];
    const float* batch_H     = (const float*)d_in[1];
    const float* hidden_h    = (const float*)d_in[2];
    const float* hidden_c    = (const float*)d_in[3];
    const int*   text        = (const int*)  d_in[4];
    const float* i2h_w       = (const float*)d_in[5];
    const float* h2h_w       = (const float*)d_in[6];
    const float* h2h_b       = (const float*)d_in[7];
    const float* conv_m2h_w  = (const float*)d_in[8];
    const float* conv_m2h_b  = (const float*)d_in[9];
    const float* conv_h2h_w  = (const float*)d_in[10];
    const float* conv_h2h_b  = (const float*)d_in[11];
    const float* score_w     = (const float*)d_in[12];
    const float* score_b     = (const float*)d_in[13];
    const float* rnn1_w_ih   = (const float*)d_in[14];
    const float* rnn1_w_hh   = (const float*)d_in[15];
    const float* rnn1_b_ih   = (const float*)d_in[16];
    const float* rnn1_b_hh   = (const float*)d_in[17];
    const float* hlin_w      = (const float*)d_in[18];
    const float* hlin_b      = (const float*)d_in[19];
    const float* rnn2_w_ih   = (const float*)d_in[20];
    const float* rnn2_w_hh   = (const float*)d_in[21];
    const float* rnn2_b_ih   = (const float*)d_in[22];
    const float* rnn2_b_hh   = (const float*)d_in[23];
    const float* gen_w       = (const float*)d_in[24];
    const float* gen_b       = (const float*)d_in[25];
    float* out = (float*)d_out;

    float *inpad3,*w2t,*fmh,*meanH,*bhproj,*Wq,*qb,*w1ih;
    float *h1a,*c1a,*h2a,*c2a,*h1b,*c1b,*c2b,*hist,*q,*ctx,*gates,*cur;
    cudaGetSymbolAddress((void**)&inpad3,g_inpad3);
    cudaGetSymbolAddress((void**)&w2t,   g_w2t);
    cudaGetSymbolAddress((void**)&fmh,   g_fmh);
    cudaGetSymbolAddress((void**)&meanH, g_meanH);
    cudaGetSymbolAddress((void**)&bhproj,g_bhproj);
    cudaGetSymbolAddress((void**)&Wq,    g_Wq);
    cudaGetSymbolAddress((void**)&qb,    g_qb);
    cudaGetSymbolAddress((void**)&w1ih,  g_w1ih);
    cudaGetSymbolAddress((void**)&h1a, g_h1a); cudaGetSymbolAddress((void**)&c1a, g_c1a);
    cudaGetSymbolAddress((void**)&h2a, g_h2a); cudaGetSymbolAddress((void**)&c2a, g_c2a);
    cudaGetSymbolAddress((void**)&h1b, g_h1b); cudaGetSymbolAddress((void**)&c1b, g_c1b);
    cudaGetSymbolAddress((void**)&c2b, g_c2b); cudaGetSymbolAddress((void**)&hist, g_h2hist);
    cudaGetSymbolAddress((void**)&q,   g_q);   cudaGetSymbolAddress((void**)&ctx, g_ctx);
    cudaGetSymbolAddress((void**)&gates, g_gates); cudaGetSymbolAddress((void**)&cur, g_cur);

    // conv prep + pipelined tensor-core conv
    {
        size_t tot = (size_t)3*BB*CH*10*32;
        pad3_kernel<<<(unsigned)((tot+255)/256),256>>>(feature_map, inpad3);
        w2t_kernel<<<(9*CH*CH+255)/256,256>>>(conv_m2h_w, w2t);
        w1ih_kernel<<<(4*HS*INSZ+255)/256,256>>>(rnn1_w_ih, w1ih);
        conv_mma_kernel<<<dim3(4,2,BB),256>>>(inpad3, w2t, conv_m2h_b, fmh);
    }

    // prologue (fp32)
    mean_kernel<<<512,256>>>(batch_H, meanH);
    gemm_kernel<<<dim3(8,4),256>>>(bhproj, HS, meanH, INSZ, i2h_w, INSZ, INSZ,
                                   h2h_b, nullptr,0, 0,0, BB, HS);
    gemm_kernel<<<dim3(8,8),256>>>(Wq, HS, conv_h2h_w, HS, h2h_w, HS, HS,
                                   nullptr, nullptr,0, 1,0, HS, HS);
    gemm_kernel<<<dim3(8,4),256>>>(qb, HS, bhproj, HS, conv_h2h_w, HS, HS,
                                   conv_h2h_b, nullptr,0, 0,0, BB, HS);
    init_kernel<<<512,256>>>(hidden_h, hidden_c, h1a, h2a, c1a, c2a);

    float *h1c=h1a,*c1c=c1a,*h2c=h2a,*c2c=c2a;
    float *h1n=h1b,*c1n=c1b,*c2n=c2b;

    for (int t=0; t<TT; t++){
        float* h2n = hist + (size_t)t*BB*HS;
        // q = qb + h2 @ Wq^T
        gemm_tf32_kernel<<<dim3(4,2),256>>>(q, HS,
            h2c, HS, Wq, HS, HS, nullptr,0,nullptr,0,0,
            nullptr,nullptr, qb, HS, nullptr,0,0, nullptr,0);
        // attention -> ctx
        attn_kernel<<<BB,256>>>(fmh, q, score_w, score_b, ctx);
        // gates1
        gemm_tf32_kernel<<<dim3(16,2),256>>>(gates, 4*HS,
            ctx, HS, w1ih, INSZ, HS,
            h1c, HS, rnn1_w_hh, HS, HS,
            rnn1_b_ih, rnn1_b_hh, nullptr,0,
            rnn1_w_ih, INSZ+NC, INSZ, text + t, TT);
        lstm_kernel<<<512,256>>>(gates, c1c, h1n, c1n);
        // cur = h1n @ hlin_w^T + hlin_b
        gemm_tf32_kernel<<<dim3(4,2),256>>>(cur, HS,
            h1n, HS, hlin_w, HS, HS, nullptr,0,nullptr,0,0,
            hlin_b, nullptr, nullptr,0, nullptr,0,0, nullptr,0);
        // gates2
        gemm_tf32_kernel<<<dim3(16,2),256>>>(gates, 4*HS,
            cur, HS, rnn2_w_ih, HS, HS,
            h2c, HS, rnn2_w_hh, HS, HS,
            rnn2_b_ih, rnn2_b_hh, nullptr,0,
            nullptr,0,0, nullptr,0);
        lstm_kernel<<<512,256>>>(gates, c2c, h2n, c2n);

        float* tp;
        tp=h1c; h1c=h1n; h1n=tp;  tp=c1c; c1c=c1n; c1n=tp;
        h2c = h2n;
        tp=c2c; c2c=c2n; c2n=tp;
    }

    // probs: one batched GEMM over all timesteps, output remapped to [b][t][n]
    gemm_kernel<<<dim3(1,104),256>>>(out, NC,
        hist, HS, gen_w, HS, HS,
        gen_b, nullptr,0, 0,1, TT*BB, NC);
}

// round 7
// speedup vs baseline: 2.2590x; 1.3499x over previous
#include <cuda_runtime.h>
#include <cuda_fp16.h>
#include <math.h>
#include <stdint.h>

#define BB 256
#define HS 512
#define INSZ 512
#define NC 38
#define TT 26
#define CH 512
#define PP 256   /* 8*32 */

// ---------------- scratch (device globals; no allocation allowed) ----------
__device__ __align__(16) __half g_ahT[(size_t)3*BB*320*CH]; // padded input, [kw][b][pos320][ic], fp16
__device__ __align__(16) __half g_bhT[9*CH*CH];             // weights [khw][oc][ic], fp16
__device__ __align__(16) __half g_fmh[(size_t)BB*CH*PP];    // conv output, fp16, 67MB (L2-resident)
__device__ float g_meanH[BB*INSZ];
__device__ float g_bhproj[BB*HS];
__device__ float g_Wq[HS*HS];                      // conv1x1 @ h2h_w
__device__ float g_qb[BB*HS];
__device__ float g_w1ih[4*HS*INSZ];                // rnn1_w_ih[:, :512] repacked ld=512
__device__ float g_h1a[BB*HS], g_c1a[BB*HS], g_h2a[BB*HS], g_c2a[BB*HS];
__device__ float g_h1b[BB*HS], g_c1b[BB*HS], g_c2b[BB*HS];
__device__ float g_h2hist[(size_t)TT*BB*HS];       // h2 per step (13.6MB)
__device__ float g_q[BB*HS];
__device__ float g_ctx[BB*HS];
__device__ float g_gates[BB*4*HS];
__device__ float g_cur[BB*HS];

// ---------------- fast math ------------------------------------------------
__device__ __forceinline__ float fexp(float x){
    float y; asm("ex2.approx.f32 %0, %1;" : "=f"(y) : "f"(x*1.4426950408889634f)); return y;
}
__device__ __forceinline__ float frcp(float x){
    float y; asm("rcp.approx.f32 %0, %1;" : "=f"(y) : "f"(x)); return y;
}
__device__ __forceinline__ float ftanh(float x){
    float xc = fminf(fmaxf(x, -15.f), 15.f);
    float t = fexp(2.f*xc);
    return (t - 1.f) * frcp(t + 1.f);
}
__device__ __forceinline__ float fsigm(float x){
    return frcp(1.f + fexp(-x));
}
__device__ __forceinline__ float tf32r(float x){
    uint32_t u; asm("cvt.rna.tf32.f32 %0, %1;" : "=r"(u) : "f"(x)); return __uint_as_float(u);
}
__device__ __forceinline__ void mma_tf32(float* d, const uint32_t* a, const uint32_t* b){
    asm volatile(
      "mma.sync.aligned.m16n8k8.row.col.f32.tf32.tf32.f32 "
      "{%0,%1,%2,%3},{%4,%5,%6,%7},{%8,%9},{%0,%1,%2,%3};"
      : "+f"(d[0]),"+f"(d[1]),"+f"(d[2]),"+f"(d[3])
      : "r"(a[0]),"r"(a[1]),"r"(a[2]),"r"(a[3]), "r"(b[0]),"r"(b[1]));
}
__device__ __forceinline__ void mma_fp16(float* d, const uint32_t* a, const uint32_t* b){
    asm volatile(
      "mma.sync.aligned.m16n8k16.row.col.f32.f16.f16.f32 "
      "{%0,%1,%2,%3},{%4,%5,%6,%7},{%8,%9},{%0,%1,%2,%3};"
      : "+f"(d[0]),"+f"(d[1]),"+f"(d[2]),"+f"(d[3])
      : "r"(a[0]),"r"(a[1]),"r"(a[2]),"r"(a[3]), "r"(b[0]),"r"(b[1]));
}

// ---------------- prep kernels ------------------------------------------------
// out[kw][b][rr*32+c][ic] = fp16(in[b][ic][(rr-1)*32 + c + kw - 1]) or 0
__global__ void padT_kernel(const float* __restrict__ in, __half* __restrict__ oh)
{
    __shared__ float s[32][33];
    int blk = blockIdx.x;            // 256b * 10rr * 16icb
    int icb = blk & 15;
    int rr  = (blk >> 4) % 10;
    int b   = blk >> 4; b /= 10;
    int t = threadIdx.x;
    int r = rr - 1;

    if ((unsigned)r < 8u){
        int c = t & 31, icq = t >> 5;
        #pragma unroll
        for (int j=0;j<4;j++){
            int ic = icq + j*8;
            s[ic][c] = in[((size_t)b*CH + icb*32 + ic)*PP + r*32 + c];
        }
    }
    __syncthreads();

    int icl = t & 31, cq = t >> 5;
    #pragma unroll
    for (int j=0;j<4;j++){
        int c = cq + j*8;
        #pragma unroll
        for (int kw=0; kw<3; kw++){
            int cc = c + kw - 1;
            float v = 0.f;
            if ((unsigned)r < 8u && (unsigned)cc < 32u) v = s[icl][cc];
            size_t off = (((size_t)kw*BB + b)*320 + rr*32 + c)*CH + icb*32 + icl;
            oh[off] = __float2half(v);
        }
    }
}

// weights: out[khw][oc][ic] fp16 from w[oc][ic][khw]
__global__ void wT_kernel(const float* __restrict__ w, __half* __restrict__ oh)
{
    int idx = blockIdx.x*256 + threadIdx.x;
    if (idx >= 9*CH*CH) return;
    int ic = idx & 511;
    int oc = (idx >> 9) & 511;
    int khw = idx >> 18;
    oh[((size_t)khw*CH + oc)*CH + ic] = __float2half(w[((size_t)oc*CH + ic)*9 + khw]);
}

// repack rnn1_w_ih[:, :INSZ] from ld=550 to ld=512
__global__ void w1ih_kernel(const float* __restrict__ w, float* __restrict__ out)
{
    int idx = blockIdx.x*256 + threadIdx.x;
    if (idx >= 4*HS*INSZ) return;
    int k = idx & 511;
    int n = idx >> 9;
    out[idx] = w[(size_t)n*(INSZ+NC) + k];
}

// ---------------- conv 3x3 SAME via fp16 mma m16n8k16, cp.async pipelined ----
// block tile 128(pos) x 128(oc), 8 warps (2m x 4n), 288 K-slabs of 16
__global__ void __launch_bounds__(256, 2) conv_fp16_kernel(
    const __half* __restrict__ Ag, const __half* __restrict__ Bg,
    const float* __restrict__ bias, __half* __restrict__ out)
{
    __shared__ __align__(16) uint32_t As[2][128][12];  // [buf][row(pos)][k-words(8)+pad]
    __shared__ __align__(16) uint32_t Bs[2][128][12];  // [buf][row(oc) ][k-words(8)+pad]
    const int b  = blockIdx.z;
    const int m0 = blockIdx.y * 128;
    const int n0 = blockIdx.x * 128;
    const int tid = threadIdx.x;
    const int lane = tid & 31, warp = tid >> 5;
    const int wm = (warp >> 2) * 64;
    const int wn = (warp & 3) * 32;
    const int gid = lane >> 2, tig = lane & 3;

    const int lrow = tid >> 1;     // 0..127
    const int lch  = tid & 1;      // 0..1 (16B chunk within 32B k-row)

    float acc[4][4][4];
    #pragma unroll
    for (int i=0;i<4;i++)
      #pragma unroll
      for (int j=0;j<4;j++)
        #pragma unroll
        for (int k=0;k<4;k++) acc[i][j][k]=0.f;

    uint32_t sA = (uint32_t)__cvta_generic_to_shared(&As[0][0][0]);
    uint32_t sB = (uint32_t)__cvta_generic_to_shared(&Bs[0][0][0]);

#define CLOAD(s) do { \
        int buf_ = (s) & 1; \
        int khw_ = (s) >> 5; \
        int icc_ = (s) & 31; \
        int kh_ = khw_ / 3, kw_ = khw_ - kh_*3; \
        int ic0_ = icc_ << 4; \
        const __half* ap_ = Ag + (((size_t)kw_*BB + b)*320 + m0 + kh_*32 + lrow)*CH + ic0_ + lch*8; \
        const __half* bp_ = Bg + ((size_t)khw_*CH + n0 + lrow)*CH + ic0_ + lch*8; \
        uint32_t da_ = sA + (uint32_t)(((buf_*128 + lrow)*12 + lch*4)*4); \
        uint32_t db_ = sB + (uint32_t)(((buf_*128 + lrow)*12 + lch*4)*4); \
        asm volatile("cp.async.ca.shared.global [%0], [%1], 16;" :: "r"(da_), "l"(ap_)); \
        asm volatile("cp.async.ca.shared.global [%0], [%1], 16;" :: "r"(db_), "l"(bp_)); \
        asm volatile("cp.async.commit_group;"); \
    } while(0)

    CLOAD(0);

    for (int s = 0; s < 288; ++s){
        if (s < 287){
            CLOAD(s + 1);
            asm volatile("cp.async.wait_group 1;");
        } else {
            asm volatile("cp.async.wait_group 0;");
        }
        __syncthreads();
        const int buf = s & 1;

        uint32_t afr[4][4], bfr[4][2];
        #pragma unroll
        for (int mi=0; mi<4; ++mi){
            int rowb = wm + mi*16 + gid;
            afr[mi][0] = As[buf][rowb  ][tig];
            afr[mi][1] = As[buf][rowb+8][tig];
            afr[mi][2] = As[buf][rowb  ][tig+4];
            afr[mi][3] = As[buf][rowb+8][tig+4];
        }
        #pragma unroll
        for (int ni=0; ni<4; ++ni){
            int colb = wn + ni*8 + gid;
            bfr[ni][0] = Bs[buf][colb][tig];
            bfr[ni][1] = Bs[buf][colb][tig+4];
        }
        #pragma unroll
        for (int mi=0; mi<4; ++mi)
            #pragma unroll
            for (int ni=0; ni<4; ++ni)
                mma_fp16(acc[mi][ni], afr[mi], bfr[ni]);
        __syncthreads();
    }
#undef CLOAD

    #pragma unroll
    for (int mi=0; mi<4; ++mi){
        int prow = m0 + wm + mi*16 + gid;
        #pragma unroll
        for (int ni=0; ni<4; ++ni){
            int oc = n0 + wn + ni*8 + tig*2;
            float bz0 = bias[oc], bz1 = bias[oc+1];
            __half* o0 = out + ((size_t)b*CH + oc)*PP;
            o0[prow]          = __float2half(acc[mi][ni][0] + bz0);
            o0[PP + prow]     = __float2half(acc[mi][ni][1] + bz1);
            o0[prow + 8]      = __float2half(acc[mi][ni][2] + bz0);
            o0[PP + prow + 8] = __float2half(acc[mi][ni][3] + bz1);
        }
    }
}

// ---------------- tf32 mma GEMM, software-pipelined --------------------------
// NOTE: all lda/ldw MUST be multiples of 4 (float4 loads).
__global__ void __launch_bounds__(256, 1) gemm_tf32_kernel(
    float* __restrict__ C, int ldc,
    const float* __restrict__ A1, int lda1, const float* __restrict__ W1, int ldw1, int K1,
    const float* __restrict__ A2, int lda2, const float* __restrict__ W2, int ldw2, int K2,
    const float* __restrict__ bias1, const float* __restrict__ bias2,
    const float* __restrict__ Cadd, int ldadd,
    const float* __restrict__ Wg, int ldwg, int gcolbase,
    const int* __restrict__ textcol, int textstride)
{
    __shared__ float As[128][20];
    __shared__ float Bs[128][20];
    const int m0 = blockIdx.y * 128;
    const int n0 = blockIdx.x * 128;
    const int tid = threadIdx.x;
    const int lane = tid & 31, warp = tid >> 5;
    const int wm = (warp >> 2) * 64;
    const int wn = (warp & 3) * 32;
    const int gid = lane >> 2, tig = lane & 3;

    const int lrow = tid >> 2;          // 0..63
    const int lk4  = (tid & 3) * 4;     // 0,4,8,12

    float acc[4][4][4];
    #pragma unroll
    for (int i=0;i<4;i++)
      #pragma unroll
      for (int j=0;j<4;j++)
        #pragma unroll
        for (int k=0;k<4;k++) acc[i][j][k]=0.f;

    const int s1 = K1 >> 4;
    const int s2 = (A2 != nullptr) ? (K2 >> 4) : 0;
    const int S  = s1 + s2;

    float4 av0, av1, bv0, bv1;

#define GEMM_LOAD(s) do { \
        const float* A_; const float* W_; int lda_, ldw_, k0_; \
        if ((s) < s1){ A_ = A1; W_ = W1; lda_ = lda1; ldw_ = ldw1; k0_ = (s) << 4; } \
        else         { A_ = A2; W_ = W2; lda_ = lda2; ldw_ = ldw2; k0_ = ((s) - s1) << 4; } \
        av0 = *(const float4*)(A_ + (size_t)(m0+lrow)*lda_    + k0_ + lk4); \
        av1 = *(const float4*)(A_ + (size_t)(m0+lrow+64)*lda_ + k0_ + lk4); \
        bv0 = *(const float4*)(W_ + (size_t)(n0+lrow)*ldw_    + k0_ + lk4); \
        bv1 = *(const float4*)(W_ + (size_t)(n0+lrow+64)*ldw_ + k0_ + lk4); \
    } while(0)

    GEMM_LOAD(0);

    for (int s = 0; s < S; ++s){
        __syncthreads();
        As[lrow   ][lk4  ] = tf32r(av0.x); As[lrow   ][lk4+1] = tf32r(av0.y);
        As[lrow   ][lk4+2] = tf32r(av0.z); As[lrow   ][lk4+3] = tf32r(av0.w);
        As[lrow+64][lk4  ] = tf32r(av1.x); As[lrow+64][lk4+1] = tf32r(av1.y);
        As[lrow+64][lk4+2] = tf32r(av1.z); As[lrow+64][lk4+3] = tf32r(av1.w);
        Bs[lrow   ][lk4  ] = tf32r(bv0.x); Bs[lrow   ][lk4+1] = tf32r(bv0.y);
        Bs[lrow   ][lk4+2] = tf32r(bv0.z); Bs[lrow   ][lk4+3] = tf32r(bv0.w);
        Bs[lrow+64][lk4  ] = tf32r(bv1.x); Bs[lrow+64][lk4+1] = tf32r(bv1.y);
        Bs[lrow+64][lk4+2] = tf32r(bv1.z); Bs[lrow+64][lk4+3] = tf32r(bv1.w);
        __syncthreads();

        if (s + 1 < S) GEMM_LOAD(s + 1);

        #pragma unroll
        for (int ss = 0; ss < 2; ++ss){
            const int kb = ss*8 + tig;
            uint32_t afr[4][4], bfr[4][2];
            #pragma unroll
            for (int mi=0; mi<4; ++mi){
                int rowb = wm + mi*16 + gid;
                afr[mi][0] = __float_as_uint(As[rowb  ][kb]);
                afr[mi][1] = __float_as_uint(As[rowb+8][kb]);
                afr[mi][2] = __float_as_uint(As[rowb  ][kb+4]);
                afr[mi][3] = __float_as_uint(As[rowb+8][kb+4]);
            }
            #pragma unroll
            for (int ni=0; ni<4; ++ni){
                int colb = wn + ni*8 + gid;
                bfr[ni][0] = __float_as_uint(Bs[colb][kb]);
                bfr[ni][1] = __float_as_uint(Bs[colb][kb+4]);
            }
            #pragma unroll
            for (int mi=0; mi<4; ++mi)
                #pragma unroll
                for (int ni=0; ni<4; ++ni)
                    mma_tf32(acc[mi][ni], afr[mi], bfr[ni]);
        }
    }
#undef GEMM_LOAD

    #pragma unroll
    for (int mi=0; mi<4; ++mi){
        int m = m0 + wm + mi*16 + gid;
        int tc0 = 0, tc1 = 0;
        if (Wg){ tc0 = textcol[m*textstride]; tc1 = textcol[(m+8)*textstride]; }
        #pragma unroll
        for (int ni=0; ni<4; ++ni){
            int n = n0 + wn + ni*8 + tig*2;
            float b0 = 0.f, b1 = 0.f;
            if (bias1){ b0 += bias1[n]; b1 += bias1[n+1]; }
            if (bias2){ b0 += bias2[n]; b1 += bias2[n+1]; }
            float v00 = acc[mi][ni][0] + b0;
            float v01 = acc[mi][ni][1] + b1;
            float v10 = acc[mi][ni][2] + b0;
            float v11 = acc[mi][ni][3] + b1;
            if (Cadd){
                v00 += Cadd[(size_t)m*ldadd + n];     v01 += Cadd[(size_t)m*ldadd + n+1];
                v10 += Cadd[(size_t)(m+8)*ldadd + n]; v11 += Cadd[(size_t)(m+8)*ldadd + n+1];
            }
            if (Wg){
                v00 += Wg[(size_t)n*ldwg + gcolbase + tc0];
                v01 += Wg[(size_t)(n+1)*ldwg + gcolbase + tc0];
                v10 += Wg[(size_t)n*ldwg + gcolbase + tc1];
                v11 += Wg[(size_t)(n+1)*ldwg + gcolbase + tc1];
            }
            C[(size_t)m*ldc + n]       = v00;
            C[(size_t)m*ldc + n+1]     = v01;
            C[(size_t)(m+8)*ldc + n]   = v10;
            C[(size_t)(m+8)*ldc + n+1] = v11;
        }
    }
}

// ---------------- fp32 fused GEMM (prologue + generator) --------------------
__global__ void gemm_kernel(
    float* __restrict__ C, int ldc,
    const float* __restrict__ A1, int lda1, const float* __restrict__ W1, int ldw1, int K1,
    const float* __restrict__ bias1,
    const float* __restrict__ Cadd, int ldadd,
    int nn, int remap, int M, int N)
{
    __shared__ float As[16][68];
    __shared__ float Bs[16][68];
    int m0 = blockIdx.y * 64;
    int n0 = blockIdx.x * 64;
    int tid = threadIdx.x;
    int tx = tid & 15, ty = tid >> 4;

    float acc[4][4];
    #pragma unroll
    for (int i=0;i<4;i++)
        #pragma unroll
        for (int j=0;j<4;j++) acc[i][j]=0.f;

    for (int k0=0; k0<K1; k0+=16){
        #pragma unroll
        for (int i=0;i<4;i++){
            int e = i*256 + tid;
            int m = e >> 4, kk = e & 15;
            int gm = m0 + m, gk = k0 + kk;
            As[kk][m] = (gm < M && gk < K1) ? A1[(size_t)gm*lda1 + gk] : 0.f;
        }
        if (nn){
            #pragma unroll
            for (int i=0;i<4;i++){
                int e = i*256 + tid;
                int kk = e >> 6, n = e & 63;
                int gn = n0 + n, gk = k0 + kk;
                Bs[kk][n] = (gn < N && gk < K1) ? W1[(size_t)gk*ldw1 + gn] : 0.f;
            }
        } else {
            #pragma unroll
            for (int i=0;i<4;i++){
                int e = i*256 + tid;
                int n = e >> 4, kk = e & 15;
                int gn = n0 + n, gk = k0 + kk;
                Bs[kk][n] = (gn < N && gk < K1) ? W1[(size_t)gn*ldw1 + gk] : 0.f;
            }
        }
        __syncthreads();
        #pragma unroll
        for (int kk=0; kk<16; kk++){
            float4 a = *(const float4*)&As[kk][ty*4];
            float4 b = *(const float4*)&Bs[kk][tx*4];
            acc[0][0]+=a.x*b.x; acc[0][1]+=a.x*b.y; acc[0][2]+=a.x*b.z; acc[0][3]+=a.x*b.w;
            acc[1][0]+=a.y*b.x; acc[1][1]+=a.y*b.y; acc[1][2]+=a.y*b.z; acc[1][3]+=a.y*b.w;
            acc[2][0]+=a.z*b.x; acc[2][1]+=a.z*b.y; acc[2][2]+=a.z*b.z; acc[2][3]+=a.z*b.w;
            acc[3][0]+=a.w*b.x; acc[3][1]+=a.w*b.y; acc[3][2]+=a.w*b.z; acc[3][3]+=a.w*b.w;
        }
        __syncthreads();
    }

    #pragma unroll
    for (int i=0;i<4;i++){
        int m = m0 + ty*4 + i;
        if (m >= M) continue;
        #pragma unroll
        for (int j=0;j<4;j++){
            int n = n0 + tx*4 + j;
            if (n >= N) continue;
            float v = acc[i][j];
            if (bias1) v += bias1[n];
            if (Cadd)  v += Cadd[(size_t)m*ldadd + n];
            if (remap){
                int t = m >> 8, b = m & 255;
                C[(size_t)(b*TT + t)*NC + n] = v;
            } else {
                C[(size_t)m*ldc + n] = v;
            }
        }
    }
}

// ---------------- mean over T of batch_H ------------------------------------
__global__ void mean_kernel(const float* __restrict__ bH, float* __restrict__ out)
{
    int idx = blockIdx.x*256 + threadIdx.x;
    if (idx >= BB*INSZ) return;
    int b = idx >> 9, k = idx & 511;
    const float* p = bH + (size_t)b*TT*INSZ + k;
    float s = 0.f;
    #pragma unroll
    for (int t=0;t<TT;t++) s += p[t*INSZ];
    out[idx] = s * (1.0f/26.0f);
}

// ---------------- init h0/c0 -------------------------------------------------
__global__ void init_kernel(const float* __restrict__ hh, const float* __restrict__ hc,
                            float* __restrict__ h1, float* __restrict__ h2,
                            float* __restrict__ c1, float* __restrict__ c2)
{
    int idx = blockIdx.x*256 + threadIdx.x;
    if (idx >= BB*HS) return;
    float h0 = 0.5f*(hh[idx] + hh[BB*HS + idx]);
    float c0 = 0.5f*(hc[idx] + hc[BB*HS + idx]);
    h1[idx]=h0; h2[idx]=h0; c1[idx]=c0; c2[idx]=c0;
}

// ---------------- attention: e -> softmax -> context (fmh fp16) --------------
__global__ void attn_kernel(const __half* __restrict__ fmh, const float* __restrict__ q,
                            const float* __restrict__ ws, const float* __restrict__ sb,
                            float* __restrict__ ctx)
{
    __shared__ float qs[CH];
    __shared__ float wss[CH];
    __shared__ float red[256];
    __shared__ float alpha[256];

    int b = blockIdx.x;
    int p = threadIdx.x;
    const __half* f = fmh + (size_t)b * CH * PP;

    qs[p]       = q[b*HS + p];
    qs[p+256]   = q[b*HS + p + 256];
    wss[p]      = ws[p];
    wss[p+256]  = ws[p+256];
    __syncthreads();

    float acc = 0.f;
    #pragma unroll 4
    for (int c=0; c<CH; c++){
        acc += ftanh(__half2float(f[c*PP + p]) + qs[c]) * wss[c];
    }
    float e = acc + sb[0];

    red[p] = e; __syncthreads();
    #pragma unroll
    for (int s=128; s>0; s>>=1){
        if (p < s) red[p] = fmaxf(red[p], red[p+s]);
        __syncthreads();
    }
    float mx = red[0];
    __syncthreads();
    float ex = fexp(e - mx);
    red[p] = ex; __syncthreads();
    #pragma unroll
    for (int s=128; s>0; s>>=1){
        if (p < s) red[p] += red[p+s];
        __syncthreads();
    }
    float sum = red[0];
    __syncthreads();
    alpha[p] = ex * frcp(sum);
    __syncthreads();

    int lane = p & 31, wid = p >> 5;
    for (int c = wid; c < CH; c += 8){
        const __half* fr = f + c*PP;
        float s = 0.f;
        #pragma unroll
        for (int pp = lane; pp < PP; pp += 32) s += alpha[pp] * __half2float(fr[pp]);
        #pragma unroll
        for (int o=16; o>0; o>>=1) s += __shfl_down_sync(0xffffffffu, s, o);
        if (lane == 0) ctx[b*HS + c] = s;
    }
}

// ---------------- LSTM pointwise --------------------------------------------
__global__ void lstm_kernel(const float* __restrict__ g, const float* __restrict__ cin,
                            float* __restrict__ hout, float* __restrict__ cout)
{
    int idx = blockIdx.x*256 + threadIdx.x;
    if (idx >= BB*HS) return;
    int b = idx >> 9, j = idx & 511;
    const float* gb = g + (size_t)b*4*HS;
    float i_ = gb[j], f_ = gb[HS + j], gg = gb[2*HS + j], o_ = gb[3*HS + j];
    float c2 = fsigm(f_)*cin[idx] + fsigm(i_)*ftanh(gg);
    cout[idx] = c2;
    hout[idx] = fsigm(o_)*ftanh(c2);
}

// ---------------- host orchestration ----------------------------------------
extern "C" void kernel_launch(void* const* d_in, const int* in_sizes, int n_in,
                              void* d_out, int out_size)
{
    const float* feature_map = (const float*)d_in[0];
    const float* batch_H     = (const float*)d_in[1];
    const float* hidden_h    = (const float*)d_in[2];
    const float* hidden_c    = (const float*)d_in[3];
    const int*   text        = (const int*)  d_in[4];
    const float* i2h_w       = (const float*)d_in[5];
    const float* h2h_w       = (const float*)d_in[6];
    const float* h2h_b       = (const float*)d_in[7];
    const float* conv_m2h_w  = (const float*)d_in[8];
    const float* conv_m2h_b  = (const float*)d_in[9];
    const float* conv_h2h_w  = (const float*)d_in[10];
    const float* conv_h2h_b  = (const float*)d_in[11];
    const float* score_w     = (const float*)d_in[12];
    const float* score_b     = (const float*)d_in[13];
    const float* rnn1_w_ih   = (const float*)d_in[14];
    const float* rnn1_w_hh   = (const float*)d_in[15];
    const float* rnn1_b_ih   = (const float*)d_in[16];
    const float* rnn1_b_hh   = (const float*)d_in[17];
    const float* hlin_w      = (const float*)d_in[18];
    const float* hlin_b      = (const float*)d_in[19];
    const float* rnn2_w_ih   = (const float*)d_in[20];
    const float* rnn2_w_hh   = (const float*)d_in[21];
    const float* rnn2_b_ih   = (const float*)d_in[22];
    const float* rnn2_b_hh   = (const float*)d_in[23];
    const float* gen_w       = (const float*)d_in[24];
    const float* gen_b       = (const float*)d_in[25];
    float* out = (float*)d_out;

    __half *ahT,*bhT,*fmh;
    float *meanH,*bhproj,*Wq,*qb,*w1ih;
    float *h1a,*c1a,*h2a,*c2a,*h1b,*c1b,*c2b,*hist,*q,*ctx,*gates,*cur;
    cudaGetSymbolAddress((void**)&ahT, g_ahT);
    cudaGetSymbolAddress((void**)&bhT, g_bhT);
    cudaGetSymbolAddress((void**)&fmh, g_fmh);
    cudaGetSymbolAddress((void**)&meanH, g_meanH);
    cudaGetSymbolAddress((void**)&bhproj,g_bhproj);
    cudaGetSymbolAddress((void**)&Wq,    g_Wq);
    cudaGetSymbolAddress((void**)&qb,    g_qb);
    cudaGetSymbolAddress((void**)&w1ih,  g_w1ih);
    cudaGetSymbolAddress((void**)&h1a, g_h1a); cudaGetSymbolAddress((void**)&c1a, g_c1a);
    cudaGetSymbolAddress((void**)&h2a, g_h2a); cudaGetSymbolAddress((void**)&c2a, g_c2a);
    cudaGetSymbolAddress((void**)&h1b, g_h1b); cudaGetSymbolAddress((void**)&c1b, g_c1b);
    cudaGetSymbolAddress((void**)&c2b, g_c2b); cudaGetSymbolAddress((void**)&hist, g_h2hist);
    cudaGetSymbolAddress((void**)&q,   g_q);   cudaGetSymbolAddress((void**)&ctx, g_ctx);
    cudaGetSymbolAddress((void**)&gates, g_gates); cudaGetSymbolAddress((void**)&cur, g_cur);

    // conv prep + fp16 tensor-core conv
    padT_kernel<<<256*10*16, 256>>>(feature_map, ahT);
    wT_kernel<<<(9*CH*CH+255)/256, 256>>>(conv_m2h_w, bhT);
    w1ih_kernel<<<(4*HS*INSZ+255)/256, 256>>>(rnn1_w_ih, w1ih);
    conv_fp16_kernel<<<dim3(4,2,BB), 256>>>(ahT, bhT, conv_m2h_b, fmh);

    // prologue (fp32)
    mean_kernel<<<512,256>>>(batch_H, meanH);
    gemm_kernel<<<dim3(8,4),256>>>(bhproj, HS, meanH, INSZ, i2h_w, INSZ, INSZ,
                                   h2h_b, nullptr,0, 0,0, BB, HS);
    gemm_kernel<<<dim3(8,8),256>>>(Wq, HS, conv_h2h_w, HS, h2h_w, HS, HS,
                                   nullptr, nullptr,0, 1,0, HS, HS);
    gemm_kernel<<<dim3(8,4),256>>>(qb, HS, bhproj, HS, conv_h2h_w, HS, HS,
                                   conv_h2h_b, nullptr,0, 0,0, BB, HS);
    init_kernel<<<512,256>>>(hidden_h, hidden_c, h1a, h2a, c1a, c2a);

    float *h1c=h1a,*c1c=c1a,*h2c=h2a,*c2c=c2a;
    float *h1n=h1b,*c1n=c1b,*c2n=c2b;

    for (int t=0; t<TT; t++){
        float* h2n = hist + (size_t)t*BB*HS;
        // q = qb + h2 @ Wq^T
        gemm_tf32_kernel<<<dim3(4,2),256>>>(q, HS,
            h2c, HS, Wq, HS, HS, nullptr,0,nullptr,0,0,
            nullptr,nullptr, qb, HS, nullptr,0,0, nullptr,0);
        // attention -> ctx
        attn_kernel<<<BB,256>>>(fmh, q, score_w, score_b, ctx);
        // gates1
        gemm_tf32_kernel<<<dim3(16,2),256>>>(gates, 4*HS,
            ctx, HS, w1ih, INSZ, HS,
            h1c, HS, rnn1_w_hh, HS, HS,
            rnn1_b_ih, rnn1_b_hh, nullptr,0,
            rnn1_w_ih, INSZ+NC, INSZ, text + t, TT);
        lstm_kernel<<<512,256>>>(gates, c1c, h1n, c1n);
        // cur = h1n @ hlin_w^T + hlin_b
        gemm_tf32_kernel<<<dim3(4,2),256>>>(cur, HS,
            h1n, HS, hlin_w, HS, HS, nullptr,0,nullptr,0,0,
            hlin_b, nullptr, nullptr,0, nullptr,0,0, nullptr,0);
        // gates2
        gemm_tf32_kernel<<<dim3(16,2),256>>>(gates, 4*HS,
            cur, HS, rnn2_w_ih, HS, HS,
            h2c, HS, rnn2_w_hh, HS, HS,
            rnn2_b_ih, rnn2_b_hh, nullptr,0,
            nullptr,0,0, nullptr,0);
        lstm_kernel<<<512,256>>>(gates, c2c, h2n, c2n);

        float* tp;
        tp=h1c; h1c=h1n; h1n=tp;  tp=c1c; c1c=c1n; c1n=tp;
        h2c = h2n;
        tp=c2c; c2c=c2n; c2n=tp;
    }

    // probs: one batched GEMM over all timesteps, output remapped to [b][t][n]
    gemm_kernel<<<dim3(1,104),256>>>(out, NC,
        hist, HS, gen_w, HS, HS,
        gen_b, nullptr,0, 0,1, TT*BB, NC);
}

// round 8
// speedup vs baseline: 2.2800x; 1.0093x over previous
#include <cuda_runtime.h>
#include <cuda_fp16.h>
#include <math.h>
#include <stdint.h>

#define BB 256
#define HS 512
#define INSZ 512
#define NC 38
#define TT 26
#define CH 512
#define PP 256   /* 8*32 */

// ---------------- scratch (device globals; no allocation allowed) ----------
__device__ __align__(16) __half g_ahT[(size_t)3*BB*320*CH]; // padded input, [kw][b][pos320][ic], fp16
__device__ __align__(16) __half g_bhT[9*CH*CH];             // weights [khw][oc][ic], fp16
__device__ __align__(16) __half g_fmh[(size_t)BB*CH*PP];    // conv output, fp16, 67MB (L2-resident)
__device__ float g_meanH[BB*INSZ];
__device__ float g_bhproj[BB*HS];
__device__ float g_Wq[HS*HS];                      // conv1x1 @ h2h_w
__device__ float g_qb[BB*HS];
__device__ float g_w1ih[4*HS*INSZ];                // rnn1_w_ih[:, :512] repacked ld=512
__device__ float g_h1a[BB*HS], g_c1a[BB*HS], g_h2a[BB*HS], g_c2a[BB*HS];
__device__ float g_h1b[BB*HS], g_c1b[BB*HS], g_c2b[BB*HS];
__device__ float g_h2hist[(size_t)TT*BB*HS];       // h2 per step (13.6MB)
__device__ float g_q[BB*HS];
__device__ float g_ctx[BB*HS];
__device__ float g_gates[BB*4*HS];
__device__ float g_cur[BB*HS];

// ---------------- fast math ------------------------------------------------
__device__ __forceinline__ float fexp(float x){
    float y; asm("ex2.approx.f32 %0, %1;" : "=f"(y) : "f"(x*1.4426950408889634f)); return y;
}
__device__ __forceinline__ float frcp(float x){
    float y; asm("rcp.approx.f32 %0, %1;" : "=f"(y) : "f"(x)); return y;
}
__device__ __forceinline__ float ftanh(float x){
    float xc = fminf(fmaxf(x, -15.f), 15.f);
    float t = fexp(2.f*xc);
    return (t - 1.f) * frcp(t + 1.f);
}
__device__ __forceinline__ float fsigm(float x){
    return frcp(1.f + fexp(-x));
}
__device__ __forceinline__ float tf32r(float x){
    uint32_t u; asm("cvt.rna.tf32.f32 %0, %1;" : "=r"(u) : "f"(x)); return __uint_as_float(u);
}
__device__ __forceinline__ void mma_tf32(float* d, const uint32_t* a, const uint32_t* b){
    asm volatile(
      "mma.sync.aligned.m16n8k8.row.col.f32.tf32.tf32.f32 "
      "{%0,%1,%2,%3},{%4,%5,%6,%7},{%8,%9},{%0,%1,%2,%3};"
      : "+f"(d[0]),"+f"(d[1]),"+f"(d[2]),"+f"(d[3])
      : "r"(a[0]),"r"(a[1]),"r"(a[2]),"r"(a[3]), "r"(b[0]),"r"(b[1]));
}
__device__ __forceinline__ void mma_fp16(float* d, const uint32_t* a, const uint32_t* b){
    asm volatile(
      "mma.sync.aligned.m16n8k16.row.col.f32.f16.f16.f32 "
      "{%0,%1,%2,%3},{%4,%5,%6,%7},{%8,%9},{%0,%1,%2,%3};"
      : "+f"(d[0]),"+f"(d[1]),"+f"(d[2]),"+f"(d[3])
      : "r"(a[0]),"r"(a[1]),"r"(a[2]),"r"(a[3]), "r"(b[0]),"r"(b[1]));
}

// ---------------- prep kernels ------------------------------------------------
// out[kw][b][rr*32+c][ic] = fp16(in[b][ic][(rr-1)*32 + c + kw - 1]) or 0
__global__ void padT_kernel(const float* __restrict__ in, __half* __restrict__ oh)
{
    __shared__ float s[32][33];
    int blk = blockIdx.x;            // 256b * 10rr * 16icb
    int icb = blk & 15;
    int rr  = (blk >> 4) % 10;
    int b   = blk >> 4; b /= 10;
    int t = threadIdx.x;
    int r = rr - 1;

    if ((unsigned)r < 8u){
        int c = t & 31, icq = t >> 5;
        #pragma unroll
        for (int j=0;j<4;j++){
            int ic = icq + j*8;
            s[ic][c] = in[((size_t)b*CH + icb*32 + ic)*PP + r*32 + c];
        }
    }
    __syncthreads();

    int icl = t & 31, cq = t >> 5;
    #pragma unroll
    for (int j=0;j<4;j++){
        int c = cq + j*8;
        #pragma unroll
        for (int kw=0; kw<3; kw++){
            int cc = c + kw - 1;
            float v = 0.f;
            if ((unsigned)r < 8u && (unsigned)cc < 32u) v = s[icl][cc];
            size_t off = (((size_t)kw*BB + b)*320 + rr*32 + c)*CH + icb*32 + icl;
            oh[off] = __float2half(v);
        }
    }
}

// weights: out[khw][oc][ic] fp16 from w[oc][ic][khw]
__global__ void wT_kernel(const float* __restrict__ w, __half* __restrict__ oh)
{
    int idx = blockIdx.x*256 + threadIdx.x;
    if (idx >= 9*CH*CH) return;
    int ic = idx & 511;
    int oc = (idx >> 9) & 511;
    int khw = idx >> 18;
    oh[((size_t)khw*CH + oc)*CH + ic] = __float2half(w[((size_t)oc*CH + ic)*9 + khw]);
}

// repack rnn1_w_ih[:, :INSZ] from ld=550 to ld=512
__global__ void w1ih_kernel(const float* __restrict__ w, float* __restrict__ out)
{
    int idx = blockIdx.x*256 + threadIdx.x;
    if (idx >= 4*HS*INSZ) return;
    int k = idx & 511;
    int n = idx >> 9;
    out[idx] = w[(size_t)n*(INSZ+NC) + k];
}

// ---------------- conv 3x3 SAME via fp16 mma m16n8k16, 4-stage cp.async ------
// block tile 128(pos) x 128(oc), 8 warps (2m x 4n), 144 K-iters of 32
// dyn smem: As[4][128][20]w + Bs[4][128][20]w = 81920 B
#define CPITCH 20
#define CSTAGE_W (128*CPITCH)

__global__ void __launch_bounds__(256, 2) conv_fp16_kernel(
    const __half* __restrict__ Ag, const __half* __restrict__ Bg,
    const float* __restrict__ bias, __half* __restrict__ out)
{
    extern __shared__ __align__(16) uint32_t sm[];
    uint32_t* Asm = sm;                    // [4][128][20]
    uint32_t* Bsm = sm + 4*CSTAGE_W;
    const int b  = blockIdx.z;
    const int m0 = blockIdx.y * 128;
    const int n0 = blockIdx.x * 128;
    const int tid = threadIdx.x;
    const int lane = tid & 31, warp = tid >> 5;
    const int wm = (warp >> 2) * 64;
    const int wn = (warp & 3) * 32;
    const int gid = lane >> 2, tig = lane & 3;

    const int lrow = tid >> 1;     // 0..127
    const int lch  = tid & 1;      // 16B chunk pair: lch and lch+2

    float acc[4][4][4];
    #pragma unroll
    for (int i=0;i<4;i++)
      #pragma unroll
      for (int j=0;j<4;j++)
        #pragma unroll
        for (int k=0;k<4;k++) acc[i][j][k]=0.f;

    uint32_t sAb = (uint32_t)__cvta_generic_to_shared(Asm);
    uint32_t sBb = (uint32_t)__cvta_generic_to_shared(Bsm);

#define CLOAD(s) do { \
        int st_  = (s) & 3; \
        int khw_ = (s) >> 4; \
        int ic0_ = ((s) & 15) << 5; \
        int kh_ = khw_ / 3, kw_ = khw_ - kh_*3; \
        const __half* ap_ = Ag + (((size_t)kw_*BB + b)*320 + m0 + kh_*32 + lrow)*CH + ic0_ + lch*8; \
        const __half* bp_ = Bg + ((size_t)khw_*CH + n0 + lrow)*CH + ic0_ + lch*8; \
        uint32_t da_ = sAb + (uint32_t)(((st_*128 + lrow)*CPITCH + lch*4)*4); \
        uint32_t db_ = sBb + (uint32_t)(((st_*128 + lrow)*CPITCH + lch*4)*4); \
        asm volatile("cp.async.ca.shared.global [%0], [%1], 16;" :: "r"(da_),      "l"(ap_)); \
        asm volatile("cp.async.ca.shared.global [%0], [%1], 16;" :: "r"(da_ + 32), "l"(ap_ + 16)); \
        asm volatile("cp.async.ca.shared.global [%0], [%1], 16;" :: "r"(db_),      "l"(bp_)); \
        asm volatile("cp.async.ca.shared.global [%0], [%1], 16;" :: "r"(db_ + 32), "l"(bp_ + 16)); \
        asm volatile("cp.async.commit_group;"); \
    } while(0)

    CLOAD(0); CLOAD(1); CLOAD(2);

    for (int s = 0; s < 144; ++s){
        asm volatile("cp.async.wait_group 2;");
        __syncthreads();
        if (s + 3 < 144) CLOAD(s + 3);

        const uint32_t* A_ = Asm + (s & 3) * CSTAGE_W;
        const uint32_t* B_ = Bsm + (s & 3) * CSTAGE_W;

        #pragma unroll
        for (int h = 0; h < 2; ++h){
            const int kb = h*8 + tig;
            uint32_t afr[4][4], bfr[4][2];
            #pragma unroll
            for (int mi=0; mi<4; ++mi){
                int rowb = wm + mi*16 + gid;
                afr[mi][0] = A_[rowb*CPITCH + kb];
                afr[mi][1] = A_[(rowb+8)*CPITCH + kb];
                afr[mi][2] = A_[rowb*CPITCH + kb + 4];
                afr[mi][3] = A_[(rowb+8)*CPITCH + kb + 4];
            }
            #pragma unroll
            for (int ni=0; ni<4; ++ni){
                int colb = wn + ni*8 + gid;
                bfr[ni][0] = B_[colb*CPITCH + kb];
                bfr[ni][1] = B_[colb*CPITCH + kb + 4];
            }
            #pragma unroll
            for (int mi=0; mi<4; ++mi)
                #pragma unroll
                for (int ni=0; ni<4; ++ni)
                    mma_fp16(acc[mi][ni], afr[mi], bfr[ni]);
        }
    }
#undef CLOAD

    #pragma unroll
    for (int mi=0; mi<4; ++mi){
        int prow = m0 + wm + mi*16 + gid;
        #pragma unroll
        for (int ni=0; ni<4; ++ni){
            int oc = n0 + wn + ni*8 + tig*2;
            float bz0 = bias[oc], bz1 = bias[oc+1];
            __half* o0 = out + ((size_t)b*CH + oc)*PP;
            o0[prow]          = __float2half(acc[mi][ni][0] + bz0);
            o0[PP + prow]     = __float2half(acc[mi][ni][1] + bz1);
            o0[prow + 8]      = __float2half(acc[mi][ni][2] + bz0);
            o0[PP + prow + 8] = __float2half(acc[mi][ni][3] + bz1);
        }
    }
}

// ---------------- tf32 mma GEMM, software-pipelined --------------------------
// NOTE: all lda/ldw MUST be multiples of 4 (float4 loads).
__global__ void __launch_bounds__(256, 1) gemm_tf32_kernel(
    float* __restrict__ C, int ldc,
    const float* __restrict__ A1, int lda1, const float* __restrict__ W1, int ldw1, int K1,
    const float* __restrict__ A2, int lda2, const float* __restrict__ W2, int ldw2, int K2,
    const float* __restrict__ bias1, const float* __restrict__ bias2,
    const float* __restrict__ Cadd, int ldadd,
    const float* __restrict__ Wg, int ldwg, int gcolbase,
    const int* __restrict__ textcol, int textstride)
{
    __shared__ float As[128][20];
    __shared__ float Bs[128][20];
    const int m0 = blockIdx.y * 128;
    const int n0 = blockIdx.x * 128;
    const int tid = threadIdx.x;
    const int lane = tid & 31, warp = tid >> 5;
    const int wm = (warp >> 2) * 64;
    const int wn = (warp & 3) * 32;
    const int gid = lane >> 2, tig = lane & 3;

    const int lrow = tid >> 2;          // 0..63
    const int lk4  = (tid & 3) * 4;     // 0,4,8,12

    float acc[4][4][4];
    #pragma unroll
    for (int i=0;i<4;i++)
      #pragma unroll
      for (int j=0;j<4;j++)
        #pragma unroll
        for (int k=0;k<4;k++) acc[i][j][k]=0.f;

    const int s1 = K1 >> 4;
    const int s2 = (A2 != nullptr) ? (K2 >> 4) : 0;
    const int S  = s1 + s2;

    float4 av0, av1, bv0, bv1;

#define GEMM_LOAD(s) do { \
        const float* A_; const float* W_; int lda_, ldw_, k0_; \
        if ((s) < s1){ A_ = A1; W_ = W1; lda_ = lda1; ldw_ = ldw1; k0_ = (s) << 4; } \
        else         { A_ = A2; W_ = W2; lda_ = lda2; ldw_ = ldw2; k0_ = ((s) - s1) << 4; } \
        av0 = *(const float4*)(A_ + (size_t)(m0+lrow)*lda_    + k0_ + lk4); \
        av1 = *(const float4*)(A_ + (size_t)(m0+lrow+64)*lda_ + k0_ + lk4); \
        bv0 = *(const float4*)(W_ + (size_t)(n0+lrow)*ldw_    + k0_ + lk4); \
        bv1 = *(const float4*)(W_ + (size_t)(n0+lrow+64)*ldw_ + k0_ + lk4); \
    } while(0)

    GEMM_LOAD(0);

    for (int s = 0; s < S; ++s){
        __syncthreads();
        As[lrow   ][lk4  ] = tf32r(av0.x); As[lrow   ][lk4+1] = tf32r(av0.y);
        As[lrow   ][lk4+2] = tf32r(av0.z); As[lrow   ][lk4+3] = tf32r(av0.w);
        As[lrow+64][lk4  ] = tf32r(av1.x); As[lrow+64][lk4+1] = tf32r(av1.y);
        As[lrow+64][lk4+2] = tf32r(av1.z); As[lrow+64][lk4+3] = tf32r(av1.w);
        Bs[lrow   ][lk4  ] = tf32r(bv0.x); Bs[lrow   ][lk4+1] = tf32r(bv0.y);
        Bs[lrow   ][lk4+2] = tf32r(bv0.z); Bs[lrow   ][lk4+3] = tf32r(bv0.w);
        Bs[lrow+64][lk4  ] = tf32r(bv1.x); Bs[lrow+64][lk4+1] = tf32r(bv1.y);
        Bs[lrow+64][lk4+2] = tf32r(bv1.z); Bs[lrow+64][lk4+3] = tf32r(bv1.w);
        __syncthreads();

        if (s + 1 < S) GEMM_LOAD(s + 1);

        #pragma unroll
        for (int ss = 0; ss < 2; ++ss){
            const int kb = ss*8 + tig;
            uint32_t afr[4][4], bfr[4][2];
            #pragma unroll
            for (int mi=0; mi<4; ++mi){
                int rowb = wm + mi*16 + gid;
                afr[mi][0] = __float_as_uint(As[rowb  ][kb]);
                afr[mi][1] = __float_as_uint(As[rowb+8][kb]);
                afr[mi][2] = __float_as_uint(As[rowb  ][kb+4]);
                afr[mi][3] = __float_as_uint(As[rowb+8][kb+4]);
            }
            #pragma unroll
            for (int ni=0; ni<4; ++ni){
                int colb = wn + ni*8 + gid;
                bfr[ni][0] = __float_as_uint(Bs[colb][kb]);
                bfr[ni][1] = __float_as_uint(Bs[colb][kb+4]);
            }
            #pragma unroll
            for (int mi=0; mi<4; ++mi)
                #pragma unroll
                for (int ni=0; ni<4; ++ni)
                    mma_tf32(acc[mi][ni], afr[mi], bfr[ni]);
        }
    }
#undef GEMM_LOAD

    #pragma unroll
    for (int mi=0; mi<4; ++mi){
        int m = m0 + wm + mi*16 + gid;
        int tc0 = 0, tc1 = 0;
        if (Wg){ tc0 = textcol[m*textstride]; tc1 = textcol[(m+8)*textstride]; }
        #pragma unroll
        for (int ni=0; ni<4; ++ni){
            int n = n0 + wn + ni*8 + tig*2;
            float b0 = 0.f, b1 = 0.f;
            if (bias1){ b0 += bias1[n]; b1 += bias1[n+1]; }
            if (bias2){ b0 += bias2[n]; b1 += bias2[n+1]; }
            float v00 = acc[mi][ni][0] + b0;
            float v01 = acc[mi][ni][1] + b1;
            float v10 = acc[mi][ni][2] + b0;
            float v11 = acc[mi][ni][3] + b1;
            if (Cadd){
                v00 += Cadd[(size_t)m*ldadd + n];     v01 += Cadd[(size_t)m*ldadd + n+1];
                v10 += Cadd[(size_t)(m+8)*ldadd + n]; v11 += Cadd[(size_t)(m+8)*ldadd + n+1];
            }
            if (Wg){
                v00 += Wg[(size_t)n*ldwg + gcolbase + tc0];
                v01 += Wg[(size_t)(n+1)*ldwg + gcolbase + tc0];
                v10 += Wg[(size_t)n*ldwg + gcolbase + tc1];
                v11 += Wg[(size_t)(n+1)*ldwg + gcolbase + tc1];
            }
            C[(size_t)m*ldc + n]       = v00;
            C[(size_t)m*ldc + n+1]     = v01;
            C[(size_t)(m+8)*ldc + n]   = v10;
            C[(size_t)(m+8)*ldc + n+1] = v11;
        }
    }
}

// ---------------- fp32 fused GEMM (prologue + generator) --------------------
__global__ void gemm_kernel(
    float* __restrict__ C, int ldc,
    const float* __restrict__ A1, int lda1, const float* __restrict__ W1, int ldw1, int K1,
    const float* __restrict__ bias1,
    const float* __restrict__ Cadd, int ldadd,
    int nn, int remap, int M, int N)
{
    __shared__ float As[16][68];
    __shared__ float Bs[16][68];
    int m0 = blockIdx.y * 64;
    int n0 = blockIdx.x * 64;
    int tid = threadIdx.x;
    int tx = tid & 15, ty = tid >> 4;

    float acc[4][4];
    #pragma unroll
    for (int i=0;i<4;i++)
        #pragma unroll
        for (int j=0;j<4;j++) acc[i][j]=0.f;

    for (int k0=0; k0<K1; k0+=16){
        #pragma unroll
        for (int i=0;i<4;i++){
            int e = i*256 + tid;
            int m = e >> 4, kk = e & 15;
            int gm = m0 + m, gk = k0 + kk;
            As[kk][m] = (gm < M && gk < K1) ? A1[(size_t)gm*lda1 + gk] : 0.f;
        }
        if (nn){
            #pragma unroll
            for (int i=0;i<4;i++){
                int e = i*256 + tid;
                int kk = e >> 6, n = e & 63;
                int gn = n0 + n, gk = k0 + kk;
                Bs[kk][n] = (gn < N && gk < K1) ? W1[(size_t)gk*ldw1 + gn] : 0.f;
            }
        } else {
            #pragma unroll
            for (int i=0;i<4;i++){
                int e = i*256 + tid;
                int n = e >> 4, kk = e & 15;
                int gn = n0 + n, gk = k0 + kk;
                Bs[kk][n] = (gn < N && gk < K1) ? W1[(size_t)gn*ldw1 + gk] : 0.f;
            }
        }
        __syncthreads();
        #pragma unroll
        for (int kk=0; kk<16; kk++){
            float4 a = *(const float4*)&As[kk][ty*4];
            float4 b = *(const float4*)&Bs[kk][tx*4];
            acc[0][0]+=a.x*b.x; acc[0][1]+=a.x*b.y; acc[0][2]+=a.x*b.z; acc[0][3]+=a.x*b.w;
            acc[1][0]+=a.y*b.x; acc[1][1]+=a.y*b.y; acc[1][2]+=a.y*b.z; acc[1][3]+=a.y*b.w;
            acc[2][0]+=a.z*b.x; acc[2][1]+=a.z*b.y; acc[2][2]+=a.z*b.z; acc[2][3]+=a.z*b.w;
            acc[3][0]+=a.w*b.x; acc[3][1]+=a.w*b.y; acc[3][2]+=a.w*b.z; acc[3][3]+=a.w*b.w;
        }
        __syncthreads();
    }

    #pragma unroll
    for (int i=0;i<4;i++){
        int m = m0 + ty*4 + i;
        if (m >= M) continue;
        #pragma unroll
        for (int j=0;j<4;j++){
            int n = n0 + tx*4 + j;
            if (n >= N) continue;
            float v = acc[i][j];
            if (bias1) v += bias1[n];
            if (Cadd)  v += Cadd[(size_t)m*ldadd + n];
            if (remap){
                int t = m >> 8, b = m & 255;
                C[(size_t)(b*TT + t)*NC + n] = v;
            } else {
                C[(size_t)m*ldc + n] = v;
            }
        }
    }
}

// ---------------- mean over T of batch_H ------------------------------------
__global__ void mean_kernel(const float* __restrict__ bH, float* __restrict__ out)
{
    int idx = blockIdx.x*256 + threadIdx.x;
    if (idx >= BB*INSZ) return;
    int b = idx >> 9, k = idx & 511;
    const float* p = bH + (size_t)b*TT*INSZ + k;
    float s = 0.f;
    #pragma unroll
    for (int t=0;t<TT;t++) s += p[t*INSZ];
    out[idx] = s * (1.0f/26.0f);
}

// ---------------- init h0/c0 -------------------------------------------------
__global__ void init_kernel(const float* __restrict__ hh, const float* __restrict__ hc,
                            float* __restrict__ h1, float* __restrict__ h2,
                            float* __restrict__ c1, float* __restrict__ c2)
{
    int idx = blockIdx.x*256 + threadIdx.x;
    if (idx >= BB*HS) return;
    float h0 = 0.5f*(hh[idx] + hh[BB*HS + idx]);
    float c0 = 0.5f*(hc[idx] + hc[BB*HS + idx]);
    h1[idx]=h0; h2[idx]=h0; c1[idx]=c0; c2[idx]=c0;
}

// ---------------- attention: e -> softmax -> context (fmh fp16) --------------
__global__ void attn_kernel(const __half* __restrict__ fmh, const float* __restrict__ q,
                            const float* __restrict__ ws, const float* __restrict__ sb,
                            float* __restrict__ ctx)
{
    __shared__ float qs[CH];
    __shared__ float wss[CH];
    __shared__ float red[256];
    __shared__ float alpha[256];

    int b = blockIdx.x;
    int p = threadIdx.x;
    const __half* f = fmh + (size_t)b * CH * PP;

    qs[p]       = q[b*HS + p];
    qs[p+256]   = q[b*HS + p + 256];
    wss[p]      = ws[p];
    wss[p+256]  = ws[p+256];
    __syncthreads();

    float acc = 0.f;
    #pragma unroll 4
    for (int c=0; c<CH; c++){
        acc += ftanh(__half2float(f[c*PP + p]) + qs[c]) * wss[c];
    }
    float e = acc + sb[0];

    red[p] = e; __syncthreads();
    #pragma unroll
    for (int s=128; s>0; s>>=1){
        if (p < s) red[p] = fmaxf(red[p], red[p+s]);
        __syncthreads();
    }
    float mx = red[0];
    __syncthreads();
    float ex = fexp(e - mx);
    red[p] = ex; __syncthreads();
    #pragma unroll
    for (int s=128; s>0; s>>=1){
        if (p < s) red[p] += red[p+s];
        __syncthreads();
    }
    float sum = red[0];
    __syncthreads();
    alpha[p] = ex * frcp(sum);
    __syncthreads();

    int lane = p & 31, wid = p >> 5;
    for (int c = wid; c < CH; c += 8){
        const __half* fr = f + c*PP;
        float s = 0.f;
        #pragma unroll
        for (int pp = lane; pp < PP; pp += 32) s += alpha[pp] * __half2float(fr[pp]);
        #pragma unroll
        for (int o=16; o>0; o>>=1) s += __shfl_down_sync(0xffffffffu, s, o);
        if (lane == 0) ctx[b*HS + c] = s;
    }
}

// ---------------- LSTM pointwise --------------------------------------------
__global__ void lstm_kernel(const float* __restrict__ g, const float* __restrict__ cin,
                            float* __restrict__ hout, float* __restrict__ cout)
{
    int idx = blockIdx.x*256 + threadIdx.x;
    if (idx >= BB*HS) return;
    int b = idx >> 9, j = idx & 511;
    const float* gb = g + (size_t)b*4*HS;
    float i_ = gb[j], f_ = gb[HS + j], gg = gb[2*HS + j], o_ = gb[3*HS + j];
    float c2 = fsigm(f_)*cin[idx] + fsigm(i_)*ftanh(gg);
    cout[idx] = c2;
    hout[idx] = fsigm(o_)*ftanh(c2);
}

// ---------------- host orchestration ----------------------------------------
extern "C" void kernel_launch(void* const* d_in, const int* in_sizes, int n_in,
                              void* d_out, int out_size)
{
    const float* feature_map = (const float*)d_in[0];
    const float* batch_H     = (const float*)d_in[1];
    const float* hidden_h    = (const float*)d_in[2];
    const float* hidden_c    = (const float*)d_in[3];
    const int*   text        = (const int*)  d_in[4];
    const float* i2h_w       = (const float*)d_in[5];
    const float* h2h_w       = (const float*)d_in[6];
    const float* h2h_b       = (const float*)d_in[7];
    const float* conv_m2h_w  = (const float*)d_in[8];
    const float* conv_m2h_b  = (const float*)d_in[9];
    const float* conv_h2h_w  = (const float*)d_in[10];
    const float* conv_h2h_b  = (const float*)d_in[11];
    const float* score_w     = (const float*)d_in[12];
    const float* score_b     = (const float*)d_in[13];
    const float* rnn1_w_ih   = (const float*)d_in[14];
    const float* rnn1_w_hh   = (const float*)d_in[15];
    const float* rnn1_b_ih   = (const float*)d_in[16];
    const float* rnn1_b_hh   = (const float*)d_in[17];
    const float* hlin_w      = (const float*)d_in[18];
    const float* hlin_b      = (const float*)d_in[19];
    const float* rnn2_w_ih   = (const float*)d_in[20];
    const float* rnn2_w_hh   = (const float*)d_in[21];
    const float* rnn2_b_ih   = (const float*)d_in[22];
    const float* rnn2_b_hh   = (const float*)d_in[23];
    const float* gen_w       = (const float*)d_in[24];
    const float* gen_b       = (const float*)d_in[25];
    float* out = (float*)d_out;

    __half *ahT,*bhT,*fmh;
    float *meanH,*bhproj,*Wq,*qb,*w1ih;
    float *h1a,*c1a,*h2a,*c2a,*h1b,*c1b,*c2b,*hist,*q,*ctx,*gates,*cur;
    cudaGetSymbolAddress((void**)&ahT, g_ahT);
    cudaGetSymbolAddress((void**)&bhT, g_bhT);
    cudaGetSymbolAddress((void**)&fmh, g_fmh);
    cudaGetSymbolAddress((void**)&meanH, g_meanH);
    cudaGetSymbolAddress((void**)&bhproj,g_bhproj);
    cudaGetSymbolAddress((void**)&Wq,    g_Wq);
    cudaGetSymbolAddress((void**)&qb,    g_qb);
    cudaGetSymbolAddress((void**)&w1ih,  g_w1ih);
    cudaGetSymbolAddress((void**)&h1a, g_h1a); cudaGetSymbolAddress((void**)&c1a, g_c1a);
    cudaGetSymbolAddress((void**)&h2a, g_h2a); cudaGetSymbolAddress((void**)&c2a, g_c2a);
    cudaGetSymbolAddress((void**)&h1b, g_h1b); cudaGetSymbolAddress((void**)&c1b, g_c1b);
    cudaGetSymbolAddress((void**)&c2b, g_c2b); cudaGetSymbolAddress((void**)&hist, g_h2hist);
    cudaGetSymbolAddress((void**)&q,   g_q);   cudaGetSymbolAddress((void**)&ctx, g_ctx);
    cudaGetSymbolAddress((void**)&gates, g_gates); cudaGetSymbolAddress((void**)&cur, g_cur);

    // conv prep + fp16 tensor-core conv (4-stage cp.async pipeline)
    const int CONV_SMEM = 2 * 4 * 128 * CPITCH * 4;   // 81920
    cudaFuncSetAttribute(conv_fp16_kernel, cudaFuncAttributeMaxDynamicSharedMemorySize, CONV_SMEM);
    padT_kernel<<<256*10*16, 256>>>(feature_map, ahT);
    wT_kernel<<<(9*CH*CH+255)/256, 256>>>(conv_m2h_w, bhT);
    w1ih_kernel<<<(4*HS*INSZ+255)/256, 256>>>(rnn1_w_ih, w1ih);
    conv_fp16_kernel<<<dim3(4,2,BB), 256, CONV_SMEM>>>(ahT, bhT, conv_m2h_b, fmh);

    // prologue (fp32)
    mean_kernel<<<512,256>>>(batch_H, meanH);
    gemm_kernel<<<dim3(8,4),256>>>(bhproj, HS, meanH, INSZ, i2h_w, INSZ, INSZ,
                                   h2h_b, nullptr,0, 0,0, BB, HS);
    gemm_kernel<<<dim3(8,8),256>>>(Wq, HS, conv_h2h_w, HS, h2h_w, HS, HS,
                                   nullptr, nullptr,0, 1,0, HS, HS);
    gemm_kernel<<<dim3(8,4),256>>>(qb, HS, bhproj, HS, conv_h2h_w, HS, HS,
                                   conv_h2h_b, nullptr,0, 0,0, BB, HS);
    init_kernel<<<512,256>>>(hidden_h, hidden_c, h1a, h2a, c1a, c2a);

    float *h1c=h1a,*c1c=c1a,*h2c=h2a,*c2c=c2a;
    float *h1n=h1b,*c1n=c1b,*c2n=c2b;

    for (int t=0; t<TT; t++){
        float* h2n = hist + (size_t)t*BB*HS;
        // q = qb + h2 @ Wq^T
        gemm_tf32_kernel<<<dim3(4,2),256>>>(q, HS,
            h2c, HS, Wq, HS, HS, nullptr,0,nullptr,0,0,
            nullptr,nullptr, qb, HS, nullptr,0,0, nullptr,0);
        // attention -> ctx
        attn_kernel<<<BB,256>>>(fmh, q, score_w, score_b, ctx);
        // gates1
        gemm_tf32_kernel<<<dim3(16,2),256>>>(gates, 4*HS,
            ctx, HS, w1ih, INSZ, HS,
            h1c, HS, rnn1_w_hh, HS, HS,
            rnn1_b_ih, rnn1_b_hh, nullptr,0,
            rnn1_w_ih, INSZ+NC, INSZ, text + t, TT);
        lstm_kernel<<<512,256>>>(gates, c1c, h1n, c1n);
        // cur = h1n @ hlin_w^T + hlin_b
        gemm_tf32_kernel<<<dim3(4,2),256>>>(cur, HS,
            h1n, HS, hlin_w, HS, HS, nullptr,0,nullptr,0,0,
            hlin_b, nullptr, nullptr,0, nullptr,0,0, nullptr,0);
        // gates2
        gemm_tf32_kernel<<<dim3(16,2),256>>>(gates, 4*HS,
            cur, HS, rnn2_w_ih, HS, HS,
            h2c, HS, rnn2_w_hh, HS, HS,
            rnn2_b_ih, rnn2_b_hh, nullptr,0,
            nullptr,0,0, nullptr,0);
        lstm_kernel<<<512,256>>>(gates, c2c, h2n, c2n);

        float* tp;
        tp=h1c; h1c=h1n; h1n=tp;  tp=c1c; c1c=c1n; c1n=tp;
        h2c = h2n;
        tp=c2c; c2c=c2n; c2n=tp;
    }

    // probs: one batched GEMM over all timesteps, output remapped to [b][t][n]
    gemm_kernel<<<dim3(1,104),256>>>(out, NC,
        hist, HS, gen_w, HS, HS,
        gen_b, nullptr,0, 0,1, TT*BB, NC);
}

// round 9
// speedup vs baseline: 3.9940x; 1.7517x over previous
#include <cuda_runtime.h>
#include <cuda_fp16.h>
#include <math.h>
#include <stdint.h>

#define BB 256
#define HS 512
#define INSZ 512
#define NC 38
#define TT 26
#define CH 512
#define PP 256   /* 8*32 */

// ---------------- scratch (device globals; no allocation allowed) ----------
__device__ __align__(16) __half g_ahT[(size_t)3*BB*320*CH]; // padded input, [kw][b][pos320][ic]
__device__ __align__(16) __half g_bhT[9*CH*CH];             // conv weights [khw][oc][ic]
__device__ __align__(16) __half g_fmh[(size_t)BB*CH*PP];    // conv output fp16, 67MB
__device__ float g_meanH[BB*INSZ];
__device__ float g_bhproj[BB*HS];
__device__ float g_Wq[HS*HS];
__device__ float g_qb[BB*HS];
// fp16 packed loop weights
__device__ __align__(16) __half g_Wq16[HS*HS];
__device__ __align__(16) __half g_hlin16[HS*HS];
__device__ __align__(16) __half g_w1ih16[4*HS*INSZ];   // row 4j+g
__device__ __align__(16) __half g_w1hh16[4*HS*HS];
__device__ __align__(16) __half g_w2ih16[4*HS*HS];
__device__ __align__(16) __half g_w2hh16[4*HS*HS];
__device__ float g_bias1p[4*HS], g_bias2p[4*HS];
__device__ float g_wgp[4*HS*NC];                       // onehot gather, packed rows
// states
__device__ __align__(16) __half g_h1a16[BB*HS], g_h1b16[BB*HS], g_h2a16[BB*HS];
__device__ float g_c1a[BB*HS], g_c1b[BB*HS], g_c2a[BB*HS], g_c2b[BB*HS];
__device__ __align__(16) __half g_hist16[(size_t)TT*BB*HS];
__device__ __align__(16) __half g_q16[BB*HS];
__device__ __align__(16) __half g_ctx16[BB*HS];
__device__ __align__(16) __half g_cur16[BB*HS];

// ---------------- fast math ------------------------------------------------
__device__ __forceinline__ float fexp(float x){
    float y; asm("ex2.approx.f32 %0, %1;" : "=f"(y) : "f"(x*1.4426950408889634f)); return y;
}
__device__ __forceinline__ float frcp(float x){
    float y; asm("rcp.approx.f32 %0, %1;" : "=f"(y) : "f"(x)); return y;
}
__device__ __forceinline__ float ftanh(float x){
    float xc = fminf(fmaxf(x, -15.f), 15.f);
    float t = fexp(2.f*xc);
    return (t - 1.f) * frcp(t + 1.f);
}
__device__ __forceinline__ float fsigm(float x){
    return frcp(1.f + fexp(-x));
}
__device__ __forceinline__ void mma_fp16(float* d, const uint32_t* a, const uint32_t* b){
    asm volatile(
      "mma.sync.aligned.m16n8k16.row.col.f32.f16.f16.f32 "
      "{%0,%1,%2,%3},{%4,%5,%6,%7},{%8,%9},{%0,%1,%2,%3};"
      : "+f"(d[0]),"+f"(d[1]),"+f"(d[2]),"+f"(d[3])
      : "r"(a[0]),"r"(a[1]),"r"(a[2]),"r"(a[3]), "r"(b[0]),"r"(b[1]));
}

// ---------------- prep kernels ------------------------------------------------
__global__ void padT_kernel(const float* __restrict__ in, __half* __restrict__ oh)
{
    __shared__ float s[32][33];
    int blk = blockIdx.x;
    int icb = blk & 15;
    int rr  = (blk >> 4) % 10;
    int b   = blk >> 4; b /= 10;
    int t = threadIdx.x;
    int r = rr - 1;

    if ((unsigned)r < 8u){
        int c = t & 31, icq = t >> 5;
        #pragma unroll
        for (int j=0;j<4;j++){
            int ic = icq + j*8;
            s[ic][c] = in[((size_t)b*CH + icb*32 + ic)*PP + r*32 + c];
        }
    }
    __syncthreads();

    int icl = t & 31, cq = t >> 5;
    #pragma unroll
    for (int j=0;j<4;j++){
        int c = cq + j*8;
        #pragma unroll
        for (int kw=0; kw<3; kw++){
            int cc = c + kw - 1;
            float v = 0.f;
            if ((unsigned)r < 8u && (unsigned)cc < 32u) v = s[icl][cc];
            size_t off = (((size_t)kw*BB + b)*320 + rr*32 + c)*CH + icb*32 + icl;
            oh[off] = __float2half(v);
        }
    }
}

__global__ void wT_kernel(const float* __restrict__ w, __half* __restrict__ oh)
{
    int idx = blockIdx.x*256 + threadIdx.x;
    if (idx >= 9*CH*CH) return;
    int ic = idx & 511;
    int oc = (idx >> 9) & 511;
    int khw = idx >> 18;
    oh[((size_t)khw*CH + oc)*CH + ic] = __float2half(w[((size_t)oc*CH + ic)*9 + khw]);
}

__global__ void cast16_kernel(const float* __restrict__ in, __half* __restrict__ out, int n)
{
    int idx = blockIdx.x*256 + threadIdx.x;
    if (idx < n) out[idx] = __float2half(in[idx]);
}

// interleave-pack gate weights: out[(4j+g)*512 + k] = w[(g*512+j)*ldw + k]
__global__ void wpack16_kernel(const float* __restrict__ w, int ldw, __half* __restrict__ out)
{
    int idx = blockIdx.x*256 + threadIdx.x;
    if (idx >= 4*HS*512) return;
    int k = idx & 511;
    int row = idx >> 9;
    int j = row >> 2, g = row & 3;
    out[idx] = __float2half(w[(size_t)(g*HS + j)*ldw + k]);
}

__global__ void bpack_kernel(const float* __restrict__ bih, const float* __restrict__ bhh,
                             float* __restrict__ out)
{
    int row = blockIdx.x*256 + threadIdx.x;
    if (row >= 4*HS) return;
    int j = row >> 2, g = row & 3;
    out[row] = bih[g*HS + j] + bhh[g*HS + j];
}

__global__ void wgpack_kernel(const float* __restrict__ w, float* __restrict__ out)
{
    int idx = blockIdx.x*256 + threadIdx.x;
    if (idx >= 4*HS*NC) return;
    int c = idx % NC;
    int row = idx / NC;
    int j = row >> 2, g = row & 3;
    out[idx] = w[(size_t)(g*HS + j)*(INSZ+NC) + INSZ + c];
}

// ---------------- conv 3x3 SAME via fp16 mma, 4-stage cp.async ---------------
#define CPITCH 20
#define CSTAGE_W (128*CPITCH)

__global__ void __launch_bounds__(256, 2) conv_fp16_kernel(
    const __half* __restrict__ Ag, const __half* __restrict__ Bg,
    const float* __restrict__ bias, __half* __restrict__ out)
{
    extern __shared__ __align__(16) uint32_t sm[];
    uint32_t* Asm = sm;
    uint32_t* Bsm = sm + 4*CSTAGE_W;
    const int b  = blockIdx.z;
    const int m0 = blockIdx.y * 128;
    const int n0 = blockIdx.x * 128;
    const int tid = threadIdx.x;
    const int lane = tid & 31, warp = tid >> 5;
    const int wm = (warp >> 2) * 64;
    const int wn = (warp & 3) * 32;
    const int gid = lane >> 2, tig = lane & 3;

    const int lrow = tid >> 1;
    const int lch  = tid & 1;

    float acc[4][4][4];
    #pragma unroll
    for (int i=0;i<4;i++)
      #pragma unroll
      for (int j=0;j<4;j++)
        #pragma unroll
        for (int k=0;k<4;k++) acc[i][j][k]=0.f;

    uint32_t sAb = (uint32_t)__cvta_generic_to_shared(Asm);
    uint32_t sBb = (uint32_t)__cvta_generic_to_shared(Bsm);

#define CLOAD(s) do { \
        int st_  = (s) & 3; \
        int khw_ = (s) >> 4; \
        int ic0_ = ((s) & 15) << 5; \
        int kh_ = khw_ / 3, kw_ = khw_ - kh_*3; \
        const __half* ap_ = Ag + (((size_t)kw_*BB + b)*320 + m0 + kh_*32 + lrow)*CH + ic0_ + lch*8; \
        const __half* bp_ = Bg + ((size_t)khw_*CH + n0 + lrow)*CH + ic0_ + lch*8; \
        uint32_t da_ = sAb + (uint32_t)(((st_*128 + lrow)*CPITCH + lch*4)*4); \
        uint32_t db_ = sBb + (uint32_t)(((st_*128 + lrow)*CPITCH + lch*4)*4); \
        asm volatile("cp.async.ca.shared.global [%0], [%1], 16;" :: "r"(da_),      "l"(ap_)); \
        asm volatile("cp.async.ca.shared.global [%0], [%1], 16;" :: "r"(da_ + 32), "l"(ap_ + 16)); \
        asm volatile("cp.async.ca.shared.global [%0], [%1], 16;" :: "r"(db_),      "l"(bp_)); \
        asm volatile("cp.async.ca.shared.global [%0], [%1], 16;" :: "r"(db_ + 32), "l"(bp_ + 16)); \
        asm volatile("cp.async.commit_group;"); \
    } while(0)

    CLOAD(0); CLOAD(1); CLOAD(2);

    for (int s = 0; s < 144; ++s){
        asm volatile("cp.async.wait_group 2;");
        __syncthreads();
        if (s + 3 < 144) CLOAD(s + 3);

        const uint32_t* A_ = Asm + (s & 3) * CSTAGE_W;
        const uint32_t* B_ = Bsm + (s & 3) * CSTAGE_W;

        #pragma unroll
        for (int h = 0; h < 2; ++h){
            const int kb = h*8 + tig;
            uint32_t afr[4][4], bfr[4][2];
            #pragma unroll
            for (int mi=0; mi<4; ++mi){
                int rowb = wm + mi*16 + gid;
                afr[mi][0] = A_[rowb*CPITCH + kb];
                afr[mi][1] = A_[(rowb+8)*CPITCH + kb];
                afr[mi][2] = A_[rowb*CPITCH + kb + 4];
                afr[mi][3] = A_[(rowb+8)*CPITCH + kb + 4];
            }
            #pragma unroll
            for (int ni=0; ni<4; ++ni){
                int colb = wn + ni*8 + gid;
                bfr[ni][0] = B_[colb*CPITCH + kb];
                bfr[ni][1] = B_[colb*CPITCH + kb + 4];
            }
            #pragma unroll
            for (int mi=0; mi<4; ++mi)
                #pragma unroll
                for (int ni=0; ni<4; ++ni)
                    mma_fp16(acc[mi][ni], afr[mi], bfr[ni]);
        }
    }
#undef CLOAD

    #pragma unroll
    for (int mi=0; mi<4; ++mi){
        int prow = m0 + wm + mi*16 + gid;
        #pragma unroll
        for (int ni=0; ni<4; ++ni){
            int oc = n0 + wn + ni*8 + tig*2;
            float bz0 = bias[oc], bz1 = bias[oc+1];
            __half* o0 = out + ((size_t)b*CH + oc)*PP;
            o0[prow]          = __float2half(acc[mi][ni][0] + bz0);
            o0[PP + prow]     = __float2half(acc[mi][ni][1] + bz1);
            o0[prow + 8]      = __float2half(acc[mi][ni][2] + bz0);
            o0[PP + prow + 8] = __float2half(acc[mi][ni][3] + bz1);
        }
    }
}

// ---------------- fp16 step GEMM (+optional fused LSTM epilogue) -------------
// block 64(M) x 128(N), 8 warps (2m x 4n), warp 32x32; K-iters of 32, 4-stage cp.async
// all lda/ldw fixed at 512 halfs. lstm mode when cout != nullptr.
#define GPITCH 20
#define GA_WORDS (64*GPITCH)
#define GB_WORDS (128*GPITCH)

__global__ void __launch_bounds__(256, 2) gemm16_kernel(
    __half* __restrict__ C16, int ldc,
    const __half* __restrict__ A1, const __half* __restrict__ W1, int K1,
    const __half* __restrict__ A2, const __half* __restrict__ W2, int K2,
    const float* __restrict__ bias, const float* __restrict__ Cadd, int ldadd,
    const float* __restrict__ Wgp, const int* __restrict__ textcol, int textstride,
    const float* __restrict__ cin, float* __restrict__ cout, __half* __restrict__ hout)
{
    extern __shared__ __align__(16) uint32_t sm[];
    uint32_t* Asm = sm;                  // [4][64][20]
    uint32_t* Bsm = sm + 4*GA_WORDS;     // [4][128][20]
    const int m0 = blockIdx.y * 64;
    const int n0 = blockIdx.x * 128;
    const int tid = threadIdx.x;
    const int lane = tid & 31, warp = tid >> 5;
    const int wm = (warp >> 2) * 32;
    const int wn = (warp & 3) * 32;
    const int gid = lane >> 2, tig = lane & 3;

    const int S1 = K1 >> 5;
    const int S2 = (A2 != nullptr) ? (K2 >> 5) : 0;
    const int S  = S1 + S2;

    float acc[2][4][4];
    #pragma unroll
    for (int i=0;i<2;i++)
      #pragma unroll
      for (int j=0;j<4;j++)
        #pragma unroll
        for (int k=0;k<4;k++) acc[i][j][k]=0.f;

    uint32_t sAb = (uint32_t)__cvta_generic_to_shared(Asm);
    uint32_t sBb = (uint32_t)__cvta_generic_to_shared(Bsm);

#define GLOAD(s) do { \
        int st_ = (s) & 3; int s_ = (s); \
        const __half* A_; const __half* W_; int k0_; \
        if (s_ < S1){ A_ = A1; W_ = W1; k0_ = s_ << 5; } \
        else        { A_ = A2; W_ = W2; k0_ = (s_ - S1) << 5; } \
        const __half* ap_ = A_ + (size_t)(m0 + (tid>>2))*512 + k0_ + (tid&3)*8; \
        uint32_t da_ = sAb + (uint32_t)(((st_*64 + (tid>>2))*GPITCH + (tid&3)*4)*4); \
        asm volatile("cp.async.ca.shared.global [%0], [%1], 16;" :: "r"(da_), "l"(ap_)); \
        const __half* bp_ = W_ + (size_t)(n0 + (tid>>1))*512 + k0_ + (tid&1)*16; \
        uint32_t db_ = sBb + (uint32_t)(((st_*128 + (tid>>1))*GPITCH + (tid&1)*8)*4); \
        asm volatile("cp.async.ca.shared.global [%0], [%1], 16;" :: "r"(db_),      "l"(bp_)); \
        asm volatile("cp.async.ca.shared.global [%0], [%1], 16;" :: "r"(db_ + 16), "l"(bp_ + 8)); \
        asm volatile("cp.async.commit_group;"); \
    } while(0)

    GLOAD(0); GLOAD(1); GLOAD(2);

    for (int s = 0; s < S; ++s){
        asm volatile("cp.async.wait_group 2;");
        __syncthreads();
        if (s + 3 < S) GLOAD(s + 3);

        const uint32_t* A_ = Asm + (s & 3) * GA_WORDS;
        const uint32_t* B_ = Bsm + (s & 3) * GB_WORDS;

        #pragma unroll
        for (int h = 0; h < 2; ++h){
            const int kb = h*8 + tig;
            uint32_t afr[2][4], bfr[4][2];
            #pragma unroll
            for (int mi=0; mi<2; ++mi){
                int rowb = wm + mi*16 + gid;
                afr[mi][0] = A_[rowb*GPITCH + kb];
                afr[mi][1] = A_[(rowb+8)*GPITCH + kb];
                afr[mi][2] = A_[rowb*GPITCH + kb + 4];
                afr[mi][3] = A_[(rowb+8)*GPITCH + kb + 4];
            }
            #pragma unroll
            for (int ni=0; ni<4; ++ni){
                int colb = wn + ni*8 + gid;
                bfr[ni][0] = B_[colb*GPITCH + kb];
                bfr[ni][1] = B_[colb*GPITCH + kb + 4];
            }
            #pragma unroll
            for (int mi=0; mi<2; ++mi)
                #pragma unroll
                for (int ni=0; ni<4; ++ni)
                    mma_fp16(acc[mi][ni], afr[mi], bfr[ni]);
        }
    }
#undef GLOAD

    #pragma unroll
    for (int mi=0; mi<2; ++mi){
        int m = m0 + wm + mi*16 + gid;
        int tc0 = 0, tc1 = 0;
        if (Wgp){ tc0 = textcol[m*textstride]; tc1 = textcol[(m+8)*textstride]; }
        #pragma unroll
        for (int ni=0; ni<4; ++ni){
            int n = n0 + wn + ni*8 + tig*2;
            float b0 = 0.f, b1 = 0.f;
            if (bias){ b0 = bias[n]; b1 = bias[n+1]; }
            float v00 = acc[mi][ni][0] + b0;
            float v01 = acc[mi][ni][1] + b1;
            float v10 = acc[mi][ni][2] + b0;
            float v11 = acc[mi][ni][3] + b1;
            if (Cadd){
                v00 += Cadd[(size_t)m*ldadd + n];     v01 += Cadd[(size_t)m*ldadd + n+1];
                v10 += Cadd[(size_t)(m+8)*ldadd + n]; v11 += Cadd[(size_t)(m+8)*ldadd + n+1];
            }
            if (Wgp){
                v00 += Wgp[n*NC + tc0];     v01 += Wgp[(n+1)*NC + tc0];
                v10 += Wgp[n*NC + tc1];     v11 += Wgp[(n+1)*NC + tc1];
            }
            if (cout){
                // lstm: even tig holds (i,f), odd holds (g,o) of same j
                float p00 = __shfl_xor_sync(0xffffffffu, v00, 1);
                float p01 = __shfl_xor_sync(0xffffffffu, v01, 1);
                float p10 = __shfl_xor_sync(0xffffffffu, v10, 1);
                float p11 = __shfl_xor_sync(0xffffffffu, v11, 1);
                if ((tig & 1) == 0){
                    int j = n >> 2;
                    float c2a = fsigm(v01)*cin[(size_t)m*HS + j] + fsigm(v00)*ftanh(p00);
                    cout[(size_t)m*HS + j] = c2a;
                    hout[(size_t)m*HS + j] = __float2half(fsigm(p01)*ftanh(c2a));
                    float c2b = fsigm(v11)*cin[(size_t)(m+8)*HS + j] + fsigm(v10)*ftanh(p10);
                    cout[(size_t)(m+8)*HS + j] = c2b;
                    hout[(size_t)(m+8)*HS + j] = __float2half(fsigm(p11)*ftanh(c2b));
                }
            } else {
                C16[(size_t)m*ldc + n]       = __float2half(v00);
                C16[(size_t)m*ldc + n+1]     = __float2half(v01);
                C16[(size_t)(m+8)*ldc + n]   = __float2half(v10);
                C16[(size_t)(m+8)*ldc + n+1] = __float2half(v11);
            }
        }
    }
}

// ---------------- fp32 SIMT GEMM (prologue) ----------------------------------
__global__ void gemm_kernel(
    float* __restrict__ C, int ldc,
    const float* __restrict__ A1, int lda1, const float* __restrict__ W1, int ldw1, int K1,
    const float* __restrict__ bias1,
    const float* __restrict__ Cadd, int ldadd,
    int nn, int M, int N)
{
    __shared__ float As[16][68];
    __shared__ float Bs[16][68];
    int m0 = blockIdx.y * 64;
    int n0 = blockIdx.x * 64;
    int tid = threadIdx.x;
    int tx = tid & 15, ty = tid >> 4;

    float acc[4][4];
    #pragma unroll
    for (int i=0;i<4;i++)
        #pragma unroll
        for (int j=0;j<4;j++) acc[i][j]=0.f;

    for (int k0=0; k0<K1; k0+=16){
        #pragma unroll
        for (int i=0;i<4;i++){
            int e = i*256 + tid;
            int m = e >> 4, kk = e & 15;
            int gm = m0 + m, gk = k0 + kk;
            As[kk][m] = (gm < M && gk < K1) ? A1[(size_t)gm*lda1 + gk] : 0.f;
        }
        if (nn){
            #pragma unroll
            for (int i=0;i<4;i++){
                int e = i*256 + tid;
                int kk = e >> 6, n = e & 63;
                int gn = n0 + n, gk = k0 + kk;
                Bs[kk][n] = (gn < N && gk < K1) ? W1[(size_t)gk*ldw1 + gn] : 0.f;
            }
        } else {
            #pragma unroll
            for (int i=0;i<4;i++){
                int e = i*256 + tid;
                int n = e >> 4, kk = e & 15;
                int gn = n0 + n, gk = k0 + kk;
                Bs[kk][n] = (gn < N && gk < K1) ? W1[(size_t)gn*ldw1 + gk] : 0.f;
            }
        }
        __syncthreads();
        #pragma unroll
        for (int kk=0; kk<16; kk++){
            float4 a = *(const float4*)&As[kk][ty*4];
            float4 b = *(const float4*)&Bs[kk][tx*4];
            acc[0][0]+=a.x*b.x; acc[0][1]+=a.x*b.y; acc[0][2]+=a.x*b.z; acc[0][3]+=a.x*b.w;
            acc[1][0]+=a.y*b.x; acc[1][1]+=a.y*b.y; acc[1][2]+=a.y*b.z; acc[1][3]+=a.y*b.w;
            acc[2][0]+=a.z*b.x; acc[2][1]+=a.z*b.y; acc[2][2]+=a.z*b.z; acc[2][3]+=a.z*b.w;
            acc[3][0]+=a.w*b.x; acc[3][1]+=a.w*b.y; acc[3][2]+=a.w*b.z; acc[3][3]+=a.w*b.w;
        }
        __syncthreads();
    }

    #pragma unroll
    for (int i=0;i<4;i++){
        int m = m0 + ty*4 + i;
        if (m >= M) continue;
        #pragma unroll
        for (int j=0;j<4;j++){
            int n = n0 + tx*4 + j;
            if (n >= N) continue;
            float v = acc[i][j];
            if (bias1) v += bias1[n];
            if (Cadd)  v += Cadd[(size_t)m*ldadd + n];
            C[(size_t)m*ldc + n] = v;
        }
    }
}

// ---------------- generator GEMM (fp16 A, fp32 W), remapped output ----------
__global__ void gen_kernel(
    float* __restrict__ C,
    const __half* __restrict__ A1, const float* __restrict__ W1,
    const float* __restrict__ bias1, int M, int N)
{
    __shared__ float As[16][68];
    __shared__ float Bs[16][68];
    int m0 = blockIdx.y * 64;
    int tid = threadIdx.x;
    int tx = tid & 15, ty = tid >> 4;

    float acc[4][4];
    #pragma unroll
    for (int i=0;i<4;i++)
        #pragma unroll
        for (int j=0;j<4;j++) acc[i][j]=0.f;

    for (int k0=0; k0<HS; k0+=16){
        #pragma unroll
        for (int i=0;i<4;i++){
            int e = i*256 + tid;
            int m = e >> 4, kk = e & 15;
            int gm = m0 + m, gk = k0 + kk;
            As[kk][m] = (gm < M) ? __half2float(A1[(size_t)gm*HS + gk]) : 0.f;
        }
        #pragma unroll
        for (int i=0;i<4;i++){
            int e = i*256 + tid;
            int n = e >> 4, kk = e & 15;
            int gk = k0 + kk;
            Bs[kk][n] = (n < N) ? W1[(size_t)n*HS + gk] : 0.f;
        }
        __syncthreads();
        #pragma unroll
        for (int kk=0; kk<16; kk++){
            float4 a = *(const float4*)&As[kk][ty*4];
            float4 b = *(const float4*)&Bs[kk][tx*4];
            acc[0][0]+=a.x*b.x; acc[0][1]+=a.x*b.y; acc[0][2]+=a.x*b.z; acc[0][3]+=a.x*b.w;
            acc[1][0]+=a.y*b.x; acc[1][1]+=a.y*b.y; acc[1][2]+=a.y*b.z; acc[1][3]+=a.y*b.w;
            acc[2][0]+=a.z*b.x; acc[2][1]+=a.z*b.y; acc[2][2]+=a.z*b.z; acc[2][3]+=a.z*b.w;
            acc[3][0]+=a.w*b.x; acc[3][1]+=a.w*b.y; acc[3][2]+=a.w*b.z; acc[3][3]+=a.w*b.w;
        }
        __syncthreads();
    }

    #pragma unroll
    for (int i=0;i<4;i++){
        int m = m0 + ty*4 + i;
        if (m >= M) continue;
        int t = m >> 8, b = m & 255;
        #pragma unroll
        for (int j=0;j<4;j++){
            int n = tx*4 + j;
            if (n >= N) continue;
            C[(size_t)(b*TT + t)*NC + n] = acc[i][j] + bias1[n];
        }
    }
}

// ---------------- mean over T of batch_H ------------------------------------
__global__ void mean_kernel(const float* __restrict__ bH, float* __restrict__ out)
{
    int idx = blockIdx.x*256 + threadIdx.x;
    if (idx >= BB*INSZ) return;
    int b = idx >> 9, k = idx & 511;
    const float* p = bH + (size_t)b*TT*INSZ + k;
    float s = 0.f;
    #pragma unroll
    for (int t=0;t<TT;t++) s += p[t*INSZ];
    out[idx] = s * (1.0f/26.0f);
}

// ---------------- init h0/c0 -------------------------------------------------
__global__ void init_kernel(const float* __restrict__ hh, const float* __restrict__ hc,
                            __half* __restrict__ h1, __half* __restrict__ h2,
                            float* __restrict__ c1, float* __restrict__ c2)
{
    int idx = blockIdx.x*256 + threadIdx.x;
    if (idx >= BB*HS) return;
    float h0 = 0.5f*(hh[idx] + hh[BB*HS + idx]);
    float c0 = 0.5f*(hc[idx] + hc[BB*HS + idx]);
    h1[idx] = __float2half(h0); h2[idx] = __float2half(h0);
    c1[idx]=c0; c2[idx]=c0;
}

// ---------------- attention: e -> softmax -> context (fp16 fmh/q/ctx) --------
__global__ void attn_kernel(const __half* __restrict__ fmh, const __half* __restrict__ q,
                            const float* __restrict__ ws, const float* __restrict__ sb,
                            __half* __restrict__ ctx)
{
    __shared__ float qs[CH];
    __shared__ float wss[CH];
    __shared__ float red[256];
    __shared__ float alpha[256];

    int b = blockIdx.x;
    int p = threadIdx.x;
    const __half* f = fmh + (size_t)b * CH * PP;

    qs[p]       = __half2float(q[b*HS + p]);
    qs[p+256]   = __half2float(q[b*HS + p + 256]);
    wss[p]      = ws[p];
    wss[p+256]  = ws[p+256];
    __syncthreads();

    float acc = 0.f;
    #pragma unroll 4
    for (int c=0; c<CH; c++){
        acc += ftanh(__half2float(f[c*PP + p]) + qs[c]) * wss[c];
    }
    float e = acc + sb[0];

    red[p] = e; __syncthreads();
    #pragma unroll
    for (int s=128; s>0; s>>=1){
        if (p < s) red[p] = fmaxf(red[p], red[p+s]);
        __syncthreads();
    }
    float mx = red[0];
    __syncthreads();
    float ex = fexp(e - mx);
    red[p] = ex; __syncthreads();
    #pragma unroll
    for (int s=128; s>0; s>>=1){
        if (p < s) red[p] += red[p+s];
        __syncthreads();
    }
    float sum = red[0];
    __syncthreads();
    alpha[p] = ex * frcp(sum);
    __syncthreads();

    int lane = p & 31, wid = p >> 5;
    for (int c = wid; c < CH; c += 8){
        const __half* fr = f + c*PP;
        float s = 0.f;
        #pragma unroll
        for (int pp = lane; pp < PP; pp += 32) s += alpha[pp] * __half2float(fr[pp]);
        #pragma unroll
        for (int o=16; o>0; o>>=1) s += __shfl_down_sync(0xffffffffu, s, o);
        if (lane == 0) ctx[b*HS + c] = __float2half(s);
    }
}

// ---------------- host orchestration ----------------------------------------
extern "C" void kernel_launch(void* const* d_in, const int* in_sizes, int n_in,
                              void* d_out, int out_size)
{
    const float* feature_map = (const float*)d_in[0];
    const float* batch_H     = (const float*)d_in[1];
    const float* hidden_h    = (const float*)d_in[2];
    const float* hidden_c    = (const float*)d_in[3];
    const int*   text        = (const int*)  d_in[4];
    const float* i2h_w       = (const float*)d_in[5];
    const float* h2h_w       = (const float*)d_in[6];
    const float* h2h_b       = (const float*)d_in[7];
    const float* conv_m2h_w  = (const float*)d_in[8];
    const float* conv_m2h_b  = (const float*)d_in[9];
    const float* conv_h2h_w  = (const float*)d_in[10];
    const float* conv_h2h_b  = (const float*)d_in[11];
    const float* score_w     = (const float*)d_in[12];
    const float* score_b     = (const float*)d_in[13];
    const float* rnn1_w_ih   = (const float*)d_in[14];
    const float* rnn1_w_hh   = (const float*)d_in[15];
    const float* rnn1_b_ih   = (const float*)d_in[16];
    const float* rnn1_b_hh   = (const float*)d_in[17];
    const float* hlin_w      = (const float*)d_in[18];
    const float* hlin_b      = (const float*)d_in[19];
    const float* rnn2_w_ih   = (const float*)d_in[20];
    const float* rnn2_w_hh   = (const float*)d_in[21];
    const float* rnn2_b_ih   = (const float*)d_in[22];
    const float* rnn2_b_hh   = (const float*)d_in[23];
    const float* gen_w       = (const float*)d_in[24];
    const float* gen_b       = (const float*)d_in[25];
    float* out = (float*)d_out;

    __half *ahT,*bhT,*fmh,*Wq16,*hlin16,*w1ih16,*w1hh16,*w2ih16,*w2hh16;
    __half *h1a16,*h1b16,*h2a16,*hist16,*q16,*ctx16,*cur16;
    float *meanH,*bhproj,*Wq,*qb,*bias1p,*bias2p,*wgp;
    float *c1a,*c1b,*c2a,*c2b;
    cudaGetSymbolAddress((void**)&ahT, g_ahT);
    cudaGetSymbolAddress((void**)&bhT, g_bhT);
    cudaGetSymbolAddress((void**)&fmh, g_fmh);
    cudaGetSymbolAddress((void**)&meanH, g_meanH);
    cudaGetSymbolAddress((void**)&bhproj,g_bhproj);
    cudaGetSymbolAddress((void**)&Wq,    g_Wq);
    cudaGetSymbolAddress((void**)&qb,    g_qb);
    cudaGetSymbolAddress((void**)&Wq16,  g_Wq16);
    cudaGetSymbolAddress((void**)&hlin16,g_hlin16);
    cudaGetSymbolAddress((void**)&w1ih16,g_w1ih16);
    cudaGetSymbolAddress((void**)&w1hh16,g_w1hh16);
    cudaGetSymbolAddress((void**)&w2ih16,g_w2ih16);
    cudaGetSymbolAddress((void**)&w2hh16,g_w2hh16);
    cudaGetSymbolAddress((void**)&bias1p,g_bias1p);
    cudaGetSymbolAddress((void**)&bias2p,g_bias2p);
    cudaGetSymbolAddress((void**)&wgp,   g_wgp);
    cudaGetSymbolAddress((void**)&h1a16, g_h1a16);
    cudaGetSymbolAddress((void**)&h1b16, g_h1b16);
    cudaGetSymbolAddress((void**)&h2a16, g_h2a16);
    cudaGetSymbolAddress((void**)&c1a, g_c1a); cudaGetSymbolAddress((void**)&c1b, g_c1b);
    cudaGetSymbolAddress((void**)&c2a, g_c2a); cudaGetSymbolAddress((void**)&c2b, g_c2b);
    cudaGetSymbolAddress((void**)&hist16, g_hist16);
    cudaGetSymbolAddress((void**)&q16,  g_q16);
    cudaGetSymbolAddress((void**)&ctx16,g_ctx16);
    cudaGetSymbolAddress((void**)&cur16,g_cur16);

    // ---- conv prep + conv ----
    const int CONV_SMEM = 2 * 4 * 128 * CPITCH * 4;   // 81920
    cudaFuncSetAttribute(conv_fp16_kernel, cudaFuncAttributeMaxDynamicSharedMemorySize, CONV_SMEM);
    const int G16_SMEM = 4 * (GA_WORDS + GB_WORDS) * 4;  // 61440
    cudaFuncSetAttribute(gemm16_kernel, cudaFuncAttributeMaxDynamicSharedMemorySize, G16_SMEM);

    padT_kernel<<<256*10*16, 256>>>(feature_map, ahT);
    wT_kernel<<<(9*CH*CH+255)/256, 256>>>(conv_m2h_w, bhT);
    conv_fp16_kernel<<<dim3(4,2,BB), 256, CONV_SMEM>>>(ahT, bhT, conv_m2h_b, fmh);

    // ---- weight packing (fp16) ----
    wpack16_kernel<<<(4*HS*512+255)/256,256>>>(rnn1_w_ih, INSZ+NC, w1ih16);
    wpack16_kernel<<<(4*HS*512+255)/256,256>>>(rnn1_w_hh, HS, w1hh16);
    wpack16_kernel<<<(4*HS*512+255)/256,256>>>(rnn2_w_ih, HS, w2ih16);
    wpack16_kernel<<<(4*HS*512+255)/256,256>>>(rnn2_w_hh, HS, w2hh16);
    bpack_kernel<<<(4*HS+255)/256,256>>>(rnn1_b_ih, rnn1_b_hh, bias1p);
    bpack_kernel<<<(4*HS+255)/256,256>>>(rnn2_b_ih, rnn2_b_hh, bias2p);
    wgpack_kernel<<<(4*HS*NC+255)/256,256>>>(rnn1_w_ih, wgp);
    cast16_kernel<<<(HS*HS+255)/256,256>>>(hlin_w, hlin16, HS*HS);

    // ---- prologue (fp32) ----
    mean_kernel<<<512,256>>>(batch_H, meanH);
    gemm_kernel<<<dim3(8,4),256>>>(bhproj, HS, meanH, INSZ, i2h_w, INSZ, INSZ,
                                   h2h_b, nullptr,0, 0, BB, HS);
    gemm_kernel<<<dim3(8,8),256>>>(Wq, HS, conv_h2h_w, HS, h2h_w, HS, HS,
                                   nullptr, nullptr,0, 1, HS, HS);
    cast16_kernel<<<(HS*HS+255)/256,256>>>(Wq, Wq16, HS*HS);
    gemm_kernel<<<dim3(8,4),256>>>(qb, HS, bhproj, HS, conv_h2h_w, HS, HS,
                                   conv_h2h_b, nullptr,0, 0, BB, HS);
    init_kernel<<<512,256>>>(hidden_h, hidden_c, h1a16, h2a16, c1a, c2a);

    __half *h1c16=h1a16, *h1n16=h1b16, *h2c16=h2a16;
    float *c1c=c1a, *c1n=c1b, *c2c=c2a, *c2n=c2b;

    for (int t=0; t<TT; t++){
        __half* h2n16 = hist16 + (size_t)t*BB*HS;
        // q = qb + h2 @ Wq^T  (fp16 out)
        gemm16_kernel<<<dim3(4,4),256,G16_SMEM>>>(q16, HS,
            h2c16, Wq16, HS, nullptr, nullptr, 0,
            nullptr, qb, HS, nullptr, nullptr, 0,
            nullptr, nullptr, nullptr);
        // attention -> ctx (fp16)
        attn_kernel<<<BB,256>>>(fmh, q16, score_w, score_b, ctx16);
        // gates1 + fused LSTM1
        gemm16_kernel<<<dim3(16,4),256,G16_SMEM>>>(nullptr, 0,
            ctx16, w1ih16, HS, h1c16, w1hh16, HS,
            bias1p, nullptr, 0, wgp, text + t, TT,
            c1c, c1n, h1n16);
        // cur = h1n @ hlin^T + hlin_b (fp16 out)
        gemm16_kernel<<<dim3(4,4),256,G16_SMEM>>>(cur16, HS,
            h1n16, hlin16, HS, nullptr, nullptr, 0,
            hlin_b, nullptr, 0, nullptr, nullptr, 0,
            nullptr, nullptr, nullptr);
        // gates2 + fused LSTM2 (h2 out -> hist slot)
        gemm16_kernel<<<dim3(16,4),256,G16_SMEM>>>(nullptr, 0,
            cur16, w2ih16, HS, h2c16, w2hh16, HS,
            bias2p, nullptr, 0, nullptr, nullptr, 0,
            c2c, c2n, h2n16);

        __half* tph;
        tph=h1c16; h1c16=h1n16; h1n16=tph;
        h2c16 = h2n16;
        float* tp;
        tp=c1c; c1c=c1n; c1n=tp;
        tp=c2c; c2c=c2n; c2n=tp;
    }

    // probs: one batched GEMM over all timesteps (fp16 hist), remap [b][t][n]
    gen_kernel<<<dim3(1,104),256>>>(out, hist16, gen_w, gen_b, TT*BB, NC);
}

// round 10
// speedup vs baseline: 4.1493x; 1.0389x over previous
#include <cuda_runtime.h>
#include <cuda_fp16.h>
#include <math.h>
#include <stdint.h>

#define BB 256
#define HS 512
#define INSZ 512
#define NC 38
#define TT 26
#define CH 512
#define PP 256   /* 8*32 */

// ---------------- scratch (device globals; no allocation allowed) ----------
__device__ __align__(16) __half g_ahT[(size_t)3*BB*320*CH]; // padded input, [kw][b][pos320][ic]
__device__ __align__(16) __half g_bhT[9*CH*CH];             // conv weights [khw][oc][ic]
__device__ __align__(16) __half g_fmh[(size_t)BB*CH*PP];    // conv output fp16, 67MB
__device__ float g_meanH[BB*INSZ];
__device__ float g_bhproj[BB*HS];
__device__ float g_Wq[HS*HS];
__device__ float g_qb[BB*HS];
__device__ float g_W2p[4*HS*HS];                       // w2ih @ hlin (fp32)
__device__ float g_badd[4*HS];                         // w2ih @ hlin_b
// fp16 packed loop weights
__device__ __align__(16) __half g_Wq16[HS*HS];
__device__ __align__(16) __half g_w1ih16[4*HS*INSZ];   // row 4j+g
__device__ __align__(16) __half g_w1hh16[4*HS*HS];
__device__ __align__(16) __half g_w2ih16[4*HS*HS];     // folded (w2ih@hlin)
__device__ __align__(16) __half g_w2hh16[4*HS*HS];
__device__ float g_bias1p[4*HS], g_bias2p[4*HS];
__device__ float g_wgp[4*HS*NC];                       // onehot gather, packed rows
// states
__device__ __align__(16) __half g_h1a16[BB*HS], g_h1b16[BB*HS], g_h2a16[BB*HS];
__device__ float g_c1a[BB*HS], g_c1b[BB*HS], g_c2a[BB*HS], g_c2b[BB*HS];
__device__ __align__(16) __half g_hist16[(size_t)TT*BB*HS];
__device__ __align__(16) __half g_q16[BB*HS];
__device__ __align__(16) __half g_ctx16[BB*HS];

// ---------------- fast math ------------------------------------------------
__device__ __forceinline__ float fexp(float x){
    float y; asm("ex2.approx.f32 %0, %1;" : "=f"(y) : "f"(x*1.4426950408889634f)); return y;
}
__device__ __forceinline__ float frcp(float x){
    float y; asm("rcp.approx.f32 %0, %1;" : "=f"(y) : "f"(x)); return y;
}
__device__ __forceinline__ float ftanh(float x){
    float xc = fminf(fmaxf(x, -15.f), 15.f);
    float t = fexp(2.f*xc);
    return (t - 1.f) * frcp(t + 1.f);
}
__device__ __forceinline__ float fsigm(float x){
    return frcp(1.f + fexp(-x));
}
__device__ __forceinline__ void mma_fp16(float* d, const uint32_t* a, const uint32_t* b){
    asm volatile(
      "mma.sync.aligned.m16n8k16.row.col.f32.f16.f16.f32 "
      "{%0,%1,%2,%3},{%4,%5,%6,%7},{%8,%9},{%0,%1,%2,%3};"
      : "+f"(d[0]),"+f"(d[1]),"+f"(d[2]),"+f"(d[3])
      : "r"(a[0]),"r"(a[1]),"r"(a[2]),"r"(a[3]), "r"(b[0]),"r"(b[1]));
}

// ---------------- prep kernels ------------------------------------------------
__global__ void padT_kernel(const float* __restrict__ in, __half* __restrict__ oh)
{
    __shared__ float s[32][33];
    int blk = blockIdx.x;
    int icb = blk & 15;
    int rr  = (blk >> 4) % 10;
    int b   = blk >> 4; b /= 10;
    int t = threadIdx.x;
    int r = rr - 1;

    if ((unsigned)r < 8u){
        int c = t & 31, icq = t >> 5;
        #pragma unroll
        for (int j=0;j<4;j++){
            int ic = icq + j*8;
            s[ic][c] = in[((size_t)b*CH + icb*32 + ic)*PP + r*32 + c];
        }
    }
    __syncthreads();

    int icl = t & 31, cq = t >> 5;
    #pragma unroll
    for (int j=0;j<4;j++){
        int c = cq + j*8;
        #pragma unroll
        for (int kw=0; kw<3; kw++){
            int cc = c + kw - 1;
            float v = 0.f;
            if ((unsigned)r < 8u && (unsigned)cc < 32u) v = s[icl][cc];
            size_t off = (((size_t)kw*BB + b)*320 + rr*32 + c)*CH + icb*32 + icl;
            oh[off] = __float2half(v);
        }
    }
}

__global__ void wT_kernel(const float* __restrict__ w, __half* __restrict__ oh)
{
    int idx = blockIdx.x*256 + threadIdx.x;
    if (idx >= 9*CH*CH) return;
    int ic = idx & 511;
    int oc = (idx >> 9) & 511;
    int khw = idx >> 18;
    oh[((size_t)khw*CH + oc)*CH + ic] = __float2half(w[((size_t)oc*CH + ic)*9 + khw]);
}

__global__ void cast16_kernel(const float* __restrict__ in, __half* __restrict__ out, int n)
{
    int idx = blockIdx.x*256 + threadIdx.x;
    if (idx < n) out[idx] = __float2half(in[idx]);
}

// interleave-pack gate weights: out[(4j+g)*512 + k] = w[(g*512+j)*ldw + k]
__global__ void wpack16_kernel(const float* __restrict__ w, int ldw, __half* __restrict__ out)
{
    int idx = blockIdx.x*256 + threadIdx.x;
    if (idx >= 4*HS*512) return;
    int k = idx & 511;
    int row = idx >> 9;
    int j = row >> 2, g = row & 3;
    out[idx] = __float2half(w[(size_t)(g*HS + j)*ldw + k]);
}

__global__ void bpack_kernel(const float* __restrict__ bih, const float* __restrict__ bhh,
                             const float* __restrict__ badd, float* __restrict__ out)
{
    int row = blockIdx.x*256 + threadIdx.x;
    if (row >= 4*HS) return;
    int j = row >> 2, g = row & 3;
    float v = bih[g*HS + j] + bhh[g*HS + j];
    if (badd) v += badd[g*HS + j];
    out[row] = v;
}

__global__ void wgpack_kernel(const float* __restrict__ w, float* __restrict__ out)
{
    int idx = blockIdx.x*256 + threadIdx.x;
    if (idx >= 4*HS*NC) return;
    int c = idx % NC;
    int row = idx / NC;
    int j = row >> 2, g = row & 3;
    out[idx] = w[(size_t)(g*HS + j)*(INSZ+NC) + INSZ + c];
}

// badd[m] = sum_k w2ih[m,k] * hlin_b[k]
__global__ void badd_kernel(const float* __restrict__ w2ih, const float* __restrict__ hlinb,
                            float* __restrict__ out)
{
    int m = blockIdx.x*256 + threadIdx.x;
    if (m >= 4*HS) return;
    const float* wr = w2ih + (size_t)m*HS;
    float s = 0.f;
    #pragma unroll 8
    for (int k=0;k<HS;k++) s += wr[k]*hlinb[k];
    out[m] = s;
}

// ---------------- conv 3x3 SAME via fp16 mma, 4-stage cp.async ---------------
#define CPITCH 20
#define CSTAGE_W (128*CPITCH)

__global__ void __launch_bounds__(256, 2) conv_fp16_kernel(
    const __half* __restrict__ Ag, const __half* __restrict__ Bg,
    const float* __restrict__ bias, __half* __restrict__ out)
{
    extern __shared__ __align__(16) uint32_t sm[];
    uint32_t* Asm = sm;
    uint32_t* Bsm = sm + 4*CSTAGE_W;
    const int b  = blockIdx.z;
    const int m0 = blockIdx.y * 128;
    const int n0 = blockIdx.x * 128;
    const int tid = threadIdx.x;
    const int lane = tid & 31, warp = tid >> 5;
    const int wm = (warp >> 2) * 64;
    const int wn = (warp & 3) * 32;
    const int gid = lane >> 2, tig = lane & 3;

    const int lrow = tid >> 1;
    const int lch  = tid & 1;

    float acc[4][4][4];
    #pragma unroll
    for (int i=0;i<4;i++)
      #pragma unroll
      for (int j=0;j<4;j++)
        #pragma unroll
        for (int k=0;k<4;k++) acc[i][j][k]=0.f;

    uint32_t sAb = (uint32_t)__cvta_generic_to_shared(Asm);
    uint32_t sBb = (uint32_t)__cvta_generic_to_shared(Bsm);

#define CLOAD(s) do { \
        int st_  = (s) & 3; \
        int khw_ = (s) >> 4; \
        int ic0_ = ((s) & 15) << 5; \
        int kh_ = khw_ / 3, kw_ = khw_ - kh_*3; \
        const __half* ap_ = Ag + (((size_t)kw_*BB + b)*320 + m0 + kh_*32 + lrow)*CH + ic0_ + lch*8; \
        const __half* bp_ = Bg + ((size_t)khw_*CH + n0 + lrow)*CH + ic0_ + lch*8; \
        uint32_t da_ = sAb + (uint32_t)(((st_*128 + lrow)*CPITCH + lch*4)*4); \
        uint32_t db_ = sBb + (uint32_t)(((st_*128 + lrow)*CPITCH + lch*4)*4); \
        asm volatile("cp.async.ca.shared.global [%0], [%1], 16;" :: "r"(da_),      "l"(ap_)); \
        asm volatile("cp.async.ca.shared.global [%0], [%1], 16;" :: "r"(da_ + 32), "l"(ap_ + 16)); \
        asm volatile("cp.async.ca.shared.global [%0], [%1], 16;" :: "r"(db_),      "l"(bp_)); \
        asm volatile("cp.async.ca.shared.global [%0], [%1], 16;" :: "r"(db_ + 32), "l"(bp_ + 16)); \
        asm volatile("cp.async.commit_group;"); \
    } while(0)

    CLOAD(0); CLOAD(1); CLOAD(2);

    for (int s = 0; s < 144; ++s){
        asm volatile("cp.async.wait_group 2;");
        __syncthreads();
        if (s + 3 < 144) CLOAD(s + 3);

        const uint32_t* A_ = Asm + (s & 3) * CSTAGE_W;
        const uint32_t* B_ = Bsm + (s & 3) * CSTAGE_W;

        #pragma unroll
        for (int h = 0; h < 2; ++h){
            const int kb = h*8 + tig;
            uint32_t afr[4][4], bfr[4][2];
            #pragma unroll
            for (int mi=0; mi<4; ++mi){
                int rowb = wm + mi*16 + gid;
                afr[mi][0] = A_[rowb*CPITCH + kb];
                afr[mi][1] = A_[(rowb+8)*CPITCH + kb];
                afr[mi][2] = A_[rowb*CPITCH + kb + 4];
                afr[mi][3] = A_[(rowb+8)*CPITCH + kb + 4];
            }
            #pragma unroll
            for (int ni=0; ni<4; ++ni){
                int colb = wn + ni*8 + gid;
                bfr[ni][0] = B_[colb*CPITCH + kb];
                bfr[ni][1] = B_[colb*CPITCH + kb + 4];
            }
            #pragma unroll
            for (int mi=0; mi<4; ++mi)
                #pragma unroll
                for (int ni=0; ni<4; ++ni)
                    mma_fp16(acc[mi][ni], afr[mi], bfr[ni]);
        }
    }
#undef CLOAD

    #pragma unroll
    for (int mi=0; mi<4; ++mi){
        int prow = m0 + wm + mi*16 + gid;
        #pragma unroll
        for (int ni=0; ni<4; ++ni){
            int oc = n0 + wn + ni*8 + tig*2;
            float bz0 = bias[oc], bz1 = bias[oc+1];
            __half* o0 = out + ((size_t)b*CH + oc)*PP;
            o0[prow]          = __float2half(acc[mi][ni][0] + bz0);
            o0[PP + prow]     = __float2half(acc[mi][ni][1] + bz1);
            o0[prow + 8]      = __float2half(acc[mi][ni][2] + bz0);
            o0[PP + prow + 8] = __float2half(acc[mi][ni][3] + bz1);
        }
    }
}

// ---------------- fp16 step GEMM (+optional fused LSTM epilogue) -------------
#define GPITCH 20
#define GA_WORDS (64*GPITCH)
#define GB_WORDS (128*GPITCH)

__global__ void __launch_bounds__(256, 2) gemm16_kernel(
    __half* __restrict__ C16, int ldc,
    const __half* __restrict__ A1, const __half* __restrict__ W1, int K1,
    const __half* __restrict__ A2, const __half* __restrict__ W2, int K2,
    const float* __restrict__ bias, const float* __restrict__ Cadd, int ldadd,
    const float* __restrict__ Wgp, const int* __restrict__ textcol, int textstride,
    const float* __restrict__ cin, float* __restrict__ cout, __half* __restrict__ hout)
{
    extern __shared__ __align__(16) uint32_t sm[];
    uint32_t* Asm = sm;                  // [4][64][20]
    uint32_t* Bsm = sm + 4*GA_WORDS;     // [4][128][20]
    const int m0 = blockIdx.y * 64;
    const int n0 = blockIdx.x * 128;
    const int tid = threadIdx.x;
    const int lane = tid & 31, warp = tid >> 5;
    const int wm = (warp >> 2) * 32;
    const int wn = (warp & 3) * 32;
    const int gid = lane >> 2, tig = lane & 3;

    const int S1 = K1 >> 5;
    const int S2 = (A2 != nullptr) ? (K2 >> 5) : 0;
    const int S  = S1 + S2;

    float acc[2][4][4];
    #pragma unroll
    for (int i=0;i<2;i++)
      #pragma unroll
      for (int j=0;j<4;j++)
        #pragma unroll
        for (int k=0;k<4;k++) acc[i][j][k]=0.f;

    uint32_t sAb = (uint32_t)__cvta_generic_to_shared(Asm);
    uint32_t sBb = (uint32_t)__cvta_generic_to_shared(Bsm);

#define GLOAD(s) do { \
        int st_ = (s) & 3; int s_ = (s); \
        const __half* A_; const __half* W_; int k0_; \
        if (s_ < S1){ A_ = A1; W_ = W1; k0_ = s_ << 5; } \
        else        { A_ = A2; W_ = W2; k0_ = (s_ - S1) << 5; } \
        const __half* ap_ = A_ + (size_t)(m0 + (tid>>2))*512 + k0_ + (tid&3)*8; \
        uint32_t da_ = sAb + (uint32_t)(((st_*64 + (tid>>2))*GPITCH + (tid&3)*4)*4); \
        asm volatile("cp.async.ca.shared.global [%0], [%1], 16;" :: "r"(da_), "l"(ap_)); \
        const __half* bp_ = W_ + (size_t)(n0 + (tid>>1))*512 + k0_ + (tid&1)*16; \
        uint32_t db_ = sBb + (uint32_t)(((st_*128 + (tid>>1))*GPITCH + (tid&1)*8)*4); \
        asm volatile("cp.async.ca.shared.global [%0], [%1], 16;" :: "r"(db_),      "l"(bp_)); \
        asm volatile("cp.async.ca.shared.global [%0], [%1], 16;" :: "r"(db_ + 16), "l"(bp_ + 8)); \
        asm volatile("cp.async.commit_group;"); \
    } while(0)

    GLOAD(0); GLOAD(1); GLOAD(2);

    for (int s = 0; s < S; ++s){
        asm volatile("cp.async.wait_group 2;");
        __syncthreads();
        if (s + 3 < S) GLOAD(s + 3);

        const uint32_t* A_ = Asm + (s & 3) * GA_WORDS;
        const uint32_t* B_ = Bsm + (s & 3) * GB_WORDS;

        #pragma unroll
        for (int h = 0; h < 2; ++h){
            const int kb = h*8 + tig;
            uint32_t afr[2][4], bfr[4][2];
            #pragma unroll
            for (int mi=0; mi<2; ++mi){
                int rowb = wm + mi*16 + gid;
                afr[mi][0] = A_[rowb*GPITCH + kb];
                afr[mi][1] = A_[(rowb+8)*GPITCH + kb];
                afr[mi][2] = A_[rowb*GPITCH + kb + 4];
                afr[mi][3] = A_[(rowb+8)*GPITCH + kb + 4];
            }
            #pragma unroll
            for (int ni=0; ni<4; ++ni){
                int colb = wn + ni*8 + gid;
                bfr[ni][0] = B_[colb*GPITCH + kb];
                bfr[ni][1] = B_[colb*GPITCH + kb + 4];
            }
            #pragma unroll
            for (int mi=0; mi<2; ++mi)
                #pragma unroll
                for (int ni=0; ni<4; ++ni)
                    mma_fp16(acc[mi][ni], afr[mi], bfr[ni]);
        }
    }
#undef GLOAD

    #pragma unroll
    for (int mi=0; mi<2; ++mi){
        int m = m0 + wm + mi*16 + gid;
        int tc0 = 0, tc1 = 0;
        if (Wgp){ tc0 = textcol[m*textstride]; tc1 = textcol[(m+8)*textstride]; }
        #pragma unroll
        for (int ni=0; ni<4; ++ni){
            int n = n0 + wn + ni*8 + tig*2;
            float b0 = 0.f, b1 = 0.f;
            if (bias){ b0 = bias[n]; b1 = bias[n+1]; }
            float v00 = acc[mi][ni][0] + b0;
            float v01 = acc[mi][ni][1] + b1;
            float v10 = acc[mi][ni][2] + b0;
            float v11 = acc[mi][ni][3] + b1;
            if (Cadd){
                v00 += Cadd[(size_t)m*ldadd + n];     v01 += Cadd[(size_t)m*ldadd + n+1];
                v10 += Cadd[(size_t)(m+8)*ldadd + n]; v11 += Cadd[(size_t)(m+8)*ldadd + n+1];
            }
            if (Wgp){
                v00 += Wgp[n*NC + tc0];     v01 += Wgp[(n+1)*NC + tc0];
                v10 += Wgp[n*NC + tc1];     v11 += Wgp[(n+1)*NC + tc1];
            }
            if (cout){
                float p00 = __shfl_xor_sync(0xffffffffu, v00, 1);
                float p01 = __shfl_xor_sync(0xffffffffu, v01, 1);
                float p10 = __shfl_xor_sync(0xffffffffu, v10, 1);
                float p11 = __shfl_xor_sync(0xffffffffu, v11, 1);
                if ((tig & 1) == 0){
                    int j = n >> 2;
                    float c2a = fsigm(v01)*cin[(size_t)m*HS + j] + fsigm(v00)*ftanh(p00);
                    cout[(size_t)m*HS + j] = c2a;
                    hout[(size_t)m*HS + j] = __float2half(fsigm(p01)*ftanh(c2a));
                    float c2b = fsigm(v11)*cin[(size_t)(m+8)*HS + j] + fsigm(v10)*ftanh(p10);
                    cout[(size_t)(m+8)*HS + j] = c2b;
                    hout[(size_t)(m+8)*HS + j] = __float2half(fsigm(p11)*ftanh(c2b));
                }
            } else {
                C16[(size_t)m*ldc + n]       = __float2half(v00);
                C16[(size_t)m*ldc + n+1]     = __float2half(v01);
                C16[(size_t)(m+8)*ldc + n]   = __float2half(v10);
                C16[(size_t)(m+8)*ldc + n+1] = __float2half(v11);
            }
        }
    }
}

// ---------------- fp32 SIMT GEMM (prologue) ----------------------------------
__global__ void gemm_kernel(
    float* __restrict__ C, int ldc,
    const float* __restrict__ A1, int lda1, const float* __restrict__ W1, int ldw1, int K1,
    const float* __restrict__ bias1,
    const float* __restrict__ Cadd, int ldadd,
    int nn, int M, int N)
{
    __shared__ float As[16][68];
    __shared__ float Bs[16][68];
    int m0 = blockIdx.y * 64;
    int n0 = blockIdx.x * 64;
    int tid = threadIdx.x;
    int tx = tid & 15, ty = tid >> 4;

    float acc[4][4];
    #pragma unroll
    for (int i=0;i<4;i++)
        #pragma unroll
        for (int j=0;j<4;j++) acc[i][j]=0.f;

    for (int k0=0; k0<K1; k0+=16){
        #pragma unroll
        for (int i=0;i<4;i++){
            int e = i*256 + tid;
            int m = e >> 4, kk = e & 15;
            int gm = m0 + m, gk = k0 + kk;
            As[kk][m] = (gm < M && gk < K1) ? A1[(size_t)gm*lda1 + gk] : 0.f;
        }
        if (nn){
            #pragma unroll
            for (int i=0;i<4;i++){
                int e = i*256 + tid;
                int kk = e >> 6, n = e & 63;
                int gn = n0 + n, gk = k0 + kk;
                Bs[kk][n] = (gn < N && gk < K1) ? W1[(size_t)gk*ldw1 + gn] : 0.f;
            }
        } else {
            #pragma unroll
            for (int i=0;i<4;i++){
                int e = i*256 + tid;
                int n = e >> 4, kk = e & 15;
                int gn = n0 + n, gk = k0 + kk;
                Bs[kk][n] = (gn < N && gk < K1) ? W1[(size_t)gn*ldw1 + gk] : 0.f;
            }
        }
        __syncthreads();
        #pragma unroll
        for (int kk=0; kk<16; kk++){
            float4 a = *(const float4*)&As[kk][ty*4];
            float4 b = *(const float4*)&Bs[kk][tx*4];
            acc[0][0]+=a.x*b.x; acc[0][1]+=a.x*b.y; acc[0][2]+=a.x*b.z; acc[0][3]+=a.x*b.w;
            acc[1][0]+=a.y*b.x; acc[1][1]+=a.y*b.y; acc[1][2]+=a.y*b.z; acc[1][3]+=a.y*b.w;
            acc[2][0]+=a.z*b.x; acc[2][1]+=a.z*b.y; acc[2][2]+=a.z*b.z; acc[2][3]+=a.z*b.w;
            acc[3][0]+=a.w*b.x; acc[3][1]+=a.w*b.y; acc[3][2]+=a.w*b.z; acc[3][3]+=a.w*b.w;
        }
        __syncthreads();
    }

    #pragma unroll
    for (int i=0;i<4;i++){
        int m = m0 + ty*4 + i;
        if (m >= M) continue;
        #pragma unroll
        for (int j=0;j<4;j++){
            int n = n0 + tx*4 + j;
            if (n >= N) continue;
            float v = acc[i][j];
            if (bias1) v += bias1[n];
            if (Cadd)  v += Cadd[(size_t)m*ldadd + n];
            C[(size_t)m*ldc + n] = v;
        }
    }
}

// ---------------- generator GEMM (fp16 A, fp32 W), remapped output ----------
__global__ void gen_kernel(
    float* __restrict__ C,
    const __half* __restrict__ A1, const float* __restrict__ W1,
    const float* __restrict__ bias1, int M, int N)
{
    __shared__ float As[16][68];
    __shared__ float Bs[16][68];
    int m0 = blockIdx.y * 64;
    int tid = threadIdx.x;
    int tx = tid & 15, ty = tid >> 4;

    float acc[4][4];
    #pragma unroll
    for (int i=0;i<4;i++)
        #pragma unroll
        for (int j=0;j<4;j++) acc[i][j]=0.f;

    for (int k0=0; k0<HS; k0+=16){
        #pragma unroll
        for (int i=0;i<4;i++){
            int e = i*256 + tid;
            int m = e >> 4, kk = e & 15;
            int gm = m0 + m, gk = k0 + kk;
            As[kk][m] = (gm < M) ? __half2float(A1[(size_t)gm*HS + gk]) : 0.f;
        }
        #pragma unroll
        for (int i=0;i<4;i++){
            int e = i*256 + tid;
            int n = e >> 4, kk = e & 15;
            int gk = k0 + kk;
            Bs[kk][n] = (n < N) ? W1[(size_t)n*HS + gk] : 0.f;
        }
        __syncthreads();
        #pragma unroll
        for (int kk=0; kk<16; kk++){
            float4 a = *(const float4*)&As[kk][ty*4];
            float4 b = *(const float4*)&Bs[kk][tx*4];
            acc[0][0]+=a.x*b.x; acc[0][1]+=a.x*b.y; acc[0][2]+=a.x*b.z; acc[0][3]+=a.x*b.w;
            acc[1][0]+=a.y*b.x; acc[1][1]+=a.y*b.y; acc[1][2]+=a.y*b.z; acc[1][3]+=a.y*b.w;
            acc[2][0]+=a.z*b.x; acc[2][1]+=a.z*b.y; acc[2][2]+=a.z*b.z; acc[2][3]+=a.z*b.w;
            acc[3][0]+=a.w*b.x; acc[3][1]+=a.w*b.y; acc[3][2]+=a.w*b.z; acc[3][3]+=a.w*b.w;
        }
        __syncthreads();
    }

    #pragma unroll
    for (int i=0;i<4;i++){
        int m = m0 + ty*4 + i;
        if (m >= M) continue;
        int t = m >> 8, b = m & 255;
        #pragma unroll
        for (int j=0;j<4;j++){
            int n = tx*4 + j;
            if (n >= N) continue;
            C[(size_t)(b*TT + t)*NC + n] = acc[i][j] + bias1[n];
        }
    }
}

// ---------------- mean over T of batch_H ------------------------------------
__global__ void mean_kernel(const float* __restrict__ bH, float* __restrict__ out)
{
    int idx = blockIdx.x*256 + threadIdx.x;
    if (idx >= BB*INSZ) return;
    int b = idx >> 9, k = idx & 511;
    const float* p = bH + (size_t)b*TT*INSZ + k;
    float s = 0.f;
    #pragma unroll
    for (int t=0;t<TT;t++) s += p[t*INSZ];
    out[idx] = s * (1.0f/26.0f);
}

// ---------------- init h0/c0 -------------------------------------------------
__global__ void init_kernel(const float* __restrict__ hh, const float* __restrict__ hc,
                            __half* __restrict__ h1, __half* __restrict__ h2,
                            float* __restrict__ c1, float* __restrict__ c2)
{
    int idx = blockIdx.x*256 + threadIdx.x;
    if (idx >= BB*HS) return;
    float h0 = 0.5f*(hh[idx] + hh[BB*HS + idx]);
    float c0 = 0.5f*(hc[idx] + hc[BB*HS + idx]);
    h1[idx] = __float2half(h0); h2[idx] = __float2half(h0);
    c1[idx]=c0; c2[idx]=c0;
}

// ---------------- attention: e -> softmax -> context (fp16 fmh/q/ctx) --------
__global__ void attn_kernel(const __half* __restrict__ fmh, const __half* __restrict__ q,
                            const float* __restrict__ ws, const float* __restrict__ sb,
                            __half* __restrict__ ctx)
{
    __shared__ float qs[CH];
    __shared__ float wss[CH];
    __shared__ float red[256];
    __shared__ float alpha[256];

    int b = blockIdx.x;
    int p = threadIdx.x;
    const __half* f = fmh + (size_t)b * CH * PP;

    qs[p]       = __half2float(q[b*HS + p]);
    qs[p+256]   = __half2float(q[b*HS + p + 256]);
    wss[p]      = ws[p];
    wss[p+256]  = ws[p+256];
    __syncthreads();

    float a0=0.f, a1=0.f, a2=0.f, a3=0.f;
    #pragma unroll 2
    for (int c=0; c<CH; c+=4){
        float f0 = __half2float(f[(c  )*PP + p]);
        float f1 = __half2float(f[(c+1)*PP + p]);
        float f2 = __half2float(f[(c+2)*PP + p]);
        float f3 = __half2float(f[(c+3)*PP + p]);
        a0 += ftanh(f0 + qs[c  ]) * wss[c  ];
        a1 += ftanh(f1 + qs[c+1]) * wss[c+1];
        a2 += ftanh(f2 + qs[c+2]) * wss[c+2];
        a3 += ftanh(f3 + qs[c+3]) * wss[c+3];
    }
    float e = (a0+a1) + (a2+a3) + sb[0];

    red[p] = e; __syncthreads();
    #pragma unroll
    for (int s=128; s>0; s>>=1){
        if (p < s) red[p] = fmaxf(red[p], red[p+s]);
        __syncthreads();
    }
    float mx = red[0];
    __syncthreads();
    float ex = fexp(e - mx);
    red[p] = ex; __syncthreads();
    #pragma unroll
    for (int s=128; s>0; s>>=1){
        if (p < s) red[p] += red[p+s];
        __syncthreads();
    }
    float sum = red[0];
    __syncthreads();
    alpha[p] = ex * frcp(sum);
    __syncthreads();

    int lane = p & 31, wid = p >> 5;
    for (int c = wid; c < CH; c += 8){
        const __half* fr = f + c*PP;
        float s = 0.f;
        #pragma unroll
        for (int pp = lane; pp < PP; pp += 32) s += alpha[pp] * __half2float(fr[pp]);
        #pragma unroll
        for (int o=16; o>0; o>>=1) s += __shfl_down_sync(0xffffffffu, s, o);
        if (lane == 0) ctx[b*HS + c] = __float2half(s);
    }
}

// ---------------- host orchestration ----------------------------------------
extern "C" void kernel_launch(void* const* d_in, const int* in_sizes, int n_in,
                              void* d_out, int out_size)
{
    const float* feature_map = (const float*)d_in[0];
    const float* batch_H     = (const float*)d_in[1];
    const float* hidden_h    = (const float*)d_in[2];
    const float* hidden_c    = (const float*)d_in[3];
    const int*   text        = (const int*)  d_in[4];
    const float* i2h_w       = (const float*)d_in[5];
    const float* h2h_w       = (const float*)d_in[6];
    const float* h2h_b       = (const float*)d_in[7];
    const float* conv_m2h_w  = (const float*)d_in[8];
    const float* conv_m2h_b  = (const float*)d_in[9];
    const float* conv_h2h_w  = (const float*)d_in[10];
    const float* conv_h2h_b  = (const float*)d_in[11];
    const float* score_w     = (const float*)d_in[12];
    const float* score_b     = (const float*)d_in[13];
    const float* rnn1_w_ih   = (const float*)d_in[14];
    const float* rnn1_w_hh   = (const float*)d_in[15];
    const float* rnn1_b_ih   = (const float*)d_in[16];
    const float* rnn1_b_hh   = (const float*)d_in[17];
    const float* hlin_w      = (const float*)d_in[18];
    const float* hlin_b      = (const float*)d_in[19];
    const float* rnn2_w_ih   = (const float*)d_in[20];
    const float* rnn2_w_hh   = (const float*)d_in[21];
    const float* rnn2_b_ih   = (const float*)d_in[22];
    const float* rnn2_b_hh   = (const float*)d_in[23];
    const float* gen_w       = (const float*)d_in[24];
    const float* gen_b       = (const float*)d_in[25];
    float* out = (float*)d_out;

    __half *ahT,*bhT,*fmh,*Wq16,*w1ih16,*w1hh16,*w2ih16,*w2hh16;
    __half *h1a16,*h1b16,*h2a16,*hist16,*q16,*ctx16;
    float *meanH,*bhproj,*Wq,*qb,*W2p,*badd,*bias1p,*bias2p,*wgp;
    float *c1a,*c1b,*c2a,*c2b;
    cudaGetSymbolAddress((void**)&ahT, g_ahT);
    cudaGetSymbolAddress((void**)&bhT, g_bhT);
    cudaGetSymbolAddress((void**)&fmh, g_fmh);
    cudaGetSymbolAddress((void**)&meanH, g_meanH);
    cudaGetSymbolAddress((void**)&bhproj,g_bhproj);
    cudaGetSymbolAddress((void**)&Wq,    g_Wq);
    cudaGetSymbolAddress((void**)&qb,    g_qb);
    cudaGetSymbolAddress((void**)&W2p,   g_W2p);
    cudaGetSymbolAddress((void**)&badd,  g_badd);
    cudaGetSymbolAddress((void**)&Wq16,  g_Wq16);
    cudaGetSymbolAddress((void**)&w1ih16,g_w1ih16);
    cudaGetSymbolAddress((void**)&w1hh16,g_w1hh16);
    cudaGetSymbolAddress((void**)&w2ih16,g_w2ih16);
    cudaGetSymbolAddress((void**)&w2hh16,g_w2hh16);
    cudaGetSymbolAddress((void**)&bias1p,g_bias1p);
    cudaGetSymbolAddress((void**)&bias2p,g_bias2p);
    cudaGetSymbolAddress((void**)&wgp,   g_wgp);
    cudaGetSymbolAddress((void**)&h1a16, g_h1a16);
    cudaGetSymbolAddress((void**)&h1b16, g_h1b16);
    cudaGetSymbolAddress((void**)&h2a16, g_h2a16);
    cudaGetSymbolAddress((void**)&c1a, g_c1a); cudaGetSymbolAddress((void**)&c1b, g_c1b);
    cudaGetSymbolAddress((void**)&c2a, g_c2a); cudaGetSymbolAddress((void**)&c2b, g_c2b);
    cudaGetSymbolAddress((void**)&hist16, g_hist16);
    cudaGetSymbolAddress((void**)&q16,  g_q16);
    cudaGetSymbolAddress((void**)&ctx16,g_ctx16);

    const int CONV_SMEM = 2 * 4 * 128 * CPITCH * 4;   // 81920
    cudaFuncSetAttribute(conv_fp16_kernel, cudaFuncAttributeMaxDynamicSharedMemorySize, CONV_SMEM);
    const int G16_SMEM = 4 * (GA_WORDS + GB_WORDS) * 4;  // 61440
    cudaFuncSetAttribute(gemm16_kernel, cudaFuncAttributeMaxDynamicSharedMemorySize, G16_SMEM);

    // ---- conv prep + conv ----
    padT_kernel<<<256*10*16, 256>>>(feature_map, ahT);
    wT_kernel<<<(9*CH*CH+255)/256, 256>>>(conv_m2h_w, bhT);
    conv_fp16_kernel<<<dim3(4,2,BB), 256, CONV_SMEM>>>(ahT, bhT, conv_m2h_b, fmh);

    // ---- weight packing ----
    wpack16_kernel<<<(4*HS*512+255)/256,256>>>(rnn1_w_ih, INSZ+NC, w1ih16);
    wpack16_kernel<<<(4*HS*512+255)/256,256>>>(rnn1_w_hh, HS, w1hh16);
    wpack16_kernel<<<(4*HS*512+255)/256,256>>>(rnn2_w_hh, HS, w2hh16);
    bpack_kernel<<<(4*HS+255)/256,256>>>(rnn1_b_ih, rnn1_b_hh, nullptr, bias1p);
    wgpack_kernel<<<(4*HS*NC+255)/256,256>>>(rnn1_w_ih, wgp);
    // fold hlin into rnn2_w_ih: W2p = w2ih @ hlin (fp32), badd = w2ih @ hlin_b
    gemm_kernel<<<dim3(8,32),256>>>(W2p, HS, rnn2_w_ih, HS, hlin_w, HS, HS,
                                    nullptr, nullptr,0, 1, 4*HS, HS);
    badd_kernel<<<(4*HS+255)/256,256>>>(rnn2_w_ih, hlin_b, badd);
    wpack16_kernel<<<(4*HS*512+255)/256,256>>>(W2p, HS, w2ih16);
    bpack_kernel<<<(4*HS+255)/256,256>>>(rnn2_b_ih, rnn2_b_hh, badd, bias2p);

    // ---- prologue (fp32) ----
    mean_kernel<<<512,256>>>(batch_H, meanH);
    gemm_kernel<<<dim3(8,4),256>>>(bhproj, HS, meanH, INSZ, i2h_w, INSZ, INSZ,
                                   h2h_b, nullptr,0, 0, BB, HS);
    gemm_kernel<<<dim3(8,8),256>>>(Wq, HS, conv_h2h_w, HS, h2h_w, HS, HS,
                                   nullptr, nullptr,0, 1, HS, HS);
    cast16_kernel<<<(HS*HS+255)/256,256>>>(Wq, Wq16, HS*HS);
    gemm_kernel<<<dim3(8,4),256>>>(qb, HS, bhproj, HS, conv_h2h_w, HS, HS,
                                   conv_h2h_b, nullptr,0, 0, BB, HS);
    init_kernel<<<512,256>>>(hidden_h, hidden_c, h1a16, h2a16, c1a, c2a);

    __half *h1c16=h1a16, *h1n16=h1b16, *h2c16=h2a16;
    float *c1c=c1a, *c1n=c1b, *c2c=c2a, *c2n=c2b;

    for (int t=0; t<TT; t++){
        __half* h2n16 = hist16 + (size_t)t*BB*HS;
        // q = qb + h2 @ Wq^T  (fp16 out)
        gemm16_kernel<<<dim3(4,4),256,G16_SMEM>>>(q16, HS,
            h2c16, Wq16, HS, nullptr, nullptr, 0,
            nullptr, qb, HS, nullptr, nullptr, 0,
            nullptr, nullptr, nullptr);
        // attention -> ctx (fp16)
        attn_kernel<<<BB,256>>>(fmh, q16, score_w, score_b, ctx16);
        // gates1 + fused LSTM1
        gemm16_kernel<<<dim3(16,4),256,G16_SMEM>>>(nullptr, 0,
            ctx16, w1ih16, HS, h1c16, w1hh16, HS,
            bias1p, nullptr, 0, wgp, text + t, TT,
            c1c, c1n, h1n16);
        // gates2 + fused LSTM2 (hlin folded into w2ih16)
        gemm16_kernel<<<dim3(16,4),256,G16_SMEM>>>(nullptr, 0,
            h1n16, w2ih16, HS, h2c16, w2hh16, HS,
            bias2p, nullptr, 0, nullptr, nullptr, 0,
            c2c, c2n, h2n16);

        __half* tph;
        tph=h1c16; h1c16=h1n16; h1n16=tph;
        h2c16 = h2n16;
        float* tp;
        tp=c1c; c1c=c1n; c1n=tp;
        tp=c2c; c2c=c2n; c2n=tp;
    }

    // probs: one batched GEMM over all timesteps (fp16 hist), remap [b][t][n]
    gen_kernel<<<dim3(1,104),256>>>(out, hist16, gen_w, gen_b, TT*BB, NC);
}

// round 11
// speedup vs baseline: 4.8287x; 1.1637x over previous
#include <cuda_runtime.h>
#include <cuda_fp16.h>
#include <math.h>
#include <stdint.h>

#define BB 256
#define HS 512
#define INSZ 512
#define NC 38
#define TT 26
#define CH 512
#define PP 256   /* 8*32 */

// ---------------- scratch (device globals; no allocation allowed) ----------
__device__ __align__(16) __half g_ahT[(size_t)3*BB*320*CH]; // padded input, [kw][b][pos320][ic]
__device__ __align__(16) __half g_bhT[9*CH*CH];             // conv weights [khw][oc][ic]
__device__ __align__(16) __half g_fmh[(size_t)BB*CH*PP];    // conv output fp16, 67MB
__device__ float g_meanH[BB*INSZ];
__device__ float g_bhproj[BB*HS];
__device__ float g_Wq[HS*HS];
__device__ float g_qb[BB*HS];
__device__ float g_W2p[4*HS*HS];                       // w2ih @ hlin (fp32)
__device__ float g_badd[4*HS];                         // w2ih @ hlin_b
// fp16 packed loop weights
__device__ __align__(16) __half g_Wq16[HS*HS];
__device__ __align__(16) __half g_w1ih16[4*HS*INSZ];   // row 4j+g
__device__ __align__(16) __half g_w1hh16[4*HS*HS];
__device__ __align__(16) __half g_w2ih16[4*HS*HS];     // folded (w2ih@hlin)
__device__ __align__(16) __half g_w2hh16[4*HS*HS];
__device__ float g_bias1p[4*HS], g_bias2p[4*HS];
__device__ float g_wgp[4*HS*NC];                       // onehot gather, packed rows
// states
__device__ __align__(16) __half g_h1a16[BB*HS], g_h1b16[BB*HS], g_h2a16[BB*HS];
__device__ float g_c1a[BB*HS], g_c1b[BB*HS], g_c2a[BB*HS], g_c2b[BB*HS];
__device__ __align__(16) __half g_hist16[(size_t)TT*BB*HS];
__device__ __align__(16) __half g_q16[BB*HS];
__device__ __align__(16) __half g_ctx16[BB*HS];

// ---------------- fast math ------------------------------------------------
__device__ __forceinline__ float fexp(float x){
    float y; asm("ex2.approx.f32 %0, %1;" : "=f"(y) : "f"(x*1.4426950408889634f)); return y;
}
__device__ __forceinline__ float frcp(float x){
    float y; asm("rcp.approx.f32 %0, %1;" : "=f"(y) : "f"(x)); return y;
}
__device__ __forceinline__ float ftanh(float x){
    float xc = fminf(fmaxf(x, -15.f), 15.f);
    float t = fexp(2.f*xc);
    return (t - 1.f) * frcp(t + 1.f);
}
__device__ __forceinline__ float ftanh_hw(float x){
    float y; asm("tanh.approx.f32 %0, %1;" : "=f"(y) : "f"(x)); return y;
}
__device__ __forceinline__ float fsigm(float x){
    return frcp(1.f + fexp(-x));
}
__device__ __forceinline__ void mma_fp16(float* d, const uint32_t* a, const uint32_t* b){
    asm volatile(
      "mma.sync.aligned.m16n8k16.row.col.f32.f16.f16.f32 "
      "{%0,%1,%2,%3},{%4,%5,%6,%7},{%8,%9},{%0,%1,%2,%3};"
      : "+f"(d[0]),"+f"(d[1]),"+f"(d[2]),"+f"(d[3])
      : "r"(a[0]),"r"(a[1]),"r"(a[2]),"r"(a[3]), "r"(b[0]),"r"(b[1]));
}

// ---------------- prep kernels ------------------------------------------------
__global__ void padT_kernel(const float* __restrict__ in, __half* __restrict__ oh)
{
    __shared__ float s[32][33];
    int blk = blockIdx.x;
    int icb = blk & 15;
    int rr  = (blk >> 4) % 10;
    int b   = blk >> 4; b /= 10;
    int t = threadIdx.x;
    int r = rr - 1;

    if ((unsigned)r < 8u){
        int c = t & 31, icq = t >> 5;
        #pragma unroll
        for (int j=0;j<4;j++){
            int ic = icq + j*8;
            s[ic][c] = in[((size_t)b*CH + icb*32 + ic)*PP + r*32 + c];
        }
    }
    __syncthreads();

    int icl = t & 31, cq = t >> 5;
    #pragma unroll
    for (int j=0;j<4;j++){
        int c = cq + j*8;
        #pragma unroll
        for (int kw=0; kw<3; kw++){
            int cc = c + kw - 1;
            float v = 0.f;
            if ((unsigned)r < 8u && (unsigned)cc < 32u) v = s[icl][cc];
            size_t off = (((size_t)kw*BB + b)*320 + rr*32 + c)*CH + icb*32 + icl;
            oh[off] = __float2half(v);
        }
    }
}

__global__ void wT_kernel(const float* __restrict__ w, __half* __restrict__ oh)
{
    int idx = blockIdx.x*256 + threadIdx.x;
    if (idx >= 9*CH*CH) return;
    int ic = idx & 511;
    int oc = (idx >> 9) & 511;
    int khw = idx >> 18;
    oh[((size_t)khw*CH + oc)*CH + ic] = __float2half(w[((size_t)oc*CH + ic)*9 + khw]);
}

__global__ void cast16_kernel(const float* __restrict__ in, __half* __restrict__ out, int n)
{
    int idx = blockIdx.x*256 + threadIdx.x;
    if (idx < n) out[idx] = __float2half(in[idx]);
}

// interleave-pack gate weights: out[(4j+g)*512 + k] = w[(g*512+j)*ldw + k]
__global__ void wpack16_kernel(const float* __restrict__ w, int ldw, __half* __restrict__ out)
{
    int idx = blockIdx.x*256 + threadIdx.x;
    if (idx >= 4*HS*512) return;
    int k = idx & 511;
    int row = idx >> 9;
    int j = row >> 2, g = row & 3;
    out[idx] = __float2half(w[(size_t)(g*HS + j)*ldw + k]);
}

__global__ void bpack_kernel(const float* __restrict__ bih, const float* __restrict__ bhh,
                             const float* __restrict__ badd, float* __restrict__ out)
{
    int row = blockIdx.x*256 + threadIdx.x;
    if (row >= 4*HS) return;
    int j = row >> 2, g = row & 3;
    float v = bih[g*HS + j] + bhh[g*HS + j];
    if (badd) v += badd[g*HS + j];
    out[row] = v;
}

__global__ void wgpack_kernel(const float* __restrict__ w, float* __restrict__ out)
{
    int idx = blockIdx.x*256 + threadIdx.x;
    if (idx >= 4*HS*NC) return;
    int c = idx % NC;
    int row = idx / NC;
    int j = row >> 2, g = row & 3;
    out[idx] = w[(size_t)(g*HS + j)*(INSZ+NC) + INSZ + c];
}

// badd[m] = sum_k w2ih[m,k] * hlin_b[k]
__global__ void badd_kernel(const float* __restrict__ w2ih, const float* __restrict__ hlinb,
                            float* __restrict__ out)
{
    int m = blockIdx.x*256 + threadIdx.x;
    if (m >= 4*HS) return;
    const float* wr = w2ih + (size_t)m*HS;
    float s = 0.f;
    #pragma unroll 8
    for (int k=0;k<HS;k++) s += wr[k]*hlinb[k];
    out[m] = s;
}

// ---------------- conv 3x3 SAME via fp16 mma, 4-stage cp.async ---------------
#define CPITCH 20
#define CSTAGE_W (128*CPITCH)

__global__ void __launch_bounds__(256, 2) conv_fp16_kernel(
    const __half* __restrict__ Ag, const __half* __restrict__ Bg,
    const float* __restrict__ bias, __half* __restrict__ out)
{
    extern __shared__ __align__(16) uint32_t sm[];
    uint32_t* Asm = sm;
    uint32_t* Bsm = sm + 4*CSTAGE_W;
    const int b  = blockIdx.z;
    const int m0 = blockIdx.y * 128;
    const int n0 = blockIdx.x * 128;
    const int tid = threadIdx.x;
    const int lane = tid & 31, warp = tid >> 5;
    const int wm = (warp >> 2) * 64;
    const int wn = (warp & 3) * 32;
    const int gid = lane >> 2, tig = lane & 3;

    const int lrow = tid >> 1;
    const int lch  = tid & 1;

    float acc[4][4][4];
    #pragma unroll
    for (int i=0;i<4;i++)
      #pragma unroll
      for (int j=0;j<4;j++)
        #pragma unroll
        for (int k=0;k<4;k++) acc[i][j][k]=0.f;

    uint32_t sAb = (uint32_t)__cvta_generic_to_shared(Asm);
    uint32_t sBb = (uint32_t)__cvta_generic_to_shared(Bsm);

#define CLOAD(s) do { \
        int st_  = (s) & 3; \
        int khw_ = (s) >> 4; \
        int ic0_ = ((s) & 15) << 5; \
        int kh_ = khw_ / 3, kw_ = khw_ - kh_*3; \
        const __half* ap_ = Ag + (((size_t)kw_*BB + b)*320 + m0 + kh_*32 + lrow)*CH + ic0_ + lch*8; \
        const __half* bp_ = Bg + ((size_t)khw_*CH + n0 + lrow)*CH + ic0_ + lch*8; \
        uint32_t da_ = sAb + (uint32_t)(((st_*128 + lrow)*CPITCH + lch*4)*4); \
        uint32_t db_ = sBb + (uint32_t)(((st_*128 + lrow)*CPITCH + lch*4)*4); \
        asm volatile("cp.async.cg.shared.global [%0], [%1], 16;" :: "r"(da_),      "l"(ap_)); \
        asm volatile("cp.async.cg.shared.global [%0], [%1], 16;" :: "r"(da_ + 32), "l"(ap_ + 16)); \
        asm volatile("cp.async.cg.shared.global [%0], [%1], 16;" :: "r"(db_),      "l"(bp_)); \
        asm volatile("cp.async.cg.shared.global [%0], [%1], 16;" :: "r"(db_ + 32), "l"(bp_ + 16)); \
        asm volatile("cp.async.commit_group;"); \
    } while(0)

    CLOAD(0); CLOAD(1); CLOAD(2);

    for (int s = 0; s < 144; ++s){
        asm volatile("cp.async.wait_group 2;");
        __syncthreads();
        if (s + 3 < 144) CLOAD(s + 3);

        const uint32_t* A_ = Asm + (s & 3) * CSTAGE_W;
        const uint32_t* B_ = Bsm + (s & 3) * CSTAGE_W;

        #pragma unroll
        for (int h = 0; h < 2; ++h){
            const int kb = h*8 + tig;
            uint32_t afr[4][4], bfr[4][2];
            #pragma unroll
            for (int mi=0; mi<4; ++mi){
                int rowb = wm + mi*16 + gid;
                afr[mi][0] = A_[rowb*CPITCH + kb];
                afr[mi][1] = A_[(rowb+8)*CPITCH + kb];
                afr[mi][2] = A_[rowb*CPITCH + kb + 4];
                afr[mi][3] = A_[(rowb+8)*CPITCH + kb + 4];
            }
            #pragma unroll
            for (int ni=0; ni<4; ++ni){
                int colb = wn + ni*8 + gid;
                bfr[ni][0] = B_[colb*CPITCH + kb];
                bfr[ni][1] = B_[colb*CPITCH + kb + 4];
            }
            #pragma unroll
            for (int mi=0; mi<4; ++mi)
                #pragma unroll
                for (int ni=0; ni<4; ++ni)
                    mma_fp16(acc[mi][ni], afr[mi], bfr[ni]);
        }
    }
#undef CLOAD

    #pragma unroll
    for (int mi=0; mi<4; ++mi){
        int prow = m0 + wm + mi*16 + gid;
        #pragma unroll
        for (int ni=0; ni<4; ++ni){
            int oc = n0 + wn + ni*8 + tig*2;
            float bz0 = bias[oc], bz1 = bias[oc+1];
            __half* o0 = out + ((size_t)b*CH + oc)*PP;
            o0[prow]          = __float2half(acc[mi][ni][0] + bz0);
            o0[PP + prow]     = __float2half(acc[mi][ni][1] + bz1);
            o0[prow + 8]      = __float2half(acc[mi][ni][2] + bz0);
            o0[PP + prow + 8] = __float2half(acc[mi][ni][3] + bz1);
        }
    }
}

// ---------------- fp16 step GEMM (+optional fused LSTM epilogue) -------------
#define GPITCH 20
#define GA_WORDS (64*GPITCH)
#define GB_WORDS (128*GPITCH)

__global__ void __launch_bounds__(256, 2) gemm16_kernel(
    __half* __restrict__ C16, int ldc,
    const __half* __restrict__ A1, const __half* __restrict__ W1, int K1,
    const __half* __restrict__ A2, const __half* __restrict__ W2, int K2,
    const float* __restrict__ bias, const float* __restrict__ Cadd, int ldadd,
    const float* __restrict__ Wgp, const int* __restrict__ textcol, int textstride,
    const float* __restrict__ cin, float* __restrict__ cout, __half* __restrict__ hout)
{
    extern __shared__ __align__(16) uint32_t sm[];
    uint32_t* Asm = sm;                  // [4][64][20]
    uint32_t* Bsm = sm + 4*GA_WORDS;     // [4][128][20]
    const int m0 = blockIdx.y * 64;
    const int n0 = blockIdx.x * 128;
    const int tid = threadIdx.x;
    const int lane = tid & 31, warp = tid >> 5;
    const int wm = (warp >> 2) * 32;
    const int wn = (warp & 3) * 32;
    const int gid = lane >> 2, tig = lane & 3;

    const int S1 = K1 >> 5;
    const int S2 = (A2 != nullptr) ? (K2 >> 5) : 0;
    const int S  = S1 + S2;

    float acc[2][4][4];
    #pragma unroll
    for (int i=0;i<2;i++)
      #pragma unroll
      for (int j=0;j<4;j++)
        #pragma unroll
        for (int k=0;k<4;k++) acc[i][j][k]=0.f;

    uint32_t sAb = (uint32_t)__cvta_generic_to_shared(Asm);
    uint32_t sBb = (uint32_t)__cvta_generic_to_shared(Bsm);

#define GLOAD(s) do { \
        int st_ = (s) & 3; int s_ = (s); \
        const __half* A_; const __half* W_; int k0_; \
        if (s_ < S1){ A_ = A1; W_ = W1; k0_ = s_ << 5; } \
        else        { A_ = A2; W_ = W2; k0_ = (s_ - S1) << 5; } \
        const __half* ap_ = A_ + (size_t)(m0 + (tid>>2))*512 + k0_ + (tid&3)*8; \
        uint32_t da_ = sAb + (uint32_t)(((st_*64 + (tid>>2))*GPITCH + (tid&3)*4)*4); \
        asm volatile("cp.async.cg.shared.global [%0], [%1], 16;" :: "r"(da_), "l"(ap_)); \
        const __half* bp_ = W_ + (size_t)(n0 + (tid>>1))*512 + k0_ + (tid&1)*16; \
        uint32_t db_ = sBb + (uint32_t)(((st_*128 + (tid>>1))*GPITCH + (tid&1)*8)*4); \
        asm volatile("cp.async.cg.shared.global [%0], [%1], 16;" :: "r"(db_),      "l"(bp_)); \
        asm volatile("cp.async.cg.shared.global [%0], [%1], 16;" :: "r"(db_ + 16), "l"(bp_ + 8)); \
        asm volatile("cp.async.commit_group;"); \
    } while(0)

    GLOAD(0); GLOAD(1); GLOAD(2);

    for (int s = 0; s < S; ++s){
        asm volatile("cp.async.wait_group 2;");
        __syncthreads();
        if (s + 3 < S) GLOAD(s + 3);

        const uint32_t* A_ = Asm + (s & 3) * GA_WORDS;
        const uint32_t* B_ = Bsm + (s & 3) * GB_WORDS;

        #pragma unroll
        for (int h = 0; h < 2; ++h){
            const int kb = h*8 + tig;
            uint32_t afr[2][4], bfr[4][2];
            #pragma unroll
            for (int mi=0; mi<2; ++mi){
                int rowb = wm + mi*16 + gid;
                afr[mi][0] = A_[rowb*GPITCH + kb];
                afr[mi][1] = A_[(rowb+8)*GPITCH + kb];
                afr[mi][2] = A_[rowb*GPITCH + kb + 4];
                afr[mi][3] = A_[(rowb+8)*GPITCH + kb + 4];
            }
            #pragma unroll
            for (int ni=0; ni<4; ++ni){
                int colb = wn + ni*8 + gid;
                bfr[ni][0] = B_[colb*GPITCH + kb];
                bfr[ni][1] = B_[colb*GPITCH + kb + 4];
            }
            #pragma unroll
            for (int mi=0; mi<2; ++mi)
                #pragma unroll
                for (int ni=0; ni<4; ++ni)
                    mma_fp16(acc[mi][ni], afr[mi], bfr[ni]);
        }
    }
#undef GLOAD

    #pragma unroll
    for (int mi=0; mi<2; ++mi){
        int m = m0 + wm + mi*16 + gid;
        int tc0 = 0, tc1 = 0;
        if (Wgp){ tc0 = textcol[m*textstride]; tc1 = textcol[(m+8)*textstride]; }
        #pragma unroll
        for (int ni=0; ni<4; ++ni){
            int n = n0 + wn + ni*8 + tig*2;
            float b0 = 0.f, b1 = 0.f;
            if (bias){ b0 = bias[n]; b1 = bias[n+1]; }
            float v00 = acc[mi][ni][0] + b0;
            float v01 = acc[mi][ni][1] + b1;
            float v10 = acc[mi][ni][2] + b0;
            float v11 = acc[mi][ni][3] + b1;
            if (Cadd){
                v00 += Cadd[(size_t)m*ldadd + n];     v01 += Cadd[(size_t)m*ldadd + n+1];
                v10 += Cadd[(size_t)(m+8)*ldadd + n]; v11 += Cadd[(size_t)(m+8)*ldadd + n+1];
            }
            if (Wgp){
                v00 += Wgp[n*NC + tc0];     v01 += Wgp[(n+1)*NC + tc0];
                v10 += Wgp[n*NC + tc1];     v11 += Wgp[(n+1)*NC + tc1];
            }
            if (cout){
                float p00 = __shfl_xor_sync(0xffffffffu, v00, 1);
                float p01 = __shfl_xor_sync(0xffffffffu, v01, 1);
                float p10 = __shfl_xor_sync(0xffffffffu, v10, 1);
                float p11 = __shfl_xor_sync(0xffffffffu, v11, 1);
                if ((tig & 1) == 0){
                    int j = n >> 2;
                    float c2a = fsigm(v01)*cin[(size_t)m*HS + j] + fsigm(v00)*ftanh(p00);
                    cout[(size_t)m*HS + j] = c2a;
                    hout[(size_t)m*HS + j] = __float2half(fsigm(p01)*ftanh(c2a));
                    float c2b = fsigm(v11)*cin[(size_t)(m+8)*HS + j] + fsigm(v10)*ftanh(p10);
                    cout[(size_t)(m+8)*HS + j] = c2b;
                    hout[(size_t)(m+8)*HS + j] = __float2half(fsigm(p11)*ftanh(c2b));
                }
            } else {
                C16[(size_t)m*ldc + n]       = __float2half(v00);
                C16[(size_t)m*ldc + n+1]     = __float2half(v01);
                C16[(size_t)(m+8)*ldc + n]   = __float2half(v10);
                C16[(size_t)(m+8)*ldc + n+1] = __float2half(v11);
            }
        }
    }
}

// ---------------- fp32 SIMT GEMM (prologue) ----------------------------------
__global__ void gemm_kernel(
    float* __restrict__ C, int ldc,
    const float* __restrict__ A1, int lda1, const float* __restrict__ W1, int ldw1, int K1,
    const float* __restrict__ bias1,
    const float* __restrict__ Cadd, int ldadd,
    int nn, int M, int N)
{
    __shared__ float As[16][68];
    __shared__ float Bs[16][68];
    int m0 = blockIdx.y * 64;
    int n0 = blockIdx.x * 64;
    int tid = threadIdx.x;
    int tx = tid & 15, ty = tid >> 4;

    float acc[4][4];
    #pragma unroll
    for (int i=0;i<4;i++)
        #pragma unroll
        for (int j=0;j<4;j++) acc[i][j]=0.f;

    for (int k0=0; k0<K1; k0+=16){
        #pragma unroll
        for (int i=0;i<4;i++){
            int e = i*256 + tid;
            int m = e >> 4, kk = e & 15;
            int gm = m0 + m, gk = k0 + kk;
            As[kk][m] = (gm < M && gk < K1) ? A1[(size_t)gm*lda1 + gk] : 0.f;
        }
        if (nn){
            #pragma unroll
            for (int i=0;i<4;i++){
                int e = i*256 + tid;
                int kk = e >> 6, n = e & 63;
                int gn = n0 + n, gk = k0 + kk;
                Bs[kk][n] = (gn < N && gk < K1) ? W1[(size_t)gk*ldw1 + gn] : 0.f;
            }
        } else {
            #pragma unroll
            for (int i=0;i<4;i++){
                int e = i*256 + tid;
                int n = e >> 4, kk = e & 15;
                int gn = n0 + n, gk = k0 + kk;
                Bs[kk][n] = (gn < N && gk < K1) ? W1[(size_t)gn*ldw1 + gk] : 0.f;
            }
        }
        __syncthreads();
        #pragma unroll
        for (int kk=0; kk<16; kk++){
            float4 a = *(const float4*)&As[kk][ty*4];
            float4 b = *(const float4*)&Bs[kk][tx*4];
            acc[0][0]+=a.x*b.x; acc[0][1]+=a.x*b.y; acc[0][2]+=a.x*b.z; acc[0][3]+=a.x*b.w;
            acc[1][0]+=a.y*b.x; acc[1][1]+=a.y*b.y; acc[1][2]+=a.y*b.z; acc[1][3]+=a.y*b.w;
            acc[2][0]+=a.z*b.x; acc[2][1]+=a.z*b.y; acc[2][2]+=a.z*b.z; acc[2][3]+=a.z*b.w;
            acc[3][0]+=a.w*b.x; acc[3][1]+=a.w*b.y; acc[3][2]+=a.w*b.z; acc[3][3]+=a.w*b.w;
        }
        __syncthreads();
    }

    #pragma unroll
    for (int i=0;i<4;i++){
        int m = m0 + ty*4 + i;
        if (m >= M) continue;
        #pragma unroll
        for (int j=0;j<4;j++){
            int n = n0 + tx*4 + j;
            if (n >= N) continue;
            float v = acc[i][j];
            if (bias1) v += bias1[n];
            if (Cadd)  v += Cadd[(size_t)m*ldadd + n];
            C[(size_t)m*ldc + n] = v;
        }
    }
}

// ---------------- generator GEMM (fp16 A, fp32 W), remapped output ----------
__global__ void gen_kernel(
    float* __restrict__ C,
    const __half* __restrict__ A1, const float* __restrict__ W1,
    const float* __restrict__ bias1, int M, int N)
{
    __shared__ float As[16][68];
    __shared__ float Bs[16][68];
    int m0 = blockIdx.y * 64;
    int tid = threadIdx.x;
    int tx = tid & 15, ty = tid >> 4;

    float acc[4][4];
    #pragma unroll
    for (int i=0;i<4;i++)
        #pragma unroll
        for (int j=0;j<4;j++) acc[i][j]=0.f;

    for (int k0=0; k0<HS; k0+=16){
        #pragma unroll
        for (int i=0;i<4;i++){
            int e = i*256 + tid;
            int m = e >> 4, kk = e & 15;
            int gm = m0 + m, gk = k0 + kk;
            As[kk][m] = (gm < M) ? __half2float(A1[(size_t)gm*HS + gk]) : 0.f;
        }
        #pragma unroll
        for (int i=0;i<4;i++){
            int e = i*256 + tid;
            int n = e >> 4, kk = e & 15;
            int gk = k0 + kk;
            Bs[kk][n] = (n < N) ? W1[(size_t)n*HS + gk] : 0.f;
        }
        __syncthreads();
        #pragma unroll
        for (int kk=0; kk<16; kk++){
            float4 a = *(const float4*)&As[kk][ty*4];
            float4 b = *(const float4*)&Bs[kk][tx*4];
            acc[0][0]+=a.x*b.x; acc[0][1]+=a.x*b.y; acc[0][2]+=a.x*b.z; acc[0][3]+=a.x*b.w;
            acc[1][0]+=a.y*b.x; acc[1][1]+=a.y*b.y; acc[1][2]+=a.y*b.z; acc[1][3]+=a.y*b.w;
            acc[2][0]+=a.z*b.x; acc[2][1]+=a.z*b.y; acc[2][2]+=a.z*b.z; acc[2][3]+=a.z*b.w;
            acc[3][0]+=a.w*b.x; acc[3][1]+=a.w*b.y; acc[3][2]+=a.w*b.z; acc[3][3]+=a.w*b.w;
        }
        __syncthreads();
    }

    #pragma unroll
    for (int i=0;i<4;i++){
        int m = m0 + ty*4 + i;
        if (m >= M) continue;
        int t = m >> 8, b = m & 255;
        #pragma unroll
        for (int j=0;j<4;j++){
            int n = tx*4 + j;
            if (n >= N) continue;
            C[(size_t)(b*TT + t)*NC + n] = acc[i][j] + bias1[n];
        }
    }
}

// ---------------- mean over T of batch_H ------------------------------------
__global__ void mean_kernel(const float* __restrict__ bH, float* __restrict__ out)
{
    int idx = blockIdx.x*256 + threadIdx.x;
    if (idx >= BB*INSZ) return;
    int b = idx >> 9, k = idx & 511;
    const float* p = bH + (size_t)b*TT*INSZ + k;
    float s = 0.f;
    #pragma unroll
    for (int t=0;t<TT;t++) s += p[t*INSZ];
    out[idx] = s * (1.0f/26.0f);
}

// ---------------- init h0/c0 -------------------------------------------------
__global__ void init_kernel(const float* __restrict__ hh, const float* __restrict__ hc,
                            __half* __restrict__ h1, __half* __restrict__ h2,
                            float* __restrict__ c1, float* __restrict__ c2)
{
    int idx = blockIdx.x*256 + threadIdx.x;
    if (idx >= BB*HS) return;
    float h0 = 0.5f*(hh[idx] + hh[BB*HS + idx]);
    float c0 = 0.5f*(hc[idx] + hc[BB*HS + idx]);
    h1[idx] = __float2half(h0); h2[idx] = __float2half(h0);
    c1[idx]=c0; c2[idx]=c0;
}

// ---------------- attention: e -> softmax -> context (fp16 fmh/q/ctx) --------
__global__ void attn_kernel(const __half* __restrict__ fmh, const __half* __restrict__ q,
                            const float* __restrict__ ws, const float* __restrict__ sb,
                            __half* __restrict__ ctx)
{
    __shared__ float qs[CH];
    __shared__ float wss[CH];
    __shared__ float red[256];
    __shared__ float alpha[256];

    int b = blockIdx.x;
    int p = threadIdx.x;
    const __half* f = fmh + (size_t)b * CH * PP;

    qs[p]       = __half2float(q[b*HS + p]);
    qs[p+256]   = __half2float(q[b*HS + p + 256]);
    wss[p]      = ws[p];
    wss[p+256]  = ws[p+256];
    __syncthreads();

    float a0=0.f, a1=0.f, a2=0.f, a3=0.f;
    #pragma unroll 2
    for (int c=0; c<CH; c+=4){
        float f0 = __half2float(f[(c  )*PP + p]);
        float f1 = __half2float(f[(c+1)*PP + p]);
        float f2 = __half2float(f[(c+2)*PP + p]);
        float f3 = __half2float(f[(c+3)*PP + p]);
        a0 += ftanh_hw(f0 + qs[c  ]) * wss[c  ];
        a1 += ftanh_hw(f1 + qs[c+1]) * wss[c+1];
        a2 += ftanh_hw(f2 + qs[c+2]) * wss[c+2];
        a3 += ftanh_hw(f3 + qs[c+3]) * wss[c+3];
    }
    float e = (a0+a1) + (a2+a3) + sb[0];

    red[p] = e; __syncthreads();
    #pragma unroll
    for (int s=128; s>0; s>>=1){
        if (p < s) red[p] = fmaxf(red[p], red[p+s]);
        __syncthreads();
    }
    float mx = red[0];
    __syncthreads();
    float ex = fexp(e - mx);
    red[p] = ex; __syncthreads();
    #pragma unroll
    for (int s=128; s>0; s>>=1){
        if (p < s) red[p] += red[p+s];
        __syncthreads();
    }
    float sum = red[0];
    __syncthreads();
    alpha[p] = ex * frcp(sum);
    __syncthreads();

    int lane = p & 31, wid = p >> 5;
    for (int c = wid; c < CH; c += 8){
        const __half* fr = f + c*PP;
        float s = 0.f;
        #pragma unroll
        for (int pp = lane; pp < PP; pp += 32) s += alpha[pp] * __half2float(fr[pp]);
        #pragma unroll
        for (int o=16; o>0; o>>=1) s += __shfl_down_sync(0xffffffffu, s, o);
        if (lane == 0) ctx[b*HS + c] = __float2half(s);
    }
}

// ---------------- host orchestration ----------------------------------------
extern "C" void kernel_launch(void* const* d_in, const int* in_sizes, int n_in,
                              void* d_out, int out_size)
{
    const float* feature_map = (const float*)d_in[0];
    const float* batch_H     = (const float*)d_in[1];
    const float* hidden_h    = (const float*)d_in[2];
    const float* hidden_c    = (const float*)d_in[3];
    const int*   text        = (const int*)  d_in[4];
    const float* i2h_w       = (const float*)d_in[5];
    const float* h2h_w       = (const float*)d_in[6];
    const float* h2h_b       = (const float*)d_in[7];
    const float* conv_m2h_w  = (const float*)d_in[8];
    const float* conv_m2h_b  = (const float*)d_in[9];
    const float* conv_h2h_w  = (const float*)d_in[10];
    const float* conv_h2h_b  = (const float*)d_in[11];
    const float* score_w     = (const float*)d_in[12];
    const float* score_b     = (const float*)d_in[13];
    const float* rnn1_w_ih   = (const float*)d_in[14];
    const float* rnn1_w_hh   = (const float*)d_in[15];
    const float* rnn1_b_ih   = (const float*)d_in[16];
    const float* rnn1_b_hh   = (const float*)d_in[17];
    const float* hlin_w      = (const float*)d_in[18];
    const float* hlin_b      = (const float*)d_in[19];
    const float* rnn2_w_ih   = (const float*)d_in[20];
    const float* rnn2_w_hh   = (const float*)d_in[21];
    const float* rnn2_b_ih   = (const float*)d_in[22];
    const float* rnn2_b_hh   = (const float*)d_in[23];
    const float* gen_w       = (const float*)d_in[24];
    const float* gen_b       = (const float*)d_in[25];
    float* out = (float*)d_out;

    __half *ahT,*bhT,*fmh,*Wq16,*w1ih16,*w1hh16,*w2ih16,*w2hh16;
    __half *h1a16,*h1b16,*h2a16,*hist16,*q16,*ctx16;
    float *meanH,*bhproj,*Wq,*qb,*W2p,*badd,*bias1p,*bias2p,*wgp;
    float *c1a,*c1b,*c2a,*c2b;
    cudaGetSymbolAddress((void**)&ahT, g_ahT);
    cudaGetSymbolAddress((void**)&bhT, g_bhT);
    cudaGetSymbolAddress((void**)&fmh, g_fmh);
    cudaGetSymbolAddress((void**)&meanH, g_meanH);
    cudaGetSymbolAddress((void**)&bhproj,g_bhproj);
    cudaGetSymbolAddress((void**)&Wq,    g_Wq);
    cudaGetSymbolAddress((void**)&qb,    g_qb);
    cudaGetSymbolAddress((void**)&W2p,   g_W2p);
    cudaGetSymbolAddress((void**)&badd,  g_badd);
    cudaGetSymbolAddress((void**)&Wq16,  g_Wq16);
    cudaGetSymbolAddress((void**)&w1ih16,g_w1ih16);
    cudaGetSymbolAddress((void**)&w1hh16,g_w1hh16);
    cudaGetSymbolAddress((void**)&w2ih16,g_w2ih16);
    cudaGetSymbolAddress((void**)&w2hh16,g_w2hh16);
    cudaGetSymbolAddress((void**)&bias1p,g_bias1p);
    cudaGetSymbolAddress((void**)&bias2p,g_bias2p);
    cudaGetSymbolAddress((void**)&wgp,   g_wgp);
    cudaGetSymbolAddress((void**)&h1a16, g_h1a16);
    cudaGetSymbolAddress((void**)&h1b16, g_h1b16);
    cudaGetSymbolAddress((void**)&h2a16, g_h2a16);
    cudaGetSymbolAddress((void**)&c1a, g_c1a); cudaGetSymbolAddress((void**)&c1b, g_c1b);
    cudaGetSymbolAddress((void**)&c2a, g_c2a); cudaGetSymbolAddress((void**)&c2b, g_c2b);
    cudaGetSymbolAddress((void**)&hist16, g_hist16);
    cudaGetSymbolAddress((void**)&q16,  g_q16);
    cudaGetSymbolAddress((void**)&ctx16,g_ctx16);

    const int CONV_SMEM = 2 * 4 * 128 * CPITCH * 4;   // 81920
    cudaFuncSetAttribute(conv_fp16_kernel, cudaFuncAttributeMaxDynamicSharedMemorySize, CONV_SMEM);
    const int G16_SMEM = 4 * (GA_WORDS + GB_WORDS) * 4;  // 61440
    cudaFuncSetAttribute(gemm16_kernel, cudaFuncAttributeMaxDynamicSharedMemorySize, G16_SMEM);

    // ---- conv prep + conv ----
    padT_kernel<<<256*10*16, 256>>>(feature_map, ahT);
    wT_kernel<<<(9*CH*CH+255)/256, 256>>>(conv_m2h_w, bhT);
    conv_fp16_kernel<<<dim3(4,2,BB), 256, CONV_SMEM>>>(ahT, bhT, conv_m2h_b, fmh);

    // ---- weight packing ----
    wpack16_kernel<<<(4*HS*512+255)/256,256>>>(rnn1_w_ih, INSZ+NC, w1ih16);
    wpack16_kernel<<<(4*HS*512+255)/256,256>>>(rnn1_w_hh, HS, w1hh16);
    wpack16_kernel<<<(4*HS*512+255)/256,256>>>(rnn2_w_hh, HS, w2hh16);
    bpack_kernel<<<(4*HS+255)/256,256>>>(rnn1_b_ih, rnn1_b_hh, nullptr, bias1p);
    wgpack_kernel<<<(4*HS*NC+255)/256,256>>>(rnn1_w_ih, wgp);
    // fold hlin into rnn2_w_ih: W2p = w2ih @ hlin (fp32), badd = w2ih @ hlin_b
    gemm_kernel<<<dim3(8,32),256>>>(W2p, HS, rnn2_w_ih, HS, hlin_w, HS, HS,
                                    nullptr, nullptr,0, 1, 4*HS, HS);
    badd_kernel<<<(4*HS+255)/256,256>>>(rnn2_w_ih, hlin_b, badd);
    wpack16_kernel<<<(4*HS*512+255)/256,256>>>(W2p, HS, w2ih16);
    bpack_kernel<<<(4*HS+255)/256,256>>>(rnn2_b_ih, rnn2_b_hh, badd, bias2p);

    // ---- prologue (fp32) ----
    mean_kernel<<<512,256>>>(batch_H, meanH);
    gemm_kernel<<<dim3(8,4),256>>>(bhproj, HS, meanH, INSZ, i2h_w, INSZ, INSZ,
                                   h2h_b, nullptr,0, 0, BB, HS);
    gemm_kernel<<<dim3(8,8),256>>>(Wq, HS, conv_h2h_w, HS, h2h_w, HS, HS,
                                   nullptr, nullptr,0, 1, HS, HS);
    cast16_kernel<<<(HS*HS+255)/256,256>>>(Wq, Wq16, HS*HS);
    gemm_kernel<<<dim3(8,4),256>>>(qb, HS, bhproj, HS, conv_h2h_w, HS, HS,
                                   conv_h2h_b, nullptr,0, 0, BB, HS);
    init_kernel<<<512,256>>>(hidden_h, hidden_c, h1a16, h2a16, c1a, c2a);

    __half *h1c16=h1a16, *h1n16=h1b16, *h2c16=h2a16;
    float *c1c=c1a, *c1n=c1b, *c2c=c2a, *c2n=c2b;

    for (int t=0; t<TT; t++){
        __half* h2n16 = hist16 + (size_t)t*BB*HS;
        // q = qb + h2 @ Wq^T  (fp16 out)
        gemm16_kernel<<<dim3(4,4),256,G16_SMEM>>>(q16, HS,
            h2c16, Wq16, HS, nullptr, nullptr, 0,
            nullptr, qb, HS, nullptr, nullptr, 0,
            nullptr, nullptr, nullptr);
        // attention -> ctx (fp16)
        attn_kernel<<<BB,256>>>(fmh, q16, score_w, score_b, ctx16);
        // gates1 + fused LSTM1
        gemm16_kernel<<<dim3(16,4),256,G16_SMEM>>>(nullptr, 0,
            ctx16, w1ih16, HS, h1c16, w1hh16, HS,
            bias1p, nullptr, 0, wgp, text + t, TT,
            c1c, c1n, h1n16);
        // gates2 + fused LSTM2 (hlin folded into w2ih16)
        gemm16_kernel<<<dim3(16,4),256,G16_SMEM>>>(nullptr, 0,
            h1n16, w2ih16, HS, h2c16, w2hh16, HS,
            bias2p, nullptr, 0, nullptr, nullptr, 0,
            c2c, c2n, h2n16);

        __half* tph;
        tph=h1c16; h1c16=h1n16; h1n16=tph;
        h2c16 = h2n16;
        float* tp;
        tp=c1c; c1c=c1n; c1n=tp;
        tp=c2c; c2c=c2n; c2n=tp;
    }

    // probs: one batched GEMM over all timesteps (fp16 hist), remap [b][t][n]
    gen_kernel<<<dim3(1,104),256>>>(out, hist16, gen_w, gen_b, TT*BB, NC);
}